// round 7
// baseline (speedup 1.0000x reference)
#include <cuda_runtime.h>
#include <cuda_bf16.h>
#include <math.h>
#include <stdint.h>

#define B_     16384
#define T_     5
#define F1_    300
#define F2_    251
#define IN_    551
#define H_     128
#define G4_    512
#define M_     (B_ * T_)          // 81920

// ---------------- scratch (device globals; device-code access ONLY) ----------
__device__ float g_xg[M_ * G4_];          // [81920][512]
__device__ float g_hbuf[B_ * T_ * H_];    // [16384][640]
__device__ float g_WhhT[H_ * G4_];        // [128][512]
__device__ float g_a1[B_ * 544];          // [16384][544] (pad cols zeroed)
__device__ float g_a2[B_ * 256];          // [16384][256]

// ---------------- prep: W_hh transpose ---------------------------------------
__global__ void k_prep(const float* __restrict__ Whh)
{
    int idx = blockIdx.x * blockDim.x + threadIdx.x;
    if (idx < H_ * G4_) {
        int k = idx / G4_;
        int g = idx % G4_;
        g_WhhT[idx] = Whh[g * H_ + k];
    }
}

// ---------------- double-bf16 tensor-core GEMM --------------------------------
// C[M,N] = A[M,K] @ B[N,K]^T (+bias, relu opt). v = hi + lo (bf16 each);
// acc += hi*hi + hi*lo + lo*hi. fp32 accumulate. Block 128x128, k-tile 32.
// 8 warps: 4(m) x 2(n); warp tile 32x64. mma.sync.m16n8k16.bf16.
// Fragments via ldmatrix.x4 (stride-40 rows -> 5r mod 8 permutation, no conflicts).
// ASEL: 0 = external A (arg), 1 = g_hbuf, 2 = g_a1 ; CSEL: 0=g_xg 1=g_a1 2=g_a2

__device__ __forceinline__ void mma_bf16(float* c, const uint32_t* a, const uint32_t* b) {
    asm volatile(
        "mma.sync.aligned.m16n8k16.row.col.f32.bf16.bf16.f32 "
        "{%0,%1,%2,%3}, {%4,%5,%6,%7}, {%8,%9}, {%0,%1,%2,%3};"
        : "+f"(c[0]), "+f"(c[1]), "+f"(c[2]), "+f"(c[3])
        : "r"(a[0]), "r"(a[1]), "r"(a[2]), "r"(a[3]), "r"(b[0]), "r"(b[1]));
}

__device__ __forceinline__ void ldsm4(uint32_t addr, uint32_t& r0, uint32_t& r1,
                                      uint32_t& r2, uint32_t& r3) {
    asm volatile("ldmatrix.sync.aligned.m8n8.x4.shared.b16 {%0,%1,%2,%3}, [%4];"
                 : "=r"(r0), "=r"(r1), "=r"(r2), "=r"(r3) : "r"(addr));
}

#define KTILE  32
#define SMK    40                       // row stride in bf16 elems (80B, 16B-mult)
#define TILE_E (128 * SMK)              // bf16 elems per tile

// split 4 floats into hi/lo bf16, store as one 8B chunk per tile
__device__ __forceinline__ void split4_store(__nv_bfloat16* Hp, __nv_bfloat16* Lp,
                                             const float v[4]) {
    __nv_bfloat16 h[4], l[4];
#pragma unroll
    for (int i = 0; i < 4; i++) {
        h[i] = __float2bfloat16_rn(v[i]);
        l[i] = __float2bfloat16_rn(v[i] - __bfloat162float(h[i]));
    }
    uint32_t h01, h23, l01, l23;
    h01 = (uint32_t)*(uint16_t*)&h[0] | ((uint32_t)*(uint16_t*)&h[1] << 16);
    h23 = (uint32_t)*(uint16_t*)&h[2] | ((uint32_t)*(uint16_t*)&h[3] << 16);
    l01 = (uint32_t)*(uint16_t*)&l[0] | ((uint32_t)*(uint16_t*)&l[1] << 16);
    l23 = (uint32_t)*(uint16_t*)&l[2] | ((uint32_t)*(uint16_t*)&l[3] << 16);
    *(uint2*)Hp = make_uint2(h01, h23);
    *(uint2*)Lp = make_uint2(l01, l23);
}

template<int AMODE, int ASEL, int CSEL, bool RELU, bool DUALBIAS>
__global__ __launch_bounds__(256, 2)
void gemm_bf16x3(const float* __restrict__ Aext, const float* __restrict__ A2, int lda,
                 int Kreal, int KT,
                 const float* __restrict__ Bw, int ldb, int Nreal,
                 const float* __restrict__ bias1, const float* __restrict__ bias2,
                 int ldc, int Nstore)
{
    const float* A = (ASEL == 1) ? (const float*)g_hbuf
                   : (ASEL == 2) ? (const float*)g_a1
                                 : Aext;
    float* C = (CSEL == 0) ? g_xg : (CSEL == 1) ? g_a1 : g_a2;

    extern __shared__ __align__(16) __nv_bfloat16 smb[];
    __nv_bfloat16* AsH = smb;                 // [128][40]
    __nv_bfloat16* AsL = smb + TILE_E;
    __nv_bfloat16* BsH = smb + 2 * TILE_E;
    __nv_bfloat16* BsL = smb + 3 * TILE_E;

    const int tid  = threadIdx.x;
    const int m0   = blockIdx.x * 128;
    const int n0   = blockIdx.y * 128;
    const int lane = tid & 31;
    const int warp = tid >> 5;
    const int wm   = warp & 3;          // m offset wm*32
    const int wn   = warp >> 2;         // n offset wn*64
    const int g    = lane >> 2;
    const int tig  = lane & 3;

    float acc[2][8][4];
#pragma unroll
    for (int mt = 0; mt < 2; mt++)
#pragma unroll
        for (int nt = 0; nt < 8; nt++)
#pragma unroll
            for (int i = 0; i < 4; i++) acc[mt][nt][i] = 0.f;

    const int lrow = tid >> 3;          // 0..31
    const int lcol = (tid & 7) * 4;     // 0,4,...,28

    // ldmatrix lane addressing: lanes 0-7 -> mat0, 8-15 -> mat1 (rows +8),
    // 16-23 -> mat2 (k +8), 24-31 -> mat3 (rows +8, k +8)
    const int fl_row = lane & 15;
    const int fl_k   = (lane >> 4) * 8;
    uint32_t AsH_u = (uint32_t)__cvta_generic_to_shared(AsH);
    uint32_t BsH_u = (uint32_t)__cvta_generic_to_shared(BsH);
    const uint32_t a_b0 = AsH_u + 2u * (uint32_t)((wm * 32 + fl_row) * SMK + fl_k);
    const uint32_t b_b0 = BsH_u + 2u * (uint32_t)((wn * 64 + fl_row) * SMK + fl_k);
    const uint32_t LOOFF = 2u * (uint32_t)TILE_E;   // hi tile -> lo tile (bytes)

    const bool b_vec = ((ldb & 3) == 0);

    for (int kt = 0; kt < KT; kt++) {
        const int kb = kt * KTILE + lcol;

        // ---- stage A tile ----
#pragma unroll
        for (int it = 0; it < 4; it++) {
            int ml = lrow + it * 32;
            int m  = m0 + ml;
            float v[4];
            if (AMODE == 1) {
                if (kb + 3 < F1_) {
                    float4 t = *(const float4*)&A[m * F1_ + kb];
                    v[0] = t.x; v[1] = t.y; v[2] = t.z; v[3] = t.w;
                } else {
#pragma unroll
                    for (int j = 0; j < 4; j++) {
                        int kg = kb + j;
                        v[j] = (kg < F1_) ? A[m * F1_ + kg]
                             : (kg < IN_) ? A2[m * F2_ + (kg - F1_)] : 0.f;
                    }
                }
            } else {
                if (kb + 3 < Kreal) {
                    float4 t = *(const float4*)&A[m * lda + kb];
                    v[0] = t.x; v[1] = t.y; v[2] = t.z; v[3] = t.w;
                } else {
#pragma unroll
                    for (int j = 0; j < 4; j++)
                        v[j] = (kb + j < Kreal) ? A[m * lda + kb + j] : 0.f;
                }
            }
            split4_store(&AsH[ml * SMK + lcol], &AsL[ml * SMK + lcol], v);
        }
        // ---- stage B tile ----
#pragma unroll
        for (int it = 0; it < 4; it++) {
            int nl = lrow + it * 32;
            int n  = n0 + nl;
            float v[4];
            if (b_vec && n < Nreal && kb + 3 < Kreal) {
                float4 t = *(const float4*)&Bw[n * ldb + kb];
                v[0] = t.x; v[1] = t.y; v[2] = t.z; v[3] = t.w;
            } else {
#pragma unroll
                for (int j = 0; j < 4; j++)
                    v[j] = (n < Nreal && kb + j < Kreal) ? Bw[n * ldb + kb + j] : 0.f;
            }
            split4_store(&BsH[nl * SMK + lcol], &BsL[nl * SMK + lcol], v);
        }
        __syncthreads();

#pragma unroll
        for (int s = 0; s < KTILE / 16; s++) {
            uint32_t aH[2][4], aL[2][4];
#pragma unroll
            for (int mt = 0; mt < 2; mt++) {
                uint32_t ad = a_b0 + 2u * (uint32_t)(mt * 16 * SMK + s * 16);
                ldsm4(ad, aH[mt][0], aH[mt][1], aH[mt][2], aH[mt][3]);
                ldsm4(ad + LOOFF, aL[mt][0], aL[mt][1], aL[mt][2], aL[mt][3]);
            }
#pragma unroll
            for (int p = 0; p < 4; p++) {
                uint32_t bd = b_b0 + 2u * (uint32_t)(p * 16 * SMK + s * 16);
                uint32_t h0, h1, h2, h3, l0, l1, l2, l3;
                ldsm4(bd, h0, h1, h2, h3);
                ldsm4(bd + LOOFF, l0, l1, l2, l3);
                uint32_t b0H[2] = {h0, h2}, b1H[2] = {h1, h3};
                uint32_t b0L[2] = {l0, l2}, b1L[2] = {l1, l3};
#pragma unroll
                for (int mt = 0; mt < 2; mt++) {
                    mma_bf16(acc[mt][2 * p],     aH[mt], b0H);
                    mma_bf16(acc[mt][2 * p],     aH[mt], b0L);
                    mma_bf16(acc[mt][2 * p],     aL[mt], b0H);
                    mma_bf16(acc[mt][2 * p + 1], aH[mt], b1H);
                    mma_bf16(acc[mt][2 * p + 1], aH[mt], b1L);
                    mma_bf16(acc[mt][2 * p + 1], aL[mt], b1H);
                }
            }
        }
        __syncthreads();
    }

    // ---- epilogue: bias (+relu), zero pad cols, store float2 ----
    float bv0[8], bv1[8];
#pragma unroll
    for (int nt = 0; nt < 8; nt++) {
        int col = n0 + wn * 64 + nt * 8 + tig * 2;
        float x0 = 0.f, x1 = 0.f;
        if (col < Nreal)     { x0 = bias1[col];     if (DUALBIAS) x0 += bias2[col]; }
        if (col + 1 < Nreal) { x1 = bias1[col + 1]; if (DUALBIAS) x1 += bias2[col + 1]; }
        bv0[nt] = x0; bv1[nt] = x1;
    }
#pragma unroll
    for (int mt = 0; mt < 2; mt++) {
#pragma unroll
        for (int i = 0; i < 2; i++) {
            int row = m0 + wm * 32 + mt * 16 + g + i * 8;
#pragma unroll
            for (int nt = 0; nt < 8; nt++) {
                int col = n0 + wn * 64 + nt * 8 + tig * 2;
                if (col < Nstore) {
                    float v0 = acc[mt][nt][i * 2]     + bv0[nt];
                    float v1 = acc[mt][nt][i * 2 + 1] + bv1[nt];
                    if (RELU) { v0 = fmaxf(v0, 0.f); v1 = fmaxf(v1, 0.f); }
                    if (col >= Nreal)     v0 = 0.f;
                    if (col + 1 >= Nreal) v1 = 0.f;
                    *(float2*)&C[row * ldc + col] = make_float2(v0, v1);
                }
            }
        }
    }
}

__device__ __forceinline__ float sigm(float x) { return 1.f / (1.f + expf(-x)); }

// ---------------- K2: LSTM recurrence (fp32; known-good) ----------------------
__global__ __launch_bounds__(256, 2)
void k2_lstm()
{
    extern __shared__ float sm2[];
    float* hT   = sm2;              // [128][32]
    float* gbuf = sm2 + 128 * 32;   // [32][512]

    const int tid = threadIdx.x;
    const int rb  = blockIdx.x * 32;

    const int tx = tid & 63;
    const int ty = tid >> 6;
    const int g0 = tx * 8;

    const int pr  = tid >> 3;
    const int pj0 = (tid & 7) * 16;

    float c[16];
#pragma unroll
    for (int i = 0; i < 16; i++) c[i] = 0.f;

    for (int t = 0; t < T_; t++) {
        float acc[8][8];
#pragma unroll
        for (int ri = 0; ri < 8; ri++) {
            int m = (rb + ty * 8 + ri) * T_ + t;
            float4 v0 = *(const float4*)&g_xg[m * G4_ + g0];
            float4 v1 = *(const float4*)&g_xg[m * G4_ + g0 + 4];
            acc[ri][0] = v0.x; acc[ri][1] = v0.y; acc[ri][2] = v0.z; acc[ri][3] = v0.w;
            acc[ri][4] = v1.x; acc[ri][5] = v1.y; acc[ri][6] = v1.z; acc[ri][7] = v1.w;
        }

        if (t > 0) {
#pragma unroll 2
            for (int k = 0; k < H_; k++) {
                float4 w0 = *(const float4*)&g_WhhT[k * G4_ + g0];
                float4 w1 = *(const float4*)&g_WhhT[k * G4_ + g0 + 4];
                float4 a0 = *(const float4*)&hT[k * 32 + ty * 8];
                float4 a1 = *(const float4*)&hT[k * 32 + ty * 8 + 4];
                float w[8] = {w0.x, w0.y, w0.z, w0.w, w1.x, w1.y, w1.z, w1.w};
                float a[8] = {a0.x, a0.y, a0.z, a0.w, a1.x, a1.y, a1.z, a1.w};
#pragma unroll
                for (int i = 0; i < 8; i++)
#pragma unroll
                    for (int j = 0; j < 8; j++) acc[i][j] = fmaf(a[i], w[j], acc[i][j]);
            }
        }

#pragma unroll
        for (int ri = 0; ri < 8; ri++) {
            float4 o0 = make_float4(acc[ri][0], acc[ri][1], acc[ri][2], acc[ri][3]);
            float4 o1 = make_float4(acc[ri][4], acc[ri][5], acc[ri][6], acc[ri][7]);
            *(float4*)&gbuf[(ty * 8 + ri) * G4_ + g0]     = o0;
            *(float4*)&gbuf[(ty * 8 + ri) * G4_ + g0 + 4] = o1;
        }
        __syncthreads();

#pragma unroll
        for (int jj = 0; jj < 16; jj++) {
            int j = pj0 + jj;
            float gi = gbuf[pr * G4_ + j];
            float gf = gbuf[pr * G4_ + 128 + j];
            float gg = gbuf[pr * G4_ + 256 + j];
            float go = gbuf[pr * G4_ + 384 + j];
            float cn = sigm(gf) * c[jj] + sigm(gi) * tanhf(gg);
            c[jj] = cn;
            float h = sigm(go) * tanhf(cn);
            hT[j * 32 + pr] = h;
            g_hbuf[(rb + pr) * (T_ * H_) + t * H_ + j] = h;
        }
        __syncthreads();
    }
}

// ---------------- K tail: layer3 (256->64), layer4 (64->2), softmax ----------
__global__ __launch_bounds__(256)
void k_tail(const float* __restrict__ W3, const float* __restrict__ b3,
            const float* __restrict__ W4, const float* __restrict__ b4,
            float* __restrict__ out)
{
    __shared__ float a2s[32 * 256];
    __shared__ float a3[32 * 64];
    __shared__ float lg[64];

    const int tid = threadIdx.x;
    const int rb  = blockIdx.x * 32;
    const int warp = tid >> 5, lane = tid & 31;

    {
        const float4* src = (const float4*)(g_a2 + rb * 256);
        float4* dst = (float4*)a2s;
        for (int i = tid; i < 32 * 256 / 4; i += 256) dst[i] = src[i];
    }
    __syncthreads();

    for (int task = warp; task < 64 * 4; task += 8) {
        int o  = task >> 2;
        int r0 = (task & 3) * 8;
        const float4* wrow = (const float4*)(W3 + o * 256);
        float acc[8];
#pragma unroll
        for (int i = 0; i < 8; i++) acc[i] = 0.f;
#pragma unroll
        for (int kb = 0; kb < 2; kb++) {
            float4 w = wrow[kb * 32 + lane];
#pragma unroll
            for (int ri = 0; ri < 8; ri++) {
                float4 xv = *(const float4*)&a2s[(r0 + ri) * 256 + kb * 128 + lane * 4];
                acc[ri] = fmaf(w.x, xv.x, fmaf(w.y, xv.y, fmaf(w.z, xv.z, fmaf(w.w, xv.w, acc[ri]))));
            }
        }
#pragma unroll
        for (int off = 16; off; off >>= 1)
#pragma unroll
            for (int ri = 0; ri < 8; ri++)
                acc[ri] += __shfl_xor_sync(0xffffffffu, acc[ri], off);
        if (lane < 8) a3[(r0 + lane) * 64 + o] = fmaxf(acc[lane] + b3[o], 0.f);
    }
    __syncthreads();

    if (tid < 64) {
        int r = tid >> 1, o = tid & 1;
        float s = b4[o];
        const float* xr = &a3[r * 64];
        const float* wr = &W4[o * 64];
#pragma unroll
        for (int k = 0; k < 64; k++) s = fmaf(xr[k], wr[k], s);
        lg[r * 2 + o] = s;
    }
    __syncthreads();

    if (tid < 32) {
        float z0 = lg[tid * 2], z1 = lg[tid * 2 + 1];
        float m = fmaxf(z0, z1);
        float e0 = expf(z0 - m), e1 = expf(z1 - m);
        float inv = 1.f / (e0 + e1);
        out[(rb + tid) * 2]     = e0 * inv;
        out[(rb + tid) * 2 + 1] = e1 * inv;
    }
}

// ---------------- launcher ----------------------------------------------------
extern "C" void kernel_launch(void* const* d_in, const int* in_sizes, int n_in,
                              void* d_out, int out_size)
{
    const float* x1   = (const float*)d_in[0];
    const float* x2   = (const float*)d_in[1];
    const float* W_ih = (const float*)d_in[2];
    const float* W_hh = (const float*)d_in[3];
    const float* b_ih = (const float*)d_in[4];
    const float* b_hh = (const float*)d_in[5];
    const float* W1   = (const float*)d_in[6];
    const float* b1   = (const float*)d_in[7];
    const float* W2   = (const float*)d_in[8];
    const float* b2   = (const float*)d_in[9];
    const float* W3   = (const float*)d_in[10];
    const float* b3   = (const float*)d_in[11];
    const float* W4   = (const float*)d_in[12];
    const float* b4   = (const float*)d_in[13];
    float* out = (float*)d_out;

    const int gemm_smem = 4 * TILE_E * 2;   // 40960 B

    cudaFuncSetAttribute(k2_lstm, cudaFuncAttributeMaxDynamicSharedMemorySize,
                         (128 * 32 + 32 * 512) * 4);

    // prep: transpose W_hh
    k_prep<<<(H_ * G4_ + 255) / 256, 256>>>(W_hh);

    // K1: g_xg = concat(x1,x2) @ W_ih^T + (b_ih + b_hh)   [81920 x 512], K=551
    {
        dim3 grid(M_ / 128, G4_ / 128);
        gemm_bf16x3<1, 0, 0, false, true><<<grid, 256, gemm_smem>>>(
            x1, x2, 0, IN_, (IN_ + KTILE - 1) / KTILE,
            W_ih, IN_, G4_, b_ih, b_hh,
            G4_, G4_);
    }

    // K2: LSTM recurrence (g_xg -> g_hbuf)
    k2_lstm<<<B_ / 32, 256, (128 * 32 + 32 * 512) * 4>>>();

    // L1: g_a1 = relu(g_hbuf @ W1^T + b1)   [16384 x 531->544], K=640
    {
        dim3 grid(B_ / 128, 5);
        gemm_bf16x3<0, 1, 1, true, false><<<grid, 256, gemm_smem>>>(
            nullptr, nullptr, 640, 640, 640 / KTILE,
            W1, 640, 531, b1, nullptr,
            544, 544);
    }

    // L2: g_a2 = relu(g_a1 @ W2^T + b2)   [16384 x 256], K=531
    {
        dim3 grid(B_ / 128, 2);
        gemm_bf16x3<0, 2, 2, true, false><<<grid, 256, gemm_smem>>>(
            nullptr, nullptr, 544, 531, (531 + KTILE - 1) / KTILE,
            W2, 531, 256, b2, nullptr,
            256, 256);
    }

    // tail: layer3 + layer4 + softmax (reads g_a2 internally)
    k_tail<<<B_ / 32, 256>>>(W3, b3, W4, b4, out);
}

// round 8
// speedup vs baseline: 1.2836x; 1.2836x over previous
#include <cuda_runtime.h>
#include <cuda_bf16.h>
#include <math.h>
#include <stdint.h>

#define B_     16384
#define T_     5
#define F1_    300
#define F2_    251
#define IN_    551
#define H_     128
#define G4_    512
#define M_     (B_ * T_)          // 81920
#define XK_    576                // concat K padded to 32-multiple

// ---------------- scratch (device globals; device-code access ONLY) ----------
__device__ float g_xg[M_ * G4_];                 // [81920][512] fp32
__device__ float g_WhhT[H_ * G4_];               // [128][512]   fp32
__device__ float g_a2[B_ * 256];                 // [16384][256] fp32

__device__ __nv_bfloat16 g_xcH[M_ * XK_];        // concat(x1,x2) hi   [81920][576]
__device__ __nv_bfloat16 g_xcL[M_ * XK_];        // lo
__device__ __nv_bfloat16 g_wihH[G4_ * XK_];      // W_ih padded        [512][576]
__device__ __nv_bfloat16 g_wihL[G4_ * XK_];
__device__ __nv_bfloat16 g_w1H[640 * 640];       // W1 padded (rows 531->640 zero)
__device__ __nv_bfloat16 g_w1L[640 * 640];
__device__ __nv_bfloat16 g_w2H[256 * 544];       // W2 padded (k 531->544 zero)
__device__ __nv_bfloat16 g_w2L[256 * 544];
__device__ __nv_bfloat16 g_hbH[B_ * 640];        // LSTM out hi        [16384][640]
__device__ __nv_bfloat16 g_hbL[B_ * 640];
__device__ __nv_bfloat16 g_a1H[B_ * 544];        // MLP L1 out hi      [16384][544]
__device__ __nv_bfloat16 g_a1L[B_ * 544];

__device__ __forceinline__ void split_bf16(float v, __nv_bfloat16& h, __nv_bfloat16& l) {
    h = __float2bfloat16_rn(v);
    l = __float2bfloat16_rn(v - __bfloat162float(h));
}

// ---------------- prep: concat+split x --------------------------------------
__global__ void k_prep_x(const float* __restrict__ x1, const float* __restrict__ x2)
{
    int idx = blockIdx.x * blockDim.x + threadIdx.x;
    if (idx >= M_ * XK_) return;
    int m = idx / XK_, k = idx % XK_;
    float v = 0.f;
    if (k < F1_)      v = x1[m * F1_ + k];
    else if (k < IN_) v = x2[m * F2_ + (k - F1_)];
    __nv_bfloat16 h, l; split_bf16(v, h, l);
    g_xcH[idx] = h; g_xcL[idx] = l;
}

// ---------------- prep: weights split + WhhT ---------------------------------
#define NW_WIH (G4_ * XK_)        // 294912
#define NW_W1  (640 * 640)        // 409600
#define NW_W2  (256 * 544)        // 139264
__global__ void k_prep_w(const float* __restrict__ Wih, const float* __restrict__ W1,
                         const float* __restrict__ W2,  const float* __restrict__ Whh)
{
    int idx = blockIdx.x * blockDim.x + threadIdx.x;
    if (idx < NW_WIH) {
        int n = idx / XK_, k = idx % XK_;
        float v = (k < IN_) ? Wih[n * IN_ + k] : 0.f;
        __nv_bfloat16 h, l; split_bf16(v, h, l);
        g_wihH[idx] = h; g_wihL[idx] = l;
        return;
    }
    idx -= NW_WIH;
    if (idx < NW_W1) {
        int n = idx / 640, k = idx % 640;
        float v = (n < 531) ? W1[n * 640 + k] : 0.f;
        __nv_bfloat16 h, l; split_bf16(v, h, l);
        g_w1H[idx] = h; g_w1L[idx] = l;
        return;
    }
    idx -= NW_W1;
    if (idx < NW_W2) {
        int n = idx / 544, k = idx % 544;
        float v = (k < 531) ? W2[n * 531 + k] : 0.f;
        __nv_bfloat16 h, l; split_bf16(v, h, l);
        g_w2H[idx] = h; g_w2L[idx] = l;
        return;
    }
    idx -= NW_W2;
    if (idx < H_ * G4_) {
        int k = idx / G4_, g = idx % G4_;
        g_WhhT[idx] = Whh[g * H_ + k];
    }
}

// ---------------- pipelined double-bf16 tensor-core GEMM ----------------------
// C = A @ B^T (+bias, relu opt); all operands pre-split bf16 hi/lo in gmem.
// acc += AhBh + AhBl + AlBh. Block 128x128, KTILE=32, 2-stage cp.async pipeline.
// 8 warps: 4(m) x 2(n); warp tile 32x64; mma.sync.m16n8k16.bf16 + ldmatrix.
// SEL: 0 = K1 (xc @ wih -> g_xg fp32), 1 = L1 (hb @ w1 -> g_a1 bf16 hi/lo),
//      2 = L2 (a1 @ w2 -> g_a2 fp32)

__device__ __forceinline__ void mma_bf16(float* c, const uint32_t* a, const uint32_t* b) {
    asm volatile(
        "mma.sync.aligned.m16n8k16.row.col.f32.bf16.bf16.f32 "
        "{%0,%1,%2,%3}, {%4,%5,%6,%7}, {%8,%9}, {%0,%1,%2,%3};"
        : "+f"(c[0]), "+f"(c[1]), "+f"(c[2]), "+f"(c[3])
        : "r"(a[0]), "r"(a[1]), "r"(a[2]), "r"(a[3]), "r"(b[0]), "r"(b[1]));
}

__device__ __forceinline__ void ldsm4(uint32_t addr, uint32_t& r0, uint32_t& r1,
                                      uint32_t& r2, uint32_t& r3) {
    asm volatile("ldmatrix.sync.aligned.m8n8.x4.shared.b16 {%0,%1,%2,%3}, [%4];"
                 : "=r"(r0), "=r"(r1), "=r"(r2), "=r"(r3) : "r"(addr));
}

__device__ __forceinline__ void cp16(uint32_t d, const void* s) {
    asm volatile("cp.async.cg.shared.global [%0], [%1], 16;" :: "r"(d), "l"(s));
}
#define CP_COMMIT() asm volatile("cp.async.commit_group;")

#define KTILE   32
#define SMK     40                      // bf16 row stride (80B): ldmatrix conflict-free
#define TILEB   (128 * SMK * 2)         // 10240 B per tile
#define STAGE_B (4 * TILEB)             // 40960 B per stage (AsH,AsL,BsH,BsL)

template<int SEL, bool RELU, bool DUALBIAS>
__global__ __launch_bounds__(256, 2)
void gemm_pipe(int lda, int ldb, int KT, int Nreal, int ldc,
               const float* __restrict__ bias1, const float* __restrict__ bias2)
{
    const __nv_bfloat16* AH = (SEL == 0) ? g_xcH  : (SEL == 1) ? g_hbH : g_a1H;
    const __nv_bfloat16* AL = (SEL == 0) ? g_xcL  : (SEL == 1) ? g_hbL : g_a1L;
    const __nv_bfloat16* BH = (SEL == 0) ? g_wihH : (SEL == 1) ? g_w1H : g_w2H;
    const __nv_bfloat16* BL = (SEL == 0) ? g_wihL : (SEL == 1) ? g_w1L : g_w2L;
    float* Cf = (SEL == 0) ? g_xg : g_a2;        // fp32 out (SEL 0/2)

    extern __shared__ __align__(16) __nv_bfloat16 smb[];
    const uint32_t smem_u = (uint32_t)__cvta_generic_to_shared(smb);

    const int tid  = threadIdx.x;
    const int m0   = blockIdx.x * 128;
    const int n0   = blockIdx.y * 128;
    const int lane = tid & 31;
    const int warp = tid >> 5;
    const int wm   = warp & 3;
    const int wn   = warp >> 2;
    const int g    = lane >> 2;
    const int tig  = lane & 3;

    float acc[2][8][4];
#pragma unroll
    for (int mt = 0; mt < 2; mt++)
#pragma unroll
        for (int nt = 0; nt < 8; nt++)
#pragma unroll
            for (int i = 0; i < 4; i++) acc[mt][nt][i] = 0.f;

    // staging addressing: thread -> row tid>>1, 32B half (tid&1) of the 64B row chunk
    const int srow = tid >> 1;
    const int shalf = tid & 1;
    const uint32_t dst_off = (uint32_t)(srow * (SMK * 2) + shalf * 32);
    const size_t a_row = (size_t)(m0 + srow) * lda + shalf * 16;
    const size_t b_row = (size_t)(n0 + srow) * ldb + shalf * 16;

    // ldmatrix lane addressing (identical to validated round-7 layout)
    const int fl_row = lane & 15;
    const int fl_k   = (lane >> 4) * 8;
    const uint32_t a_frag0 = smem_u + 2u * (uint32_t)((wm * 32 + fl_row) * SMK + fl_k);
    const uint32_t b_frag0 = smem_u + (uint32_t)(2 * TILEB)
                           + 2u * (uint32_t)((wn * 64 + fl_row) * SMK + fl_k);

    auto issue_stage = [&](int kt, int st) {
        uint32_t d = smem_u + (uint32_t)(st * STAGE_B) + dst_off;
        const __nv_bfloat16* pa = AH + a_row + (size_t)kt * KTILE;
        const __nv_bfloat16* pl = AL + a_row + (size_t)kt * KTILE;
        const __nv_bfloat16* pb = BH + b_row + (size_t)kt * KTILE;
        const __nv_bfloat16* pc = BL + b_row + (size_t)kt * KTILE;
        cp16(d,                 pa); cp16(d + 16,             pa + 8);
        cp16(d + TILEB,         pl); cp16(d + TILEB + 16,     pl + 8);
        cp16(d + 2 * TILEB,     pb); cp16(d + 2 * TILEB + 16, pb + 8);
        cp16(d + 3 * TILEB,     pc); cp16(d + 3 * TILEB + 16, pc + 8);
    };

    issue_stage(0, 0);
    CP_COMMIT();

    for (int kt = 0; kt < KT; kt++) {
        if (kt + 1 < KT) {
            issue_stage(kt + 1, (kt + 1) & 1);
            CP_COMMIT();
            asm volatile("cp.async.wait_group 1;");
        } else {
            asm volatile("cp.async.wait_group 0;");
        }
        __syncthreads();

        const uint32_t sb = (uint32_t)((kt & 1) * STAGE_B);
#pragma unroll
        for (int s = 0; s < KTILE / 16; s++) {
            uint32_t aH[2][4], aL[2][4];
#pragma unroll
            for (int mt = 0; mt < 2; mt++) {
                uint32_t ad = a_frag0 + sb + 2u * (uint32_t)(mt * 16 * SMK + s * 16);
                ldsm4(ad, aH[mt][0], aH[mt][1], aH[mt][2], aH[mt][3]);
                ldsm4(ad + TILEB, aL[mt][0], aL[mt][1], aL[mt][2], aL[mt][3]);
            }
#pragma unroll
            for (int p = 0; p < 4; p++) {
                uint32_t bd = b_frag0 + sb + 2u * (uint32_t)(p * 16 * SMK + s * 16);
                uint32_t h0, h1, h2, h3, l0, l1, l2, l3;
                ldsm4(bd, h0, h1, h2, h3);
                ldsm4(bd + TILEB, l0, l1, l2, l3);
                uint32_t b0H[2] = {h0, h2}, b1H[2] = {h1, h3};
                uint32_t b0L[2] = {l0, l2}, b1L[2] = {l1, l3};
#pragma unroll
                for (int mt = 0; mt < 2; mt++) {
                    mma_bf16(acc[mt][2 * p],     aH[mt], b0H);
                    mma_bf16(acc[mt][2 * p],     aH[mt], b0L);
                    mma_bf16(acc[mt][2 * p],     aL[mt], b0H);
                    mma_bf16(acc[mt][2 * p + 1], aH[mt], b1H);
                    mma_bf16(acc[mt][2 * p + 1], aH[mt], b1L);
                    mma_bf16(acc[mt][2 * p + 1], aL[mt], b1H);
                }
            }
        }
        __syncthreads();
    }

    // ---- epilogue ----
    float bv0[8], bv1[8];
#pragma unroll
    for (int nt = 0; nt < 8; nt++) {
        int col = n0 + wn * 64 + nt * 8 + tig * 2;
        float x0 = 0.f, x1 = 0.f;
        if (col < Nreal)     { x0 = bias1[col];     if (DUALBIAS) x0 += bias2[col]; }
        if (col + 1 < Nreal) { x1 = bias1[col + 1]; if (DUALBIAS) x1 += bias2[col + 1]; }
        bv0[nt] = x0; bv1[nt] = x1;
    }
#pragma unroll
    for (int mt = 0; mt < 2; mt++) {
#pragma unroll
        for (int i = 0; i < 2; i++) {
            int row = m0 + wm * 32 + mt * 16 + g + i * 8;
#pragma unroll
            for (int nt = 0; nt < 8; nt++) {
                int col = n0 + wn * 64 + nt * 8 + tig * 2;
                if (col < ldc) {
                    float v0 = acc[mt][nt][i * 2]     + bv0[nt];
                    float v1 = acc[mt][nt][i * 2 + 1] + bv1[nt];
                    if (RELU) { v0 = fmaxf(v0, 0.f); v1 = fmaxf(v1, 0.f); }
                    if (col >= Nreal)     v0 = 0.f;
                    if (col + 1 >= Nreal) v1 = 0.f;
                    if (SEL == 1) {
                        __nv_bfloat16 h0, l0, h1, l1;
                        split_bf16(v0, h0, l0);
                        split_bf16(v1, h1, l1);
                        uint32_t hp = (uint32_t)*(uint16_t*)&h0 | ((uint32_t)*(uint16_t*)&h1 << 16);
                        uint32_t lp = (uint32_t)*(uint16_t*)&l0 | ((uint32_t)*(uint16_t*)&l1 << 16);
                        *(uint32_t*)&g_a1H[(size_t)row * ldc + col] = hp;
                        *(uint32_t*)&g_a1L[(size_t)row * ldc + col] = lp;
                    } else {
                        *(float2*)&Cf[(size_t)row * ldc + col] = make_float2(v0, v1);
                    }
                }
            }
        }
    }
}

__device__ __forceinline__ float sigm(float x) { return 1.f / (1.f + expf(-x)); }

// ---------------- K2: LSTM recurrence (fp32; writes hi/lo bf16 h) -------------
__global__ __launch_bounds__(256, 2)
void k2_lstm()
{
    extern __shared__ float sm2[];
    float* hT   = sm2;              // [128][32]
    float* gbuf = sm2 + 128 * 32;   // [32][512]

    const int tid = threadIdx.x;
    const int rb  = blockIdx.x * 32;

    const int tx = tid & 63;
    const int ty = tid >> 6;
    const int g0 = tx * 8;

    const int pr  = tid >> 3;
    const int pj0 = (tid & 7) * 16;

    float c[16];
#pragma unroll
    for (int i = 0; i < 16; i++) c[i] = 0.f;

    for (int t = 0; t < T_; t++) {
        float acc[8][8];
#pragma unroll
        for (int ri = 0; ri < 8; ri++) {
            int m = (rb + ty * 8 + ri) * T_ + t;
            float4 v0 = *(const float4*)&g_xg[m * G4_ + g0];
            float4 v1 = *(const float4*)&g_xg[m * G4_ + g0 + 4];
            acc[ri][0] = v0.x; acc[ri][1] = v0.y; acc[ri][2] = v0.z; acc[ri][3] = v0.w;
            acc[ri][4] = v1.x; acc[ri][5] = v1.y; acc[ri][6] = v1.z; acc[ri][7] = v1.w;
        }

        if (t > 0) {
#pragma unroll 2
            for (int k = 0; k < H_; k++) {
                float4 w0 = *(const float4*)&g_WhhT[k * G4_ + g0];
                float4 w1 = *(const float4*)&g_WhhT[k * G4_ + g0 + 4];
                float4 a0 = *(const float4*)&hT[k * 32 + ty * 8];
                float4 a1 = *(const float4*)&hT[k * 32 + ty * 8 + 4];
                float w[8] = {w0.x, w0.y, w0.z, w0.w, w1.x, w1.y, w1.z, w1.w};
                float a[8] = {a0.x, a0.y, a0.z, a0.w, a1.x, a1.y, a1.z, a1.w};
#pragma unroll
                for (int i = 0; i < 8; i++)
#pragma unroll
                    for (int j = 0; j < 8; j++) acc[i][j] = fmaf(a[i], w[j], acc[i][j]);
            }
        }

#pragma unroll
        for (int ri = 0; ri < 8; ri++) {
            float4 o0 = make_float4(acc[ri][0], acc[ri][1], acc[ri][2], acc[ri][3]);
            float4 o1 = make_float4(acc[ri][4], acc[ri][5], acc[ri][6], acc[ri][7]);
            *(float4*)&gbuf[(ty * 8 + ri) * G4_ + g0]     = o0;
            *(float4*)&gbuf[(ty * 8 + ri) * G4_ + g0 + 4] = o1;
        }
        __syncthreads();

#pragma unroll
        for (int jj = 0; jj < 16; jj++) {
            int j = pj0 + jj;
            float gi = gbuf[pr * G4_ + j];
            float gf = gbuf[pr * G4_ + 128 + j];
            float gg = gbuf[pr * G4_ + 256 + j];
            float go = gbuf[pr * G4_ + 384 + j];
            float cn = sigm(gf) * c[jj] + sigm(gi) * tanhf(gg);
            c[jj] = cn;
            float h = sigm(go) * tanhf(cn);
            hT[j * 32 + pr] = h;
            __nv_bfloat16 hh, hl; split_bf16(h, hh, hl);
            size_t idx = (size_t)(rb + pr) * (T_ * H_) + t * H_ + j;
            g_hbH[idx] = hh;
            g_hbL[idx] = hl;
        }
        __syncthreads();
    }
}

// ---------------- K tail: layer3 (256->64), layer4 (64->2), softmax ----------
__global__ __launch_bounds__(256)
void k_tail(const float* __restrict__ W3, const float* __restrict__ b3,
            const float* __restrict__ W4, const float* __restrict__ b4,
            float* __restrict__ out)
{
    __shared__ float a2s[32 * 256];
    __shared__ float a3[32 * 64];
    __shared__ float lg[64];

    const int tid = threadIdx.x;
    const int rb  = blockIdx.x * 32;
    const int warp = tid >> 5, lane = tid & 31;

    {
        const float4* src = (const float4*)(g_a2 + (size_t)rb * 256);
        float4* dst = (float4*)a2s;
        for (int i = tid; i < 32 * 256 / 4; i += 256) dst[i] = src[i];
    }
    __syncthreads();

    for (int task = warp; task < 64 * 4; task += 8) {
        int o  = task >> 2;
        int r0 = (task & 3) * 8;
        const float4* wrow = (const float4*)(W3 + o * 256);
        float acc[8];
#pragma unroll
        for (int i = 0; i < 8; i++) acc[i] = 0.f;
#pragma unroll
        for (int kb = 0; kb < 2; kb++) {
            float4 w = wrow[kb * 32 + lane];
#pragma unroll
            for (int ri = 0; ri < 8; ri++) {
                float4 xv = *(const float4*)&a2s[(r0 + ri) * 256 + kb * 128 + lane * 4];
                acc[ri] = fmaf(w.x, xv.x, fmaf(w.y, xv.y, fmaf(w.z, xv.z, fmaf(w.w, xv.w, acc[ri]))));
            }
        }
#pragma unroll
        for (int off = 16; off; off >>= 1)
#pragma unroll
            for (int ri = 0; ri < 8; ri++)
                acc[ri] += __shfl_xor_sync(0xffffffffu, acc[ri], off);
        if (lane < 8) a3[(r0 + lane) * 64 + o] = fmaxf(acc[lane] + b3[o], 0.f);
    }
    __syncthreads();

    if (tid < 64) {
        int r = tid >> 1, o = tid & 1;
        float s = b4[o];
        const float* xr = &a3[r * 64];
        const float* wr = &W4[o * 64];
#pragma unroll
        for (int k = 0; k < 64; k++) s = fmaf(xr[k], wr[k], s);
        lg[r * 2 + o] = s;
    }
    __syncthreads();

    if (tid < 32) {
        float z0 = lg[tid * 2], z1 = lg[tid * 2 + 1];
        float m = fmaxf(z0, z1);
        float e0 = expf(z0 - m), e1 = expf(z1 - m);
        float inv = 1.f / (e0 + e1);
        out[(rb + tid) * 2]     = e0 * inv;
        out[(rb + tid) * 2 + 1] = e1 * inv;
    }
}

// ---------------- launcher ----------------------------------------------------
extern "C" void kernel_launch(void* const* d_in, const int* in_sizes, int n_in,
                              void* d_out, int out_size)
{
    const float* x1   = (const float*)d_in[0];
    const float* x2   = (const float*)d_in[1];
    const float* W_ih = (const float*)d_in[2];
    const float* W_hh = (const float*)d_in[3];
    const float* b_ih = (const float*)d_in[4];
    const float* b_hh = (const float*)d_in[5];
    const float* W1   = (const float*)d_in[6];
    const float* b1   = (const float*)d_in[7];
    const float* W2   = (const float*)d_in[8];
    const float* b2   = (const float*)d_in[9];
    const float* W3   = (const float*)d_in[10];
    const float* b3   = (const float*)d_in[11];
    const float* W4   = (const float*)d_in[12];
    const float* b4   = (const float*)d_in[13];
    float* out = (float*)d_out;

    const int gemm_smem = 2 * STAGE_B;   // 81920 B

    cudaFuncSetAttribute(gemm_pipe<0, false, true>,
                         cudaFuncAttributeMaxDynamicSharedMemorySize, gemm_smem);
    cudaFuncSetAttribute(gemm_pipe<1, true, false>,
                         cudaFuncAttributeMaxDynamicSharedMemorySize, gemm_smem);
    cudaFuncSetAttribute(gemm_pipe<2, true, false>,
                         cudaFuncAttributeMaxDynamicSharedMemorySize, gemm_smem);
    cudaFuncSetAttribute(k2_lstm, cudaFuncAttributeMaxDynamicSharedMemorySize,
                         (128 * 32 + 32 * 512) * 4);

    // prep: concat+split x ; split weights + WhhT
    k_prep_x<<<(M_ * XK_ + 255) / 256, 256>>>(x1, x2);
    {
        int total = NW_WIH + NW_W1 + NW_W2 + H_ * G4_;
        k_prep_w<<<(total + 255) / 256, 256>>>(W_ih, W1, W2, W_hh);
    }

    // K1: g_xg = xc @ wih^T + (b_ih + b_hh)   [81920 x 512], K=576
    {
        dim3 grid(M_ / 128, G4_ / 128);
        gemm_pipe<0, false, true><<<grid, 256, gemm_smem>>>(
            XK_, XK_, XK_ / KTILE, G4_, G4_, b_ih, b_hh);
    }

    // K2: LSTM recurrence (g_xg -> g_hbH/L)
    k2_lstm<<<B_ / 32, 256, (128 * 32 + 32 * 512) * 4>>>();

    // L1: g_a1 = relu(hb @ w1^T + b1)   [16384 x 531->544], K=640
    {
        dim3 grid(B_ / 128, 5);
        gemm_pipe<1, true, false><<<grid, 256, gemm_smem>>>(
            640, 640, 640 / KTILE, 531, 544, b1, nullptr);
    }

    // L2: g_a2 = relu(a1 @ w2^T + b2)   [16384 x 256], K=544
    {
        dim3 grid(B_ / 128, 2);
        gemm_pipe<2, true, false><<<grid, 256, gemm_smem>>>(
            544, 544, 544 / KTILE, 256, 256, b2, nullptr);
    }

    // tail: layer3 + layer4 + softmax (reads g_a2 internally)
    k_tail<<<B_ / 32, 256>>>(W3, b3, W4, b4, out);
}

// round 9
// speedup vs baseline: 1.3746x; 1.0709x over previous
#include <cuda_runtime.h>
#include <cuda_bf16.h>
#include <math.h>
#include <stdint.h>

#define B_     16384
#define T_     5
#define F1_    300
#define F2_    251
#define IN_    551
#define H_     128
#define G4_    512
#define M_     (B_ * T_)          // 81920
#define XK_    576                // concat K padded to 32-multiple

// ---------------- scratch (device globals; device-code access ONLY) ----------
__device__ float g_xg[M_ * G4_];                 // [81920][512] fp32 (xg + biases)
__device__ float g_gate[B_ * G4_];               // [16384][512] fp32 (h@Whh + xg), per step
__device__ float g_c[B_ * H_];                   // [16384][128] fp32 cell state
__device__ float g_a2[B_ * 256];                 // [16384][256] fp32

__device__ __nv_bfloat16 g_xcH[M_ * XK_];        // concat(x1,x2) hi [81920][576]
__device__ __nv_bfloat16 g_xcL[M_ * XK_];
__device__ __nv_bfloat16 g_wihH[G4_ * XK_];      // W_ih padded [512][576]
__device__ __nv_bfloat16 g_wihL[G4_ * XK_];
__device__ __nv_bfloat16 g_w1H[640 * 640];       // W1 padded (rows 531->640 zero)
__device__ __nv_bfloat16 g_w1L[640 * 640];
__device__ __nv_bfloat16 g_w2H[256 * 544];       // W2 padded (k 531->544 zero)
__device__ __nv_bfloat16 g_w2L[256 * 544];
__device__ __nv_bfloat16 g_whhH[G4_ * H_];       // W_hh [512][128]
__device__ __nv_bfloat16 g_whhL[G4_ * H_];
__device__ __nv_bfloat16 g_hsH[T_ * B_ * H_];    // h slabs [5][16384][128]
__device__ __nv_bfloat16 g_hsL[T_ * B_ * H_];
__device__ __nv_bfloat16 g_a1H[B_ * 544];        // MLP L1 out [16384][544]
__device__ __nv_bfloat16 g_a1L[B_ * 544];

__device__ __forceinline__ void split_bf16(float v, __nv_bfloat16& h, __nv_bfloat16& l) {
    h = __float2bfloat16_rn(v);
    l = __float2bfloat16_rn(v - __bfloat162float(h));
}

// ---------------- prep: concat+split x --------------------------------------
__global__ void k_prep_x(const float* __restrict__ x1, const float* __restrict__ x2)
{
    int idx = blockIdx.x * blockDim.x + threadIdx.x;
    if (idx >= M_ * XK_) return;
    int m = idx / XK_, k = idx % XK_;
    float v = 0.f;
    if (k < F1_)      v = x1[m * F1_ + k];
    else if (k < IN_) v = x2[m * F2_ + (k - F1_)];
    __nv_bfloat16 h, l; split_bf16(v, h, l);
    g_xcH[idx] = h; g_xcL[idx] = l;
}

// ---------------- prep: weights split ----------------------------------------
#define NW_WIH (G4_ * XK_)        // 294912
#define NW_W1  (640 * 640)        // 409600
#define NW_W2  (256 * 544)        // 139264
#define NW_WHH (G4_ * H_)         // 65536
__global__ void k_prep_w(const float* __restrict__ Wih, const float* __restrict__ W1,
                         const float* __restrict__ W2,  const float* __restrict__ Whh)
{
    int idx = blockIdx.x * blockDim.x + threadIdx.x;
    if (idx < NW_WIH) {
        int n = idx / XK_, k = idx % XK_;
        float v = (k < IN_) ? Wih[n * IN_ + k] : 0.f;
        __nv_bfloat16 h, l; split_bf16(v, h, l);
        g_wihH[idx] = h; g_wihL[idx] = l;
        return;
    }
    idx -= NW_WIH;
    if (idx < NW_W1) {
        int n = idx / 640, k = idx % 640;
        float v = (n < 531) ? W1[n * 640 + k] : 0.f;
        __nv_bfloat16 h, l; split_bf16(v, h, l);
        g_w1H[idx] = h; g_w1L[idx] = l;
        return;
    }
    idx -= NW_W1;
    if (idx < NW_W2) {
        int n = idx / 544, k = idx % 544;
        float v = (k < 531) ? W2[n * 531 + k] : 0.f;
        __nv_bfloat16 h, l; split_bf16(v, h, l);
        g_w2H[idx] = h; g_w2L[idx] = l;
        return;
    }
    idx -= NW_W2;
    if (idx < NW_WHH) {
        __nv_bfloat16 h, l; split_bf16(Whh[idx], h, l);
        g_whhH[idx] = h; g_whhL[idx] = l;
    }
}

// ---------------- pipelined double-bf16 tensor-core GEMM ----------------------
// acc += AhBh + AhBl + AlBh. Block 128x128, KTILE=32, 2-stage cp.async.
// SEL: 0 = K1 (xc @ wih -> g_xg fp32, dual bias)
//      1 = L1 (hs-slab @ w1 -> g_a1 bf16 hi/lo, bias+relu)
//      2 = L2 (a1 @ w2 -> g_a2 fp32, bias+relu)
//      3 = gates (hs[t-1] @ whh + xg[:,t] -> g_gate fp32, no bias)
// BIAS: 0 none, 1 single, 2 dual.

__device__ __forceinline__ void mma_bf16(float* c, const uint32_t* a, const uint32_t* b) {
    asm volatile(
        "mma.sync.aligned.m16n8k16.row.col.f32.bf16.bf16.f32 "
        "{%0,%1,%2,%3}, {%4,%5,%6,%7}, {%8,%9}, {%0,%1,%2,%3};"
        : "+f"(c[0]), "+f"(c[1]), "+f"(c[2]), "+f"(c[3])
        : "r"(a[0]), "r"(a[1]), "r"(a[2]), "r"(a[3]), "r"(b[0]), "r"(b[1]));
}

__device__ __forceinline__ void ldsm4(uint32_t addr, uint32_t& r0, uint32_t& r1,
                                      uint32_t& r2, uint32_t& r3) {
    asm volatile("ldmatrix.sync.aligned.m8n8.x4.shared.b16 {%0,%1,%2,%3}, [%4];"
                 : "=r"(r0), "=r"(r1), "=r"(r2), "=r"(r3) : "r"(addr));
}

__device__ __forceinline__ void cp16(uint32_t d, const void* s) {
    asm volatile("cp.async.cg.shared.global [%0], [%1], 16;" :: "r"(d), "l"(s));
}
#define CP_COMMIT() asm volatile("cp.async.commit_group;")

#define KTILE   32
#define SMK     40
#define TILEB   (128 * SMK * 2)         // 10240 B
#define STAGE_B (4 * TILEB)             // 40960 B

template<int SEL, int BIAS, bool RELU>
__global__ __launch_bounds__(256, 2)
void gemm_pipe(int lda, int ldb, int KT, int Nreal, int ldc,
               const float* __restrict__ bias1, const float* __restrict__ bias2,
               int tstep)
{
    const __nv_bfloat16* AH = (SEL == 0) ? g_xcH
                            : (SEL == 2) ? g_a1H
                            : (SEL == 3) ? g_hsH + (size_t)(tstep - 1) * (B_ * H_)
                                         : g_hsH;   // SEL 1: slab-indexed
    const __nv_bfloat16* AL = (SEL == 0) ? g_xcL
                            : (SEL == 2) ? g_a1L
                            : (SEL == 3) ? g_hsL + (size_t)(tstep - 1) * (B_ * H_)
                                         : g_hsL;
    const __nv_bfloat16* BH = (SEL == 0) ? g_wihH : (SEL == 1) ? g_w1H
                            : (SEL == 2) ? g_w2H : g_whhH;
    const __nv_bfloat16* BL = (SEL == 0) ? g_wihL : (SEL == 1) ? g_w1L
                            : (SEL == 2) ? g_w2L : g_whhL;
    float* Cf = (SEL == 0) ? g_xg : (SEL == 3) ? g_gate : g_a2;

    extern __shared__ __align__(16) __nv_bfloat16 smb[];
    const uint32_t smem_u = (uint32_t)__cvta_generic_to_shared(smb);

    const int tid  = threadIdx.x;
    const int m0   = blockIdx.x * 128;
    const int n0   = blockIdx.y * 128;
    const int lane = tid & 31;
    const int warp = tid >> 5;
    const int wm   = warp & 3;
    const int wn   = warp >> 2;
    const int g    = lane >> 2;
    const int tig  = lane & 3;

    float acc[2][8][4];
#pragma unroll
    for (int mt = 0; mt < 2; mt++)
#pragma unroll
        for (int nt = 0; nt < 8; nt++)
#pragma unroll
            for (int i = 0; i < 4; i++) acc[mt][nt][i] = 0.f;

    const int srow = tid >> 1;
    const int shalf = tid & 1;
    const uint32_t dst_off = (uint32_t)(srow * (SMK * 2) + shalf * 32);

    const int fl_row = lane & 15;
    const int fl_k   = (lane >> 4) * 8;
    const uint32_t a_frag0 = smem_u + 2u * (uint32_t)((wm * 32 + fl_row) * SMK + fl_k);
    const uint32_t b_frag0 = smem_u + (uint32_t)(2 * TILEB)
                           + 2u * (uint32_t)((wn * 64 + fl_row) * SMK + fl_k);

    auto a_off = [&](int kt) -> size_t {
        if (SEL == 1) {   // A[m][k], k = t*128 + j  ->  g_hs[t][m][j]
            int t  = kt >> 2;                 // 128 / KTILE
            int j0 = (kt & 3) * KTILE;
            return ((size_t)t * B_ + (m0 + srow)) * H_ + j0 + shalf * 16;
        }
        return (size_t)(m0 + srow) * lda + (size_t)kt * KTILE + shalf * 16;
    };

    auto issue_stage = [&](int kt, int st) {
        uint32_t d = smem_u + (uint32_t)(st * STAGE_B) + dst_off;
        size_t ao = a_off(kt);
        size_t bo = (size_t)(n0 + srow) * ldb + (size_t)kt * KTILE + shalf * 16;
        const __nv_bfloat16* pa = AH + ao;
        const __nv_bfloat16* pl = AL + ao;
        const __nv_bfloat16* pb = BH + bo;
        const __nv_bfloat16* pc = BL + bo;
        cp16(d,                 pa); cp16(d + 16,             pa + 8);
        cp16(d + TILEB,         pl); cp16(d + TILEB + 16,     pl + 8);
        cp16(d + 2 * TILEB,     pb); cp16(d + 2 * TILEB + 16, pb + 8);
        cp16(d + 3 * TILEB,     pc); cp16(d + 3 * TILEB + 16, pc + 8);
    };

    issue_stage(0, 0);
    CP_COMMIT();

    for (int kt = 0; kt < KT; kt++) {
        if (kt + 1 < KT) {
            issue_stage(kt + 1, (kt + 1) & 1);
            CP_COMMIT();
            asm volatile("cp.async.wait_group 1;");
        } else {
            asm volatile("cp.async.wait_group 0;");
        }
        __syncthreads();

        const uint32_t sb = (uint32_t)((kt & 1) * STAGE_B);
#pragma unroll
        for (int s = 0; s < KTILE / 16; s++) {
            uint32_t aH[2][4], aL[2][4];
#pragma unroll
            for (int mt = 0; mt < 2; mt++) {
                uint32_t ad = a_frag0 + sb + 2u * (uint32_t)(mt * 16 * SMK + s * 16);
                ldsm4(ad, aH[mt][0], aH[mt][1], aH[mt][2], aH[mt][3]);
                ldsm4(ad + TILEB, aL[mt][0], aL[mt][1], aL[mt][2], aL[mt][3]);
            }
#pragma unroll
            for (int p = 0; p < 4; p++) {
                uint32_t bd = b_frag0 + sb + 2u * (uint32_t)(p * 16 * SMK + s * 16);
                uint32_t h0, h1, h2, h3, l0, l1, l2, l3;
                ldsm4(bd, h0, h1, h2, h3);
                ldsm4(bd + TILEB, l0, l1, l2, l3);
                uint32_t b0H[2] = {h0, h2}, b1H[2] = {h1, h3};
                uint32_t b0L[2] = {l0, l2}, b1L[2] = {l1, l3};
#pragma unroll
                for (int mt = 0; mt < 2; mt++) {
                    mma_bf16(acc[mt][2 * p],     aH[mt], b0H);
                    mma_bf16(acc[mt][2 * p],     aH[mt], b0L);
                    mma_bf16(acc[mt][2 * p],     aL[mt], b0H);
                    mma_bf16(acc[mt][2 * p + 1], aH[mt], b1H);
                    mma_bf16(acc[mt][2 * p + 1], aH[mt], b1L);
                    mma_bf16(acc[mt][2 * p + 1], aL[mt], b1H);
                }
            }
        }
        __syncthreads();
    }

    // ---- epilogue ----
    float bv0[8], bv1[8];
#pragma unroll
    for (int nt = 0; nt < 8; nt++) {
        int col = n0 + wn * 64 + nt * 8 + tig * 2;
        float x0 = 0.f, x1 = 0.f;
        if (BIAS >= 1) {
            if (col < Nreal)     { x0 = bias1[col];     if (BIAS == 2) x0 += bias2[col]; }
            if (col + 1 < Nreal) { x1 = bias1[col + 1]; if (BIAS == 2) x1 += bias2[col + 1]; }
        }
        bv0[nt] = x0; bv1[nt] = x1;
    }
#pragma unroll
    for (int mt = 0; mt < 2; mt++) {
#pragma unroll
        for (int i = 0; i < 2; i++) {
            int row = m0 + wm * 32 + mt * 16 + g + i * 8;
#pragma unroll
            for (int nt = 0; nt < 8; nt++) {
                int col = n0 + wn * 64 + nt * 8 + tig * 2;
                if (col < ldc) {
                    float v0 = acc[mt][nt][i * 2]     + bv0[nt];
                    float v1 = acc[mt][nt][i * 2 + 1] + bv1[nt];
                    if (SEL == 3) {   // add xg (biases already inside)
                        size_t xb = ((size_t)row * T_ + tstep) * G4_ + col;
                        v0 += g_xg[xb];
                        v1 += g_xg[xb + 1];
                    }
                    if (RELU) { v0 = fmaxf(v0, 0.f); v1 = fmaxf(v1, 0.f); }
                    if (col >= Nreal)     v0 = 0.f;
                    if (col + 1 >= Nreal) v1 = 0.f;
                    if (SEL == 1) {
                        __nv_bfloat16 h0, l0, h1, l1;
                        split_bf16(v0, h0, l0);
                        split_bf16(v1, h1, l1);
                        uint32_t hp = (uint32_t)*(uint16_t*)&h0 | ((uint32_t)*(uint16_t*)&h1 << 16);
                        uint32_t lp = (uint32_t)*(uint16_t*)&l0 | ((uint32_t)*(uint16_t*)&l1 << 16);
                        *(uint32_t*)&g_a1H[(size_t)row * ldc + col] = hp;
                        *(uint32_t*)&g_a1L[(size_t)row * ldc + col] = lp;
                    } else {
                        *(float2*)&Cf[(size_t)row * ldc + col] = make_float2(v0, v1);
                    }
                }
            }
        }
    }
}

__device__ __forceinline__ float sigm(float x) { return 1.f / (1.f + expf(-x)); }

// ---------------- pointwise LSTM step ----------------------------------------
template<bool FIRST>
__global__ __launch_bounds__(256)
void k_point(int t)
{
    int idx = blockIdx.x * blockDim.x + threadIdx.x;   // b*128 + j
    int b = idx >> 7, j = idx & 127;
    float gi, gf, gg, go;
    if (FIRST) {
        size_t base = (size_t)b * T_ * G4_ + j;        // xg row b*5+0
        gi = g_xg[base];       gf = g_xg[base + 128];
        gg = g_xg[base + 256]; go = g_xg[base + 384];
    } else {
        size_t base = (size_t)b * G4_ + j;
        gi = g_gate[base];       gf = g_gate[base + 128];
        gg = g_gate[base + 256]; go = g_gate[base + 384];
    }
    float c = FIRST ? 0.f : g_c[idx];
    float cn = sigm(gf) * c + sigm(gi) * tanhf(gg);
    g_c[idx] = cn;
    float h = sigm(go) * tanhf(cn);
    __nv_bfloat16 hh, hl; split_bf16(h, hh, hl);
    size_t ho = (size_t)t * (B_ * H_) + idx;
    g_hsH[ho] = hh; g_hsL[ho] = hl;
}

// ---------------- K tail: layer3 (256->64), layer4 (64->2), softmax ----------
__global__ __launch_bounds__(256)
void k_tail(const float* __restrict__ W3, const float* __restrict__ b3,
            const float* __restrict__ W4, const float* __restrict__ b4,
            float* __restrict__ out)
{
    __shared__ float a2s[32 * 256];
    __shared__ float a3[32 * 64];
    __shared__ float lg[64];

    const int tid = threadIdx.x;
    const int rb  = blockIdx.x * 32;
    const int warp = tid >> 5, lane = tid & 31;

    {
        const float4* src = (const float4*)(g_a2 + (size_t)rb * 256);
        float4* dst = (float4*)a2s;
        for (int i = tid; i < 32 * 256 / 4; i += 256) dst[i] = src[i];
    }
    __syncthreads();

    for (int task = warp; task < 64 * 4; task += 8) {
        int o  = task >> 2;
        int r0 = (task & 3) * 8;
        const float4* wrow = (const float4*)(W3 + o * 256);
        float acc[8];
#pragma unroll
        for (int i = 0; i < 8; i++) acc[i] = 0.f;
#pragma unroll
        for (int kb = 0; kb < 2; kb++) {
            float4 w = wrow[kb * 32 + lane];
#pragma unroll
            for (int ri = 0; ri < 8; ri++) {
                float4 xv = *(const float4*)&a2s[(r0 + ri) * 256 + kb * 128 + lane * 4];
                acc[ri] = fmaf(w.x, xv.x, fmaf(w.y, xv.y, fmaf(w.z, xv.z, fmaf(w.w, xv.w, acc[ri]))));
            }
        }
#pragma unroll
        for (int off = 16; off; off >>= 1)
#pragma unroll
            for (int ri = 0; ri < 8; ri++)
                acc[ri] += __shfl_xor_sync(0xffffffffu, acc[ri], off);
        if (lane < 8) a3[(r0 + lane) * 64 + o] = fmaxf(acc[lane] + b3[o], 0.f);
    }
    __syncthreads();

    if (tid < 64) {
        int r = tid >> 1, o = tid & 1;
        float s = b4[o];
        const float* xr = &a3[r * 64];
        const float* wr = &W4[o * 64];
#pragma unroll
        for (int k = 0; k < 64; k++) s = fmaf(xr[k], wr[k], s);
        lg[r * 2 + o] = s;
    }
    __syncthreads();

    if (tid < 32) {
        float z0 = lg[tid * 2], z1 = lg[tid * 2 + 1];
        float m = fmaxf(z0, z1);
        float e0 = expf(z0 - m), e1 = expf(z1 - m);
        float inv = 1.f / (e0 + e1);
        out[(rb + tid) * 2]     = e0 * inv;
        out[(rb + tid) * 2 + 1] = e1 * inv;
    }
}

// ---------------- launcher ----------------------------------------------------
extern "C" void kernel_launch(void* const* d_in, const int* in_sizes, int n_in,
                              void* d_out, int out_size)
{
    const float* x1   = (const float*)d_in[0];
    const float* x2   = (const float*)d_in[1];
    const float* W_ih = (const float*)d_in[2];
    const float* W_hh = (const float*)d_in[3];
    const float* b_ih = (const float*)d_in[4];
    const float* b_hh = (const float*)d_in[5];
    const float* W1   = (const float*)d_in[6];
    const float* b1   = (const float*)d_in[7];
    const float* W2   = (const float*)d_in[8];
    const float* b2   = (const float*)d_in[9];
    const float* W3   = (const float*)d_in[10];
    const float* b3   = (const float*)d_in[11];
    const float* W4   = (const float*)d_in[12];
    const float* b4   = (const float*)d_in[13];
    float* out = (float*)d_out;

    const int gemm_smem = 2 * STAGE_B;   // 81920 B

    cudaFuncSetAttribute(gemm_pipe<0, 2, false>,
                         cudaFuncAttributeMaxDynamicSharedMemorySize, gemm_smem);
    cudaFuncSetAttribute(gemm_pipe<3, 0, false>,
                         cudaFuncAttributeMaxDynamicSharedMemorySize, gemm_smem);
    cudaFuncSetAttribute(gemm_pipe<1, 1, true>,
                         cudaFuncAttributeMaxDynamicSharedMemorySize, gemm_smem);
    cudaFuncSetAttribute(gemm_pipe<2, 1, true>,
                         cudaFuncAttributeMaxDynamicSharedMemorySize, gemm_smem);

    // prep
    k_prep_x<<<(M_ * XK_ + 255) / 256, 256>>>(x1, x2);
    {
        int total = NW_WIH + NW_W1 + NW_W2 + NW_WHH;
        k_prep_w<<<(total + 255) / 256, 256>>>(W_ih, W1, W2, W_hh);
    }

    // K1: g_xg = xc @ wih^T + (b_ih + b_hh)   [81920 x 512], K=576
    {
        dim3 grid(M_ / 128, G4_ / 128);
        gemm_pipe<0, 2, false><<<grid, 256, gemm_smem>>>(
            XK_, XK_, XK_ / KTILE, G4_, G4_, b_ih, b_hh, 0);
    }

    // LSTM: t=0 pointwise, then 4 x (gate GEMM + pointwise)
    k_point<true><<<(B_ * H_) / 256, 256>>>(0);
    for (int t = 1; t < T_; t++) {
        dim3 grid(B_ / 128, G4_ / 128);
        gemm_pipe<3, 0, false><<<grid, 256, gemm_smem>>>(
            H_, H_, H_ / KTILE, G4_, G4_, nullptr, nullptr, t);
        k_point<false><<<(B_ * H_) / 256, 256>>>(t);
    }

    // L1: g_a1 = relu(hs-slab @ w1^T + b1)   [16384 x 531->544], K=640
    {
        dim3 grid(B_ / 128, 5);
        gemm_pipe<1, 1, true><<<grid, 256, gemm_smem>>>(
            0, 640, 640 / KTILE, 531, 544, b1, nullptr, 0);
    }

    // L2: g_a2 = relu(a1 @ w2^T + b2)   [16384 x 256], K=544
    {
        dim3 grid(B_ / 128, 2);
        gemm_pipe<2, 1, true><<<grid, 256, gemm_smem>>>(
            544, 544, 544 / KTILE, 256, 256, b2, nullptr, 0);
    }

    // tail
    k_tail<<<B_ / 32, 256>>>(W3, b3, W4, b4, out);
}

// round 10
// speedup vs baseline: 2.3094x; 1.6801x over previous
#include <cuda_runtime.h>
#include <cuda_bf16.h>
#include <math.h>
#include <stdint.h>

#define B_     16384
#define T_     5
#define F1_    300
#define F2_    251
#define IN_    551
#define H_     128
#define G4_    512
#define M_     (B_ * T_)          // 81920
#define XK_    576                // concat K padded to 32-multiple

// ---------------- scratch (device globals; device-code access ONLY) ----------
__device__ float g_xg[M_ * G4_];                 // [81920][512] fp32 (xg + biases)
__device__ float g_gate[B_ * G4_];               // [16384][512] fp32 (h@Whh + xg)
__device__ float g_c[B_ * H_];                   // [16384][128] fp32 cell state
__device__ float g_a2[B_ * 256];                 // [16384][256] fp32

__device__ __nv_bfloat16 g_xc[M_ * XK_];         // concat(x1,x2) bf16 [81920][576]
__device__ __nv_bfloat16 g_wih[G4_ * XK_];       // W_ih padded [512][576]
__device__ __nv_bfloat16 g_w1[640 * 640];        // W1 padded (rows 531->640 zero)
__device__ __nv_bfloat16 g_w2[256 * 544];        // W2 padded (k 531->544 zero)
__device__ __nv_bfloat16 g_whh[G4_ * H_];        // W_hh [512][128]
__device__ __nv_bfloat16 g_hs[T_ * B_ * H_];     // h slabs [5][16384][128]
__device__ __nv_bfloat16 g_a1[B_ * 544];         // MLP L1 out [16384][544]

// ---------------- prep: concat x ----------------------------------------------
__global__ void k_prep_x(const float* __restrict__ x1, const float* __restrict__ x2)
{
    int idx = blockIdx.x * blockDim.x + threadIdx.x;
    if (idx >= M_ * XK_) return;
    int m = idx / XK_, k = idx % XK_;
    float v = 0.f;
    if (k < F1_)      v = x1[m * F1_ + k];
    else if (k < IN_) v = x2[m * F2_ + (k - F1_)];
    g_xc[idx] = __float2bfloat16_rn(v);
}

// ---------------- prep: weights -------------------------------------------------
#define NW_WIH (G4_ * XK_)        // 294912
#define NW_W1  (640 * 640)        // 409600
#define NW_W2  (256 * 544)        // 139264
#define NW_WHH (G4_ * H_)         // 65536
__global__ void k_prep_w(const float* __restrict__ Wih, const float* __restrict__ W1,
                         const float* __restrict__ W2,  const float* __restrict__ Whh)
{
    int idx = blockIdx.x * blockDim.x + threadIdx.x;
    if (idx < NW_WIH) {
        int n = idx / XK_, k = idx % XK_;
        g_wih[idx] = __float2bfloat16_rn((k < IN_) ? Wih[n * IN_ + k] : 0.f);
        return;
    }
    idx -= NW_WIH;
    if (idx < NW_W1) {
        int n = idx / 640, k = idx % 640;
        g_w1[idx] = __float2bfloat16_rn((n < 531) ? W1[n * 640 + k] : 0.f);
        return;
    }
    idx -= NW_W1;
    if (idx < NW_W2) {
        int n = idx / 544, k = idx % 544;
        g_w2[idx] = __float2bfloat16_rn((k < 531) ? W2[n * 531 + k] : 0.f);
        return;
    }
    idx -= NW_W2;
    if (idx < NW_WHH) {
        g_whh[idx] = __float2bfloat16_rn(Whh[idx]);
    }
}

// ---------------- pipelined bf16 tensor-core GEMM ------------------------------
// C = A @ B^T (+bias/relu/xg-add). 1x bf16 MMA, fp32 accumulate.
// Block 128x128, KTILE=32, 4-stage cp.async pipeline.
// SEL: 0 = K1 (xc @ wih -> g_xg fp32, dual bias)
//      1 = L1 (hs-slab @ w1 -> g_a1 bf16, bias+relu)
//      2 = L2 (a1 @ w2 -> g_a2 fp32, bias+relu)
//      3 = gates (hs[t-1] @ whh + xg[:,t] -> g_gate fp32)
// BIAS: 0 none, 1 single, 2 dual.

__device__ __forceinline__ void mma_bf16(float* c, const uint32_t* a, const uint32_t* b) {
    asm volatile(
        "mma.sync.aligned.m16n8k16.row.col.f32.bf16.bf16.f32 "
        "{%0,%1,%2,%3}, {%4,%5,%6,%7}, {%8,%9}, {%0,%1,%2,%3};"
        : "+f"(c[0]), "+f"(c[1]), "+f"(c[2]), "+f"(c[3])
        : "r"(a[0]), "r"(a[1]), "r"(a[2]), "r"(a[3]), "r"(b[0]), "r"(b[1]));
}

__device__ __forceinline__ void ldsm4(uint32_t addr, uint32_t& r0, uint32_t& r1,
                                      uint32_t& r2, uint32_t& r3) {
    asm volatile("ldmatrix.sync.aligned.m8n8.x4.shared.b16 {%0,%1,%2,%3}, [%4];"
                 : "=r"(r0), "=r"(r1), "=r"(r2), "=r"(r3) : "r"(addr));
}

__device__ __forceinline__ void cp16(uint32_t d, const void* s) {
    asm volatile("cp.async.cg.shared.global [%0], [%1], 16;" :: "r"(d), "l"(s));
}
#define CP_COMMIT() asm volatile("cp.async.commit_group;")

#define KTILE   32
#define SMK     40                      // bf16 row stride: ldmatrix conflict-free
#define TILEB   (128 * SMK * 2)         // 10240 B per tile (A or B)
#define STAGE_B (2 * TILEB)             // 20480 B per stage
#define NSTAGE  4

template<int SEL, int BIAS, bool RELU>
__global__ __launch_bounds__(256, 2)
void gemm_pipe(int lda, int ldb, int KT, int Nreal, int ldc,
               const float* __restrict__ bias1, const float* __restrict__ bias2,
               int tstep)
{
    const __nv_bfloat16* A = (SEL == 0) ? g_xc
                           : (SEL == 2) ? g_a1
                           : (SEL == 3) ? g_hs + (size_t)(tstep - 1) * (B_ * H_)
                                        : g_hs;   // SEL 1: slab-indexed
    const __nv_bfloat16* Bm = (SEL == 0) ? g_wih : (SEL == 1) ? g_w1
                            : (SEL == 2) ? g_w2 : g_whh;
    float* Cf = (SEL == 0) ? g_xg : (SEL == 3) ? g_gate : g_a2;

    extern __shared__ __align__(16) __nv_bfloat16 smb[];
    const uint32_t smem_u = (uint32_t)__cvta_generic_to_shared(smb);

    const int tid  = threadIdx.x;
    const int m0   = blockIdx.x * 128;
    const int n0   = blockIdx.y * 128;
    const int lane = tid & 31;
    const int warp = tid >> 5;
    const int wm   = warp & 3;
    const int wn   = warp >> 2;
    const int g    = lane >> 2;
    const int tig  = lane & 3;

    float acc[2][8][4];
#pragma unroll
    for (int mt = 0; mt < 2; mt++)
#pragma unroll
        for (int nt = 0; nt < 8; nt++)
#pragma unroll
            for (int i = 0; i < 4; i++) acc[mt][nt][i] = 0.f;

    const int srow = tid >> 1;
    const int shalf = tid & 1;
    const uint32_t dst_off = (uint32_t)(srow * (SMK * 2) + shalf * 32);

    const int fl_row = lane & 15;
    const int fl_k   = (lane >> 4) * 8;
    const uint32_t a_frag0 = smem_u + 2u * (uint32_t)((wm * 32 + fl_row) * SMK + fl_k);
    const uint32_t b_frag0 = smem_u + (uint32_t)TILEB
                           + 2u * (uint32_t)((wn * 64 + fl_row) * SMK + fl_k);

    auto a_off = [&](int kt) -> size_t {
        if (SEL == 1) {   // A[m][k], k = t*128 + j  ->  g_hs[t][m][j]
            int t  = kt >> 2;                 // 128 / KTILE
            int j0 = (kt & 3) * KTILE;
            return ((size_t)t * B_ + (m0 + srow)) * H_ + j0 + shalf * 16;
        }
        return (size_t)(m0 + srow) * lda + (size_t)kt * KTILE + shalf * 16;
    };

    auto issue_stage = [&](int kt, int st) {
        uint32_t d = smem_u + (uint32_t)(st * STAGE_B) + dst_off;
        const __nv_bfloat16* pa = A + a_off(kt);
        const __nv_bfloat16* pb = Bm + (size_t)(n0 + srow) * ldb
                                + (size_t)kt * KTILE + shalf * 16;
        cp16(d,             pa); cp16(d + 16,         pa + 8);
        cp16(d + TILEB,     pb); cp16(d + TILEB + 16, pb + 8);
    };

    // prologue: fill NSTAGE-1 stages (all GEMMs here have KT >= 4)
#pragma unroll
    for (int p = 0; p < NSTAGE - 1; p++) {
        issue_stage(p, p);
        CP_COMMIT();
    }

    for (int kt = 0; kt < KT; kt++) {
        if (kt + NSTAGE - 1 < KT) {
            issue_stage(kt + NSTAGE - 1, (kt + NSTAGE - 1) & (NSTAGE - 1));
            CP_COMMIT();
            asm volatile("cp.async.wait_group %0;" :: "n"(NSTAGE - 1));
        } else {
            int rem = KT - kt - 1;    // groups that must stay outstanding
            if (rem >= 3)      asm volatile("cp.async.wait_group 3;");
            else if (rem == 2) asm volatile("cp.async.wait_group 2;");
            else if (rem == 1) asm volatile("cp.async.wait_group 1;");
            else               asm volatile("cp.async.wait_group 0;");
        }
        __syncthreads();

        const uint32_t sb = (uint32_t)((kt & (NSTAGE - 1)) * STAGE_B);
#pragma unroll
        for (int s = 0; s < KTILE / 16; s++) {
            uint32_t aH[2][4];
#pragma unroll
            for (int mt = 0; mt < 2; mt++) {
                uint32_t ad = a_frag0 + sb + 2u * (uint32_t)(mt * 16 * SMK + s * 16);
                ldsm4(ad, aH[mt][0], aH[mt][1], aH[mt][2], aH[mt][3]);
            }
#pragma unroll
            for (int p = 0; p < 4; p++) {
                uint32_t bd = b_frag0 + sb + 2u * (uint32_t)(p * 16 * SMK + s * 16);
                uint32_t h0, h1, h2, h3;
                ldsm4(bd, h0, h1, h2, h3);
                uint32_t b0H[2] = {h0, h2}, b1H[2] = {h1, h3};
#pragma unroll
                for (int mt = 0; mt < 2; mt++) {
                    mma_bf16(acc[mt][2 * p],     aH[mt], b0H);
                    mma_bf16(acc[mt][2 * p + 1], aH[mt], b1H);
                }
            }
        }
        __syncthreads();
    }

    // ---- epilogue ----
    float bv0[8], bv1[8];
#pragma unroll
    for (int nt = 0; nt < 8; nt++) {
        int col = n0 + wn * 64 + nt * 8 + tig * 2;
        float x0 = 0.f, x1 = 0.f;
        if (BIAS >= 1) {
            if (col < Nreal)     { x0 = bias1[col];     if (BIAS == 2) x0 += bias2[col]; }
            if (col + 1 < Nreal) { x1 = bias1[col + 1]; if (BIAS == 2) x1 += bias2[col + 1]; }
        }
        bv0[nt] = x0; bv1[nt] = x1;
    }
#pragma unroll
    for (int mt = 0; mt < 2; mt++) {
#pragma unroll
        for (int i = 0; i < 2; i++) {
            int row = m0 + wm * 32 + mt * 16 + g + i * 8;
#pragma unroll
            for (int nt = 0; nt < 8; nt++) {
                int col = n0 + wn * 64 + nt * 8 + tig * 2;
                if (col < ldc) {
                    float v0 = acc[mt][nt][i * 2]     + bv0[nt];
                    float v1 = acc[mt][nt][i * 2 + 1] + bv1[nt];
                    if (SEL == 3) {   // add xg (biases already inside)
                        size_t xb = ((size_t)row * T_ + tstep) * G4_ + col;
                        v0 += g_xg[xb];
                        v1 += g_xg[xb + 1];
                    }
                    if (RELU) { v0 = fmaxf(v0, 0.f); v1 = fmaxf(v1, 0.f); }
                    if (col >= Nreal)     v0 = 0.f;
                    if (col + 1 >= Nreal) v1 = 0.f;
                    if (SEL == 1) {
                        __nv_bfloat16 h0 = __float2bfloat16_rn(v0);
                        __nv_bfloat16 h1 = __float2bfloat16_rn(v1);
                        uint32_t hp = (uint32_t)*(uint16_t*)&h0
                                    | ((uint32_t)*(uint16_t*)&h1 << 16);
                        *(uint32_t*)&g_a1[(size_t)row * ldc + col] = hp;
                    } else {
                        *(float2*)&Cf[(size_t)row * ldc + col] = make_float2(v0, v1);
                    }
                }
            }
        }
    }
}

__device__ __forceinline__ float sigm(float x) { return 1.f / (1.f + expf(-x)); }

// ---------------- pointwise LSTM step ----------------------------------------
template<bool FIRST>
__global__ __launch_bounds__(256)
void k_point(int t)
{
    int idx = blockIdx.x * blockDim.x + threadIdx.x;   // b*128 + j
    int b = idx >> 7, j = idx & 127;
    float gi, gf, gg, go;
    if (FIRST) {
        size_t base = (size_t)b * T_ * G4_ + j;        // xg row b*5+0
        gi = g_xg[base];       gf = g_xg[base + 128];
        gg = g_xg[base + 256]; go = g_xg[base + 384];
    } else {
        size_t base = (size_t)b * G4_ + j;
        gi = g_gate[base];       gf = g_gate[base + 128];
        gg = g_gate[base + 256]; go = g_gate[base + 384];
    }
    float c = FIRST ? 0.f : g_c[idx];
    float cn = sigm(gf) * c + sigm(gi) * tanhf(gg);
    g_c[idx] = cn;
    float h = sigm(go) * tanhf(cn);
    g_hs[(size_t)t * (B_ * H_) + idx] = __float2bfloat16_rn(h);
}

// ---------------- K tail: layer3 (256->64), layer4 (64->2), softmax ----------
__global__ __launch_bounds__(256)
void k_tail(const float* __restrict__ W3, const float* __restrict__ b3,
            const float* __restrict__ W4, const float* __restrict__ b4,
            float* __restrict__ out)
{
    __shared__ float a2s[32 * 256];
    __shared__ float a3[32 * 64];
    __shared__ float lg[64];

    const int tid = threadIdx.x;
    const int rb  = blockIdx.x * 32;
    const int warp = tid >> 5, lane = tid & 31;

    {
        const float4* src = (const float4*)(g_a2 + (size_t)rb * 256);
        float4* dst = (float4*)a2s;
        for (int i = tid; i < 32 * 256 / 4; i += 256) dst[i] = src[i];
    }
    __syncthreads();

    for (int task = warp; task < 64 * 4; task += 8) {
        int o  = task >> 2;
        int r0 = (task & 3) * 8;
        const float4* wrow = (const float4*)(W3 + o * 256);
        float acc[8];
#pragma unroll
        for (int i = 0; i < 8; i++) acc[i] = 0.f;
#pragma unroll
        for (int kb = 0; kb < 2; kb++) {
            float4 w = wrow[kb * 32 + lane];
#pragma unroll
            for (int ri = 0; ri < 8; ri++) {
                float4 xv = *(const float4*)&a2s[(r0 + ri) * 256 + kb * 128 + lane * 4];
                acc[ri] = fmaf(w.x, xv.x, fmaf(w.y, xv.y, fmaf(w.z, xv.z, fmaf(w.w, xv.w, acc[ri]))));
            }
        }
#pragma unroll
        for (int off = 16; off; off >>= 1)
#pragma unroll
            for (int ri = 0; ri < 8; ri++)
                acc[ri] += __shfl_xor_sync(0xffffffffu, acc[ri], off);
        if (lane < 8) a3[(r0 + lane) * 64 + o] = fmaxf(acc[lane] + b3[o], 0.f);
    }
    __syncthreads();

    if (tid < 64) {
        int r = tid >> 1, o = tid & 1;
        float s = b4[o];
        const float* xr = &a3[r * 64];
        const float* wr = &W4[o * 64];
#pragma unroll
        for (int k = 0; k < 64; k++) s = fmaf(xr[k], wr[k], s);
        lg[r * 2 + o] = s;
    }
    __syncthreads();

    if (tid < 32) {
        float z0 = lg[tid * 2], z1 = lg[tid * 2 + 1];
        float m = fmaxf(z0, z1);
        float e0 = expf(z0 - m), e1 = expf(z1 - m);
        float inv = 1.f / (e0 + e1);
        out[(rb + tid) * 2]     = e0 * inv;
        out[(rb + tid) * 2 + 1] = e1 * inv;
    }
}

// ---------------- launcher ----------------------------------------------------
extern "C" void kernel_launch(void* const* d_in, const int* in_sizes, int n_in,
                              void* d_out, int out_size)
{
    const float* x1   = (const float*)d_in[0];
    const float* x2   = (const float*)d_in[1];
    const float* W_ih = (const float*)d_in[2];
    const float* W_hh = (const float*)d_in[3];
    const float* b_ih = (const float*)d_in[4];
    const float* b_hh = (const float*)d_in[5];
    const float* W1   = (const float*)d_in[6];
    const float* b1   = (const float*)d_in[7];
    const float* W2   = (const float*)d_in[8];
    const float* b2   = (const float*)d_in[9];
    const float* W3   = (const float*)d_in[10];
    const float* b3   = (const float*)d_in[11];
    const float* W4   = (const float*)d_in[12];
    const float* b4   = (const float*)d_in[13];
    float* out = (float*)d_out;

    const int gemm_smem = NSTAGE * STAGE_B;   // 81920 B

    cudaFuncSetAttribute(gemm_pipe<0, 2, false>,
                         cudaFuncAttributeMaxDynamicSharedMemorySize, gemm_smem);
    cudaFuncSetAttribute(gemm_pipe<3, 0, false>,
                         cudaFuncAttributeMaxDynamicSharedMemorySize, gemm_smem);
    cudaFuncSetAttribute(gemm_pipe<1, 1, true>,
                         cudaFuncAttributeMaxDynamicSharedMemorySize, gemm_smem);
    cudaFuncSetAttribute(gemm_pipe<2, 1, true>,
                         cudaFuncAttributeMaxDynamicSharedMemorySize, gemm_smem);

    // prep
    k_prep_x<<<(M_ * XK_ + 255) / 256, 256>>>(x1, x2);
    {
        int total = NW_WIH + NW_W1 + NW_W2 + NW_WHH;
        k_prep_w<<<(total + 255) / 256, 256>>>(W_ih, W1, W2, W_hh);
    }

    // K1: g_xg = xc @ wih^T + (b_ih + b_hh)   [81920 x 512], K=576
    {
        dim3 grid(M_ / 128, G4_ / 128);
        gemm_pipe<0, 2, false><<<grid, 256, gemm_smem>>>(
            XK_, XK_, XK_ / KTILE, G4_, G4_, b_ih, b_hh, 0);
    }

    // LSTM: t=0 pointwise, then 4 x (gate GEMM + pointwise)
    k_point<true><<<(B_ * H_) / 256, 256>>>(0);
    for (int t = 1; t < T_; t++) {
        dim3 grid(B_ / 128, G4_ / 128);
        gemm_pipe<3, 0, false><<<grid, 256, gemm_smem>>>(
            H_, H_, H_ / KTILE, G4_, G4_, nullptr, nullptr, t);
        k_point<false><<<(B_ * H_) / 256, 256>>>(t);
    }

    // L1: g_a1 = relu(hs-slab @ w1^T + b1)   [16384 x 531->544], K=640
    {
        dim3 grid(B_ / 128, 5);
        gemm_pipe<1, 1, true><<<grid, 256, gemm_smem>>>(
            0, 640, 640 / KTILE, 531, 544, b1, nullptr, 0);
    }

    // L2: g_a2 = relu(a1 @ w2^T + b2)   [16384 x 256], K=544
    {
        dim3 grid(B_ / 128, 2);
        gemm_pipe<2, 1, true><<<grid, 256, gemm_smem>>>(
            544, 544, 544 / KTILE, 256, 256, b2, nullptr, 0);
    }

    // tail
    k_tail<<<B_ / 32, 256>>>(W3, b3, W4, b4, out);
}

// round 11
// speedup vs baseline: 2.5595x; 1.1083x over previous
#include <cuda_runtime.h>
#include <cuda_bf16.h>
#include <math.h>
#include <stdint.h>

#define B_     16384
#define T_     5
#define F1_    300
#define F2_    251
#define IN_    551
#define H_     128
#define G4_    512
#define M_     (B_ * T_)          // 81920
#define XK_    576                // concat K padded to 32-multiple

// NOTE on gate layout: gate columns are PERMUTED as quad-interleave:
// col 4j+q = original gate q*128+j, q in {i,f,g,o}. Baked into g_wih/g_whh/g_bias
// at prep time; g_xg therefore comes out permuted; pointwise consumes quads.

// ---------------- scratch (device globals; device-code access ONLY) ----------
__device__ float g_xg[M_ * G4_];                 // [81920][512] fp32 (permuted cols)
__device__ float g_c[B_ * H_];                   // [16384][128] fp32 cell state
__device__ float g_a2[B_ * 256];                 // [16384][256] fp32
__device__ float g_bias[G4_];                    // permuted b_ih+b_hh

__device__ __nv_bfloat16 g_xc[M_ * XK_];         // concat(x1,x2) bf16 [81920][576]
__device__ __nv_bfloat16 g_wih[G4_ * XK_];       // W_ih permuted rows [512][576]
__device__ __nv_bfloat16 g_w1[640 * 640];        // W1 padded (rows 531->640 zero)
__device__ __nv_bfloat16 g_w2[256 * 544];        // W2 padded (k 531->544 zero)
__device__ __nv_bfloat16 g_whh[G4_ * H_];        // W_hh permuted rows [512][128]
__device__ __nv_bfloat16 g_hs[T_ * B_ * H_];     // h slabs [5][16384][128]
__device__ __nv_bfloat16 g_a1[B_ * 544];         // MLP L1 out [16384][544]

// ---------------- fast gate functions (tanh.approx) ---------------------------
__device__ __forceinline__ float ftanh(float x) {
    float y; asm("tanh.approx.f32 %0, %1;" : "=f"(y) : "f"(x)); return y;
}
__device__ __forceinline__ float fsigm(float x) {
    return fmaf(0.5f, ftanh(0.5f * x), 0.5f);
}

// ---------------- prep: concat x ----------------------------------------------
__global__ void k_prep_x(const float* __restrict__ x1, const float* __restrict__ x2)
{
    int idx = blockIdx.x * blockDim.x + threadIdx.x;
    if (idx >= M_ * XK_) return;
    int m = idx / XK_, k = idx % XK_;
    float v = 0.f;
    if (k < F1_)      v = x1[m * F1_ + k];
    else if (k < IN_) v = x2[m * F2_ + (k - F1_)];
    g_xc[idx] = __float2bfloat16_rn(v);
}

// ---------------- prep: weights (with gate permutation) ------------------------
#define NW_WIH (G4_ * XK_)        // 294912
#define NW_W1  (640 * 640)        // 409600
#define NW_W2  (256 * 544)        // 139264
#define NW_WHH (G4_ * H_)         // 65536
__global__ void k_prep_w(const float* __restrict__ Wih, const float* __restrict__ W1,
                         const float* __restrict__ W2,  const float* __restrict__ Whh,
                         const float* __restrict__ bih, const float* __restrict__ bhh)
{
    int idx = blockIdx.x * blockDim.x + threadIdx.x;
    if (idx < NW_WIH) {
        int n = idx / XK_, k = idx % XK_;
        int on = (n & 3) * 128 + (n >> 2);      // permuted -> original gate row
        g_wih[idx] = __float2bfloat16_rn((k < IN_) ? Wih[on * IN_ + k] : 0.f);
        return;
    }
    idx -= NW_WIH;
    if (idx < NW_W1) {
        int n = idx / 640, k = idx % 640;
        g_w1[idx] = __float2bfloat16_rn((n < 531) ? W1[n * 640 + k] : 0.f);
        return;
    }
    idx -= NW_W1;
    if (idx < NW_W2) {
        int n = idx / 544, k = idx % 544;
        g_w2[idx] = __float2bfloat16_rn((k < 531) ? W2[n * 531 + k] : 0.f);
        return;
    }
    idx -= NW_W2;
    if (idx < NW_WHH) {
        int n = idx / H_, k = idx % H_;
        int on = (n & 3) * 128 + (n >> 2);
        g_whh[idx] = __float2bfloat16_rn(Whh[on * H_ + k]);
        return;
    }
    idx -= NW_WHH;
    if (idx < G4_) {
        int on = (idx & 3) * 128 + (idx >> 2);
        g_bias[idx] = bih[on] + bhh[on];
    }
}

// ---------------- pipelined bf16 tensor-core GEMM ------------------------------
// C = A @ B^T. Block 128x128, KTILE=32, 4-stage cp.async pipeline.
// Grid: blockIdx.x = n-block (A reuse in L2), blockIdx.y = m-block.
// SEL: 0 = K1 (xc @ wih -> g_xg fp32, g_bias)
//      1 = L1 (hs-slab @ w1 -> g_a1 bf16, bias+relu)
//      2 = L2 (a1 @ w2 -> g_a2 fp32, bias+relu)
//      3 = gate step (hs[t-1] @ whh + xg[:,t] -> FUSED LSTM pointwise -> g_c, g_hs[t])
// BIAS: 0 none, 1 single(arg), 3 g_bias.

__device__ __forceinline__ void mma_bf16(float* c, const uint32_t* a, const uint32_t* b) {
    asm volatile(
        "mma.sync.aligned.m16n8k16.row.col.f32.bf16.bf16.f32 "
        "{%0,%1,%2,%3}, {%4,%5,%6,%7}, {%8,%9}, {%0,%1,%2,%3};"
        : "+f"(c[0]), "+f"(c[1]), "+f"(c[2]), "+f"(c[3])
        : "r"(a[0]), "r"(a[1]), "r"(a[2]), "r"(a[3]), "r"(b[0]), "r"(b[1]));
}

__device__ __forceinline__ void ldsm4(uint32_t addr, uint32_t& r0, uint32_t& r1,
                                      uint32_t& r2, uint32_t& r3) {
    asm volatile("ldmatrix.sync.aligned.m8n8.x4.shared.b16 {%0,%1,%2,%3}, [%4];"
                 : "=r"(r0), "=r"(r1), "=r"(r2), "=r"(r3) : "r"(addr));
}

__device__ __forceinline__ void cp16(uint32_t d, const void* s) {
    asm volatile("cp.async.cg.shared.global [%0], [%1], 16;" :: "r"(d), "l"(s));
}
#define CP_COMMIT() asm volatile("cp.async.commit_group;")

#define KTILE   32
#define SMK     40
#define TILEB   (128 * SMK * 2)         // 10240 B
#define STAGE_B (2 * TILEB)             // 20480 B
#define NSTAGE  4
#define CSTRIDE 36                      // c staging row stride (floats, 16B-mult)
#define HSTRIDE 40                      // h staging row stride (bf16, 16B-mult)

template<int SEL, int BIAS, bool RELU>
__global__ __launch_bounds__(256, 2)
void gemm_pipe(int lda, int ldb, int KT, int Nreal, int ldc,
               const float* __restrict__ bias1, int tstep)
{
    const __nv_bfloat16* A = (SEL == 0) ? g_xc
                           : (SEL == 2) ? g_a1
                           : (SEL == 3) ? g_hs + (size_t)(tstep - 1) * (B_ * H_)
                                        : g_hs;   // SEL 1: slab-indexed
    const __nv_bfloat16* Bm = (SEL == 0) ? g_wih : (SEL == 1) ? g_w1
                            : (SEL == 2) ? g_w2 : g_whh;
    float* Cf = (SEL == 0) ? g_xg : g_a2;

    extern __shared__ __align__(16) __nv_bfloat16 smb[];
    const uint32_t smem_u = (uint32_t)__cvta_generic_to_shared(smb);

    const int tid  = threadIdx.x;
    const int n0   = blockIdx.x * 128;
    const int m0   = blockIdx.y * 128;
    const int lane = tid & 31;
    const int warp = tid >> 5;
    const int wm   = warp & 3;
    const int wn   = warp >> 2;
    const int g    = lane >> 2;
    const int tig  = lane & 3;

    float acc[2][8][4];
#pragma unroll
    for (int mt = 0; mt < 2; mt++)
#pragma unroll
        for (int nt = 0; nt < 8; nt++)
#pragma unroll
            for (int i = 0; i < 4; i++) acc[mt][nt][i] = 0.f;

    const int srow = tid >> 1;
    const int shalf = tid & 1;
    const uint32_t dst_off = (uint32_t)(srow * (SMK * 2) + shalf * 32);

    const int fl_row = lane & 15;
    const int fl_k   = (lane >> 4) * 8;
    const uint32_t a_frag0 = smem_u + 2u * (uint32_t)((wm * 32 + fl_row) * SMK + fl_k);
    const uint32_t b_frag0 = smem_u + (uint32_t)TILEB
                           + 2u * (uint32_t)((wn * 64 + fl_row) * SMK + fl_k);

    auto a_off = [&](int kt) -> size_t {
        if (SEL == 1) {   // A[m][k], k = t*128 + j  ->  g_hs[t][m][j]
            int t  = kt >> 2;
            int j0 = (kt & 3) * KTILE;
            return ((size_t)t * B_ + (m0 + srow)) * H_ + j0 + shalf * 16;
        }
        return (size_t)(m0 + srow) * lda + (size_t)kt * KTILE + shalf * 16;
    };

    auto issue_stage = [&](int kt, int st) {
        uint32_t d = smem_u + (uint32_t)(st * STAGE_B) + dst_off;
        const __nv_bfloat16* pa = A + a_off(kt);
        const __nv_bfloat16* pb = Bm + (size_t)(n0 + srow) * ldb
                                + (size_t)kt * KTILE + shalf * 16;
        cp16(d,             pa); cp16(d + 16,         pa + 8);
        cp16(d + TILEB,     pb); cp16(d + TILEB + 16, pb + 8);
    };

#pragma unroll
    for (int p = 0; p < NSTAGE - 1; p++) {
        issue_stage(p, p);
        CP_COMMIT();
    }

    for (int kt = 0; kt < KT; kt++) {
        if (kt + NSTAGE - 1 < KT) {
            issue_stage(kt + NSTAGE - 1, (kt + NSTAGE - 1) & (NSTAGE - 1));
            CP_COMMIT();
            asm volatile("cp.async.wait_group %0;" :: "n"(NSTAGE - 1));
        } else {
            int rem = KT - kt - 1;
            if (rem >= 3)      asm volatile("cp.async.wait_group 3;");
            else if (rem == 2) asm volatile("cp.async.wait_group 2;");
            else if (rem == 1) asm volatile("cp.async.wait_group 1;");
            else               asm volatile("cp.async.wait_group 0;");
        }
        __syncthreads();

        const uint32_t sb = (uint32_t)((kt & (NSTAGE - 1)) * STAGE_B);
#pragma unroll
        for (int s = 0; s < KTILE / 16; s++) {
            uint32_t aH[2][4];
#pragma unroll
            for (int mt = 0; mt < 2; mt++) {
                uint32_t ad = a_frag0 + sb + 2u * (uint32_t)(mt * 16 * SMK + s * 16);
                ldsm4(ad, aH[mt][0], aH[mt][1], aH[mt][2], aH[mt][3]);
            }
#pragma unroll
            for (int p = 0; p < 4; p++) {
                uint32_t bd = b_frag0 + sb + 2u * (uint32_t)(p * 16 * SMK + s * 16);
                uint32_t h0, h1, h2, h3;
                ldsm4(bd, h0, h1, h2, h3);
                uint32_t b0H[2] = {h0, h2}, b1H[2] = {h1, h3};
#pragma unroll
                for (int mt = 0; mt < 2; mt++) {
                    mma_bf16(acc[mt][2 * p],     aH[mt], b0H);
                    mma_bf16(acc[mt][2 * p + 1], aH[mt], b1H);
                }
            }
        }
        __syncthreads();
    }

    if (SEL == 3) {
        // ---- fused LSTM pointwise epilogue (quad-permuted gate layout) ----
        float* csm = (float*)smb;                                   // [128][36]
        __nv_bfloat16* hsm = (__nv_bfloat16*)((char*)smb + 128 * CSTRIDE * 4);
        const int jbase = n0 >> 2;                                  // np*32
        const bool evenL = (lane & 1) == 0;

        // stage c tile
        {
            int row = tid >> 1, half = tid & 1;
            float4* d = (float4*)&csm[row * CSTRIDE + half * 16];
            const float4* s = (const float4*)&g_c[(size_t)(m0 + row) * H_ + jbase + half * 16];
            d[0] = s[0]; d[1] = s[1]; d[2] = s[2]; d[3] = s[3];
        }
        __syncthreads();

#pragma unroll
        for (int mt = 0; mt < 2; mt++)
#pragma unroll
            for (int nt = 0; nt < 8; nt++) {
                int rl0 = wm * 32 + mt * 16 + g;
                size_t xb0 = ((size_t)(m0 + rl0) * T_ + tstep) * G4_
                           + n0 + wn * 64 + nt * 8 + tig * 2;
                size_t xb1 = ((size_t)(m0 + rl0 + 8) * T_ + tstep) * G4_
                           + n0 + wn * 64 + nt * 8 + tig * 2;
                float v0 = acc[mt][nt][0] + g_xg[xb0];
                float v1 = acc[mt][nt][1] + g_xg[xb0 + 1];
                float v2 = acc[mt][nt][2] + g_xg[xb1];
                float v3 = acc[mt][nt][3] + g_xg[xb1 + 1];
                float s0 = __shfl_xor_sync(0xffffffffu, v0, 1);
                float s1 = __shfl_xor_sync(0xffffffffu, v1, 1);
                float s2 = __shfl_xor_sync(0xffffffffu, v2, 1);
                float s3 = __shfl_xor_sync(0xffffffffu, v3, 1);
                float gi, gf, gg, go; int rl;
                if (evenL) { gi = v0; gf = v1; gg = s0; go = s1; rl = rl0; }
                else       { gi = s2; gf = s3; gg = v2; go = v3; rl = rl0 + 8; }
                int jl = wn * 16 + nt * 2 + (tig >> 1);
                float c0 = csm[rl * CSTRIDE + jl];
                float cn = fsigm(gf) * c0 + fsigm(gi) * ftanh(gg);
                csm[rl * CSTRIDE + jl] = cn;
                float h = fsigm(go) * ftanh(cn);
                hsm[rl * HSTRIDE + jl] = __float2bfloat16_rn(h);
            }
        __syncthreads();

        // write back c and h (coalesced)
        {
            int row = tid >> 1, half = tid & 1;
            float4* s = (float4*)&csm[row * CSTRIDE + half * 16];
            float4* d = (float4*)&g_c[(size_t)(m0 + row) * H_ + jbase + half * 16];
            d[0] = s[0]; d[1] = s[1]; d[2] = s[2]; d[3] = s[3];
            if (half == 0) {
                uint4* hs4 = (uint4*)&hsm[row * HSTRIDE];
                uint4* hd  = (uint4*)&g_hs[(size_t)tstep * (B_ * H_)
                                           + (size_t)(m0 + row) * H_ + jbase];
                hd[0] = hs4[0]; hd[1] = hs4[1]; hd[2] = hs4[2]; hd[3] = hs4[3];
            }
        }
        return;
    }

    // ---- standard epilogue ----
    float bv0[8], bv1[8];
#pragma unroll
    for (int nt = 0; nt < 8; nt++) {
        int col = n0 + wn * 64 + nt * 8 + tig * 2;
        float x0 = 0.f, x1 = 0.f;
        if (BIAS == 1) {
            if (col < Nreal)     x0 = bias1[col];
            if (col + 1 < Nreal) x1 = bias1[col + 1];
        } else if (BIAS == 3) {
            x0 = g_bias[col]; x1 = g_bias[col + 1];
        }
        bv0[nt] = x0; bv1[nt] = x1;
    }
#pragma unroll
    for (int mt = 0; mt < 2; mt++) {
#pragma unroll
        for (int i = 0; i < 2; i++) {
            int row = m0 + wm * 32 + mt * 16 + g + i * 8;
#pragma unroll
            for (int nt = 0; nt < 8; nt++) {
                int col = n0 + wn * 64 + nt * 8 + tig * 2;
                if (col < ldc) {
                    float v0 = acc[mt][nt][i * 2]     + bv0[nt];
                    float v1 = acc[mt][nt][i * 2 + 1] + bv1[nt];
                    if (RELU) { v0 = fmaxf(v0, 0.f); v1 = fmaxf(v1, 0.f); }
                    if (col >= Nreal)     v0 = 0.f;
                    if (col + 1 >= Nreal) v1 = 0.f;
                    if (SEL == 1) {
                        __nv_bfloat16 h0 = __float2bfloat16_rn(v0);
                        __nv_bfloat16 h1 = __float2bfloat16_rn(v1);
                        uint32_t hp = (uint32_t)*(uint16_t*)&h0
                                    | ((uint32_t)*(uint16_t*)&h1 << 16);
                        *(uint32_t*)&g_a1[(size_t)row * ldc + col] = hp;
                    } else {
                        *(float2*)&Cf[(size_t)row * ldc + col] = make_float2(v0, v1);
                    }
                }
            }
        }
    }
}

// ---------------- t0 pointwise (quad layout: contiguous float4) ----------------
__global__ __launch_bounds__(256)
void k_point0()
{
    int idx = blockIdx.x * blockDim.x + threadIdx.x;   // b*128 + j
    int b = idx >> 7, j = idx & 127;
    float4 q = *(const float4*)&g_xg[(size_t)b * T_ * G4_ + 4 * j]; // (i,f,g,o)
    float cn = fsigm(q.x) * ftanh(q.z);                 // c_prev = 0
    g_c[idx] = cn;
    float h = fsigm(q.w) * ftanh(cn);
    g_hs[idx] = __float2bfloat16_rn(h);
}

// ---------------- K tail: layer3 (256->64), layer4 (64->2), softmax ----------
__global__ __launch_bounds__(256)
void k_tail(const float* __restrict__ W3, const float* __restrict__ b3,
            const float* __restrict__ W4, const float* __restrict__ b4,
            float* __restrict__ out)
{
    __shared__ float a2s[32 * 256];
    __shared__ float a3[32 * 64];
    __shared__ float lg[64];

    const int tid = threadIdx.x;
    const int rb  = blockIdx.x * 32;
    const int warp = tid >> 5, lane = tid & 31;

    {
        const float4* src = (const float4*)(g_a2 + (size_t)rb * 256);
        float4* dst = (float4*)a2s;
        for (int i = tid; i < 32 * 256 / 4; i += 256) dst[i] = src[i];
    }
    __syncthreads();

    for (int task = warp; task < 64 * 4; task += 8) {
        int o  = task >> 2;
        int r0 = (task & 3) * 8;
        const float4* wrow = (const float4*)(W3 + o * 256);
        float acc[8];
#pragma unroll
        for (int i = 0; i < 8; i++) acc[i] = 0.f;
#pragma unroll
        for (int kb = 0; kb < 2; kb++) {
            float4 w = wrow[kb * 32 + lane];
#pragma unroll
            for (int ri = 0; ri < 8; ri++) {
                float4 xv = *(const float4*)&a2s[(r0 + ri) * 256 + kb * 128 + lane * 4];
                acc[ri] = fmaf(w.x, xv.x, fmaf(w.y, xv.y, fmaf(w.z, xv.z, fmaf(w.w, xv.w, acc[ri]))));
            }
        }
#pragma unroll
        for (int off = 16; off; off >>= 1)
#pragma unroll
            for (int ri = 0; ri < 8; ri++)
                acc[ri] += __shfl_xor_sync(0xffffffffu, acc[ri], off);
        if (lane < 8) a3[(r0 + lane) * 64 + o] = fmaxf(acc[lane] + b3[o], 0.f);
    }
    __syncthreads();

    if (tid < 64) {
        int r = tid >> 1, o = tid & 1;
        float s = b4[o];
        const float* xr = &a3[r * 64];
        const float* wr = &W4[o * 64];
#pragma unroll
        for (int k = 0; k < 64; k++) s = fmaf(xr[k], wr[k], s);
        lg[r * 2 + o] = s;
    }
    __syncthreads();

    if (tid < 32) {
        float z0 = lg[tid * 2], z1 = lg[tid * 2 + 1];
        float m = fmaxf(z0, z1);
        float e0 = expf(z0 - m), e1 = expf(z1 - m);
        float inv = 1.f / (e0 + e1);
        out[(rb + tid) * 2]     = e0 * inv;
        out[(rb + tid) * 2 + 1] = e1 * inv;
    }
}

// ---------------- launcher ----------------------------------------------------
extern "C" void kernel_launch(void* const* d_in, const int* in_sizes, int n_in,
                              void* d_out, int out_size)
{
    const float* x1   = (const float*)d_in[0];
    const float* x2   = (const float*)d_in[1];
    const float* W_ih = (const float*)d_in[2];
    const float* W_hh = (const float*)d_in[3];
    const float* b_ih = (const float*)d_in[4];
    const float* b_hh = (const float*)d_in[5];
    const float* W1   = (const float*)d_in[6];
    const float* b1   = (const float*)d_in[7];
    const float* W2   = (const float*)d_in[8];
    const float* b2   = (const float*)d_in[9];
    const float* W3   = (const float*)d_in[10];
    const float* b3   = (const float*)d_in[11];
    const float* W4   = (const float*)d_in[12];
    const float* b4   = (const float*)d_in[13];
    float* out = (float*)d_out;

    const int gemm_smem = NSTAGE * STAGE_B;   // 81920 B

    cudaFuncSetAttribute(gemm_pipe<0, 3, false>,
                         cudaFuncAttributeMaxDynamicSharedMemorySize, gemm_smem);
    cudaFuncSetAttribute(gemm_pipe<3, 0, false>,
                         cudaFuncAttributeMaxDynamicSharedMemorySize, gemm_smem);
    cudaFuncSetAttribute(gemm_pipe<1, 1, true>,
                         cudaFuncAttributeMaxDynamicSharedMemorySize, gemm_smem);
    cudaFuncSetAttribute(gemm_pipe<2, 1, true>,
                         cudaFuncAttributeMaxDynamicSharedMemorySize, gemm_smem);

    // prep
    k_prep_x<<<(M_ * XK_ + 255) / 256, 256>>>(x1, x2);
    {
        int total = NW_WIH + NW_W1 + NW_W2 + NW_WHH + G4_;
        k_prep_w<<<(total + 255) / 256, 256>>>(W_ih, W1, W2, W_hh, b_ih, b_hh);
    }

    // K1: g_xg = xc @ wih^T + g_bias   [81920 x 512], K=576  (permuted cols)
    {
        dim3 grid(G4_ / 128, M_ / 128);
        gemm_pipe<0, 3, false><<<grid, 256, gemm_smem>>>(
            XK_, XK_, XK_ / KTILE, G4_, G4_, nullptr, 0);
    }

    // LSTM: t=0 pointwise, then 4 x fused (gate GEMM + pointwise epilogue)
    k_point0<<<(B_ * H_) / 256, 256>>>();
    for (int t = 1; t < T_; t++) {
        dim3 grid(G4_ / 128, B_ / 128);
        gemm_pipe<3, 0, false><<<grid, 256, gemm_smem>>>(
            H_, H_, H_ / KTILE, G4_, G4_, nullptr, t);
    }

    // L1: g_a1 = relu(hs-slab @ w1^T + b1)   [16384 x 531->544], K=640
    {
        dim3 grid(5, B_ / 128);
        gemm_pipe<1, 1, true><<<grid, 256, gemm_smem>>>(
            0, 640, 640 / KTILE, 531, 544, b1, 0);
    }

    // L2: g_a2 = relu(a1 @ w2^T + b2)   [16384 x 256], K=544
    {
        dim3 grid(2, B_ / 128);
        gemm_pipe<2, 1, true><<<grid, 256, gemm_smem>>>(
            544, 544, 544 / KTILE, 256, 256, b2, 0);
    }

    // tail
    k_tail<<<B_ / 32, 256>>>(W3, b3, W4, b4, out);
}

// round 13
// speedup vs baseline: 2.6380x; 1.0307x over previous
#include <cuda_runtime.h>
#include <cuda_bf16.h>
#include <math.h>
#include <stdint.h>

#define B_     16384
#define T_     5
#define F1_    300
#define F2_    251
#define IN_    551
#define H_     128
#define G4_    512
#define M_     (B_ * T_)          // 81920
#define XK_    576                // concat K padded to 32-multiple
#define WK_    704                // H_ + XK_  (combined recurrence K)
#define WKT    (WK_ / 32)         // 22 k-tiles

// Gate columns PERMUTED quad-interleaved: col 4j+q = original q*128+j.

// ---------------- scratch (device globals; device-code access ONLY) ----------
__device__ float g_c[B_ * H_];                   // [16384][128] fp32 cell state
__device__ float g_a2[B_ * 256];                 // [16384][256] fp32
__device__ float g_bias[G4_];                    // permuted b_ih+b_hh

__device__ __nv_bfloat16 g_xc[M_ * XK_];         // concat(x1,x2) bf16 [81920][576]
__device__ __nv_bfloat16 g_wcat[G4_ * WK_];      // [Whh | Wih] permuted rows [512][704]
__device__ __nv_bfloat16 g_w1[640 * 640];        // W1 padded
__device__ __nv_bfloat16 g_w2[256 * 544];        // W2 padded
__device__ __nv_bfloat16 g_hs[T_ * B_ * H_];     // h slabs [5][16384][128]
__device__ __nv_bfloat16 g_a1[B_ * 544];         // MLP L1 out [16384][544]

// ---------------- fast gate functions ----------------------------------------
__device__ __forceinline__ float ftanh(float x) {
    float y; asm("tanh.approx.f32 %0, %1;" : "=f"(y) : "f"(x)); return y;
}
__device__ __forceinline__ float fsigm(float x) {
    return fmaf(0.5f, ftanh(0.5f * x), 0.5f);
}

// ---------------- prep: concat x ----------------------------------------------
__global__ void k_prep_x(const float* __restrict__ x1, const float* __restrict__ x2)
{
    int idx = blockIdx.x * blockDim.x + threadIdx.x;
    if (idx >= M_ * XK_) return;
    int m = idx / XK_, k = idx % XK_;
    float v = 0.f;
    if (k < F1_)      v = x1[m * F1_ + k];
    else if (k < IN_) v = x2[m * F2_ + (k - F1_)];
    g_xc[idx] = __float2bfloat16_rn(v);
}

// ---------------- prep: weights (gate permuted, Whh|Wih merged) ----------------
#define NW_WCAT (G4_ * WK_)       // 360448
#define NW_W1   (640 * 640)       // 409600
#define NW_W2   (256 * 544)       // 139264
__global__ void k_prep_w(const float* __restrict__ Wih, const float* __restrict__ W1,
                         const float* __restrict__ W2,  const float* __restrict__ Whh,
                         const float* __restrict__ bih, const float* __restrict__ bhh)
{
    int idx = blockIdx.x * blockDim.x + threadIdx.x;
    if (idx < NW_WCAT) {
        int n = idx / WK_, k = idx % WK_;
        int on = (n & 3) * 128 + (n >> 2);      // permuted -> original gate row
        float v;
        if (k < H_)                 v = Whh[on * H_ + k];
        else if (k - H_ < IN_)      v = Wih[on * IN_ + (k - H_)];
        else                        v = 0.f;
        g_wcat[idx] = __float2bfloat16_rn(v);
        return;
    }
    idx -= NW_WCAT;
    if (idx < NW_W1) {
        int n = idx / 640, k = idx % 640;
        g_w1[idx] = __float2bfloat16_rn((n < 531) ? W1[n * 640 + k] : 0.f);
        return;
    }
    idx -= NW_W1;
    if (idx < NW_W2) {
        int n = idx / 544, k = idx % 544;
        g_w2[idx] = __float2bfloat16_rn((k < 531) ? W2[n * 531 + k] : 0.f);
        return;
    }
    idx -= NW_W2;
    if (idx < G4_) {
        int on = (idx & 3) * 128 + (idx >> 2);
        g_bias[idx] = bih[on] + bhh[on];
    }
}

// ---------------- shared low-level helpers -------------------------------------
__device__ __forceinline__ void cp16(uint32_t d, const void* s) {
    asm volatile("cp.async.cg.shared.global [%0], [%1], 16;" :: "r"(d), "l"(s));
}
#define CP_COMMIT() asm volatile("cp.async.commit_group;")

__device__ __forceinline__ void mma_bf16(float* c, const uint32_t* a, const uint32_t* b) {
    asm volatile(
        "mma.sync.aligned.m16n8k16.row.col.f32.bf16.bf16.f32 "
        "{%0,%1,%2,%3}, {%4,%5,%6,%7}, {%8,%9}, {%0,%1,%2,%3};"
        : "+f"(c[0]), "+f"(c[1]), "+f"(c[2]), "+f"(c[3])
        : "r"(a[0]), "r"(a[1]), "r"(a[2]), "r"(a[3]), "r"(b[0]), "r"(b[1]));
}

__device__ __forceinline__ void ldsm4(uint32_t addr, uint32_t& r0, uint32_t& r1,
                                      uint32_t& r2, uint32_t& r3) {
    asm volatile("ldmatrix.sync.aligned.m8n8.x4.shared.b16 {%0,%1,%2,%3}, [%4];"
                 : "=r"(r0), "=r"(r1), "=r"(r2), "=r"(r3) : "r"(addr));
}

#define KTILE   32
#define SMK     40
#define TILEB   (128 * SMK * 2)         // 10240 B
#define STAGE_B (2 * TILEB)             // 20480 B
#define NSTAGE  4
#define CSTRIDE 36
#define HSTRIDE 40

// ================= fused recurrence step =======================================
// gates_t = [h_{t-1} | x_t] @ wcat^T + bias  ->  LSTM pointwise  -> g_c, g_hs[t]
// K = 704 (t>0) or 576 (t=0, skip h k-tiles). Fused pointwise epilogue.
__global__ __launch_bounds__(256, 2)
void k_step(int tstep)
{
    extern __shared__ __align__(16) __nv_bfloat16 smb[];
    const uint32_t smem_u = (uint32_t)__cvta_generic_to_shared(smb);

    const int tid  = threadIdx.x;
    const int n0   = blockIdx.x * 128;
    const int m0   = blockIdx.y * 128;
    const int lane = tid & 31;
    const int warp = tid >> 5;
    const int wm   = warp & 3;
    const int wn   = warp >> 2;
    const int g    = lane >> 2;
    const int tig  = lane & 3;

    const __nv_bfloat16* hprev = g_hs + (size_t)(tstep - 1) * (B_ * H_);
    const int kt0 = (tstep == 0) ? 4 : 0;      // skip h tiles at t=0
    const int KTe = WKT - kt0;

    float acc[2][8][4];
#pragma unroll
    for (int mt = 0; mt < 2; mt++)
#pragma unroll
        for (int nt = 0; nt < 8; nt++)
#pragma unroll
            for (int i = 0; i < 4; i++) acc[mt][nt][i] = 0.f;

    const int srow = tid >> 1;
    const int shalf = tid & 1;
    const uint32_t dst_off = (uint32_t)(srow * (SMK * 2) + shalf * 32);

    const int fl_row = lane & 15;
    const int fl_k   = (lane >> 4) * 8;
    const uint32_t a_frag0 = smem_u + 2u * (uint32_t)((wm * 32 + fl_row) * SMK + fl_k);
    const uint32_t b_frag0 = smem_u + (uint32_t)TILEB
                           + 2u * (uint32_t)((wn * 64 + fl_row) * SMK + fl_k);

    auto issue_stage = [&](int kt, int st) {
        uint32_t d = smem_u + (uint32_t)(st * STAGE_B) + dst_off;
        const __nv_bfloat16* pa;
        if (kt < 4) {   // h part: k = kt*32 .. (never taken at t=0)
            pa = hprev + (size_t)(m0 + srow) * H_ + kt * KTILE + shalf * 16;
        } else {        // x part: row (b*T + t), k' = (kt-4)*32
            pa = g_xc + ((size_t)(m0 + srow) * T_ + tstep) * XK_
               + (kt - 4) * KTILE + shalf * 16;
        }
        const __nv_bfloat16* pb = g_wcat + (size_t)(n0 + srow) * WK_
                                + (size_t)kt * KTILE + shalf * 16;
        cp16(d,             pa); cp16(d + 16,         pa + 8);
        cp16(d + TILEB,     pb); cp16(d + TILEB + 16, pb + 8);
    };

#pragma unroll
    for (int p = 0; p < NSTAGE - 1; p++) {
        issue_stage(kt0 + p, p);
        CP_COMMIT();
    }

    for (int ki = 0; ki < KTe; ki++) {
        if (ki + NSTAGE - 1 < KTe) {
            issue_stage(kt0 + ki + NSTAGE - 1, (ki + NSTAGE - 1) & (NSTAGE - 1));
            CP_COMMIT();
            asm volatile("cp.async.wait_group %0;" :: "n"(NSTAGE - 1));
        } else {
            int rem = KTe - ki - 1;
            if (rem >= 3)      asm volatile("cp.async.wait_group 3;");
            else if (rem == 2) asm volatile("cp.async.wait_group 2;");
            else if (rem == 1) asm volatile("cp.async.wait_group 1;");
            else               asm volatile("cp.async.wait_group 0;");
        }
        __syncthreads();

        const uint32_t sb = (uint32_t)((ki & (NSTAGE - 1)) * STAGE_B);
#pragma unroll
        for (int s = 0; s < KTILE / 16; s++) {
            uint32_t aH[2][4];
#pragma unroll
            for (int mt = 0; mt < 2; mt++) {
                uint32_t ad = a_frag0 + sb + 2u * (uint32_t)(mt * 16 * SMK + s * 16);
                ldsm4(ad, aH[mt][0], aH[mt][1], aH[mt][2], aH[mt][3]);
            }
#pragma unroll
            for (int p = 0; p < 4; p++) {
                uint32_t bd = b_frag0 + sb + 2u * (uint32_t)(p * 16 * SMK + s * 16);
                uint32_t h0, h1, h2, h3;
                ldsm4(bd, h0, h1, h2, h3);
                uint32_t b0H[2] = {h0, h2}, b1H[2] = {h1, h3};
#pragma unroll
                for (int mt = 0; mt < 2; mt++) {
                    mma_bf16(acc[mt][2 * p],     aH[mt], b0H);
                    mma_bf16(acc[mt][2 * p + 1], aH[mt], b1H);
                }
            }
        }
        __syncthreads();
    }

    // ---- fused LSTM pointwise epilogue (quad-permuted gate layout) ----
    float* csm = (float*)smb;                                   // [128][36]
    __nv_bfloat16* hsm = (__nv_bfloat16*)((char*)smb + 128 * CSTRIDE * 4);
    const int jbase = n0 >> 2;
    const bool evenL = (lane & 1) == 0;

    // stage c tile (zeros at t=0)
    {
        int row = tid >> 1, half = tid & 1;
        float4* d = (float4*)&csm[row * CSTRIDE + half * 16];
        if (tstep == 0) {
            float4 z = make_float4(0.f, 0.f, 0.f, 0.f);
            d[0] = z; d[1] = z; d[2] = z; d[3] = z;
        } else {
            const float4* s = (const float4*)&g_c[(size_t)(m0 + row) * H_ + jbase + half * 16];
            d[0] = s[0]; d[1] = s[1]; d[2] = s[2]; d[3] = s[3];
        }
    }
    __syncthreads();

    float bv0[8], bv1[8];
#pragma unroll
    for (int nt = 0; nt < 8; nt++) {
        int col = n0 + wn * 64 + nt * 8 + tig * 2;
        bv0[nt] = g_bias[col];
        bv1[nt] = g_bias[col + 1];
    }

#pragma unroll
    for (int mt = 0; mt < 2; mt++)
#pragma unroll
        for (int nt = 0; nt < 8; nt++) {
            int rl0 = wm * 32 + mt * 16 + g;
            float v0 = acc[mt][nt][0] + bv0[nt];
            float v1 = acc[mt][nt][1] + bv1[nt];
            float v2 = acc[mt][nt][2] + bv0[nt];
            float v3 = acc[mt][nt][3] + bv1[nt];
            float s0 = __shfl_xor_sync(0xffffffffu, v0, 1);
            float s1 = __shfl_xor_sync(0xffffffffu, v1, 1);
            float s2 = __shfl_xor_sync(0xffffffffu, v2, 1);
            float s3 = __shfl_xor_sync(0xffffffffu, v3, 1);
            float gi, gf, gg, go; int rl;
            if (evenL) { gi = v0; gf = v1; gg = s0; go = s1; rl = rl0; }
            else       { gi = s2; gf = s3; gg = v2; go = v3; rl = rl0 + 8; }
            int jl = wn * 16 + nt * 2 + (tig >> 1);
            float c0 = csm[rl * CSTRIDE + jl];
            float cn = fsigm(gf) * c0 + fsigm(gi) * ftanh(gg);
            csm[rl * CSTRIDE + jl] = cn;
            float h = fsigm(go) * ftanh(cn);
            hsm[rl * HSTRIDE + jl] = __float2bfloat16_rn(h);
        }
    __syncthreads();

    // write back c and h (coalesced)
    {
        int row = tid >> 1, half = tid & 1;
        float4* s = (float4*)&csm[row * CSTRIDE + half * 16];
        float4* d = (float4*)&g_c[(size_t)(m0 + row) * H_ + jbase + half * 16];
        d[0] = s[0]; d[1] = s[1]; d[2] = s[2]; d[3] = s[3];
        if (half == 0) {
            uint4* hs4 = (uint4*)&hsm[row * HSTRIDE];
            uint4* hd  = (uint4*)&g_hs[(size_t)tstep * (B_ * H_)
                                       + (size_t)(m0 + row) * H_ + jbase];
            hd[0] = hs4[0]; hd[1] = hs4[1]; hd[2] = hs4[2]; hd[3] = hs4[3];
        }
    }
}

// ================= legacy-mma pipelined GEMM (validated; L1/L2) ================
// SEL: 1 = L1 (hs-slab @ w1 -> g_a1 bf16, bias+relu)
//      2 = L2 (a1 @ w2 -> g_a2 fp32, bias+relu)
template<int SEL>
__global__ __launch_bounds__(256, 2)
void gemm_pipe(int lda, int ldb, int KT, int Nreal, int ldc,
               const float* __restrict__ bias1)
{
    const __nv_bfloat16* A = (SEL == 2) ? g_a1 : g_hs;
    const __nv_bfloat16* Bm = (SEL == 1) ? g_w1 : g_w2;

    extern __shared__ __align__(16) __nv_bfloat16 smb[];
    const uint32_t smem_u = (uint32_t)__cvta_generic_to_shared(smb);

    const int tid  = threadIdx.x;
    const int n0   = blockIdx.x * 128;
    const int m0   = blockIdx.y * 128;
    const int lane = tid & 31;
    const int warp = tid >> 5;
    const int wm   = warp & 3;
    const int wn   = warp >> 2;
    const int g    = lane >> 2;
    const int tig  = lane & 3;

    float acc[2][8][4];
#pragma unroll
    for (int mt = 0; mt < 2; mt++)
#pragma unroll
        for (int nt = 0; nt < 8; nt++)
#pragma unroll
            for (int i = 0; i < 4; i++) acc[mt][nt][i] = 0.f;

    const int srow = tid >> 1;
    const int shalf = tid & 1;
    const uint32_t dst_off = (uint32_t)(srow * (SMK * 2) + shalf * 32);

    const int fl_row = lane & 15;
    const int fl_k   = (lane >> 4) * 8;
    const uint32_t a_frag0 = smem_u + 2u * (uint32_t)((wm * 32 + fl_row) * SMK + fl_k);
    const uint32_t b_frag0 = smem_u + (uint32_t)TILEB
                           + 2u * (uint32_t)((wn * 64 + fl_row) * SMK + fl_k);

    auto a_off = [&](int kt) -> size_t {
        if (SEL == 1) {
            int t  = kt >> 2;
            int j0 = (kt & 3) * KTILE;
            return ((size_t)t * B_ + (m0 + srow)) * H_ + j0 + shalf * 16;
        }
        return (size_t)(m0 + srow) * lda + (size_t)kt * KTILE + shalf * 16;
    };

    auto issue_stage = [&](int kt, int st) {
        uint32_t d = smem_u + (uint32_t)(st * STAGE_B) + dst_off;
        const __nv_bfloat16* pa = A + a_off(kt);
        const __nv_bfloat16* pb = Bm + (size_t)(n0 + srow) * ldb
                                + (size_t)kt * KTILE + shalf * 16;
        cp16(d,             pa); cp16(d + 16,         pa + 8);
        cp16(d + TILEB,     pb); cp16(d + TILEB + 16, pb + 8);
    };

#pragma unroll
    for (int p = 0; p < NSTAGE - 1; p++) {
        issue_stage(p, p);
        CP_COMMIT();
    }

    for (int kt = 0; kt < KT; kt++) {
        if (kt + NSTAGE - 1 < KT) {
            issue_stage(kt + NSTAGE - 1, (kt + NSTAGE - 1) & (NSTAGE - 1));
            CP_COMMIT();
            asm volatile("cp.async.wait_group %0;" :: "n"(NSTAGE - 1));
        } else {
            int rem = KT - kt - 1;
            if (rem >= 3)      asm volatile("cp.async.wait_group 3;");
            else if (rem == 2) asm volatile("cp.async.wait_group 2;");
            else if (rem == 1) asm volatile("cp.async.wait_group 1;");
            else               asm volatile("cp.async.wait_group 0;");
        }
        __syncthreads();

        const uint32_t sb = (uint32_t)((kt & (NSTAGE - 1)) * STAGE_B);
#pragma unroll
        for (int s = 0; s < KTILE / 16; s++) {
            uint32_t aH[2][4];
#pragma unroll
            for (int mt = 0; mt < 2; mt++) {
                uint32_t ad = a_frag0 + sb + 2u * (uint32_t)(mt * 16 * SMK + s * 16);
                ldsm4(ad, aH[mt][0], aH[mt][1], aH[mt][2], aH[mt][3]);
            }
#pragma unroll
            for (int p = 0; p < 4; p++) {
                uint32_t bd = b_frag0 + sb + 2u * (uint32_t)(p * 16 * SMK + s * 16);
                uint32_t h0, h1, h2, h3;
                ldsm4(bd, h0, h1, h2, h3);
                uint32_t b0H[2] = {h0, h2}, b1H[2] = {h1, h3};
#pragma unroll
                for (int mt = 0; mt < 2; mt++) {
                    mma_bf16(acc[mt][2 * p],     aH[mt], b0H);
                    mma_bf16(acc[mt][2 * p + 1], aH[mt], b1H);
                }
            }
        }
        __syncthreads();
    }

    float bv0[8], bv1[8];
#pragma unroll
    for (int nt = 0; nt < 8; nt++) {
        int col = n0 + wn * 64 + nt * 8 + tig * 2;
        bv0[nt] = (col < Nreal)     ? bias1[col]     : 0.f;
        bv1[nt] = (col + 1 < Nreal) ? bias1[col + 1] : 0.f;
    }
#pragma unroll
    for (int mt = 0; mt < 2; mt++) {
#pragma unroll
        for (int i = 0; i < 2; i++) {
            int row = m0 + wm * 32 + mt * 16 + g + i * 8;
#pragma unroll
            for (int nt = 0; nt < 8; nt++) {
                int col = n0 + wn * 64 + nt * 8 + tig * 2;
                if (col < ldc) {
                    float v0 = fmaxf(acc[mt][nt][i * 2]     + bv0[nt], 0.f);
                    float v1 = fmaxf(acc[mt][nt][i * 2 + 1] + bv1[nt], 0.f);
                    if (col >= Nreal)     v0 = 0.f;
                    if (col + 1 >= Nreal) v1 = 0.f;
                    if (SEL == 1) {
                        __nv_bfloat16 h0 = __float2bfloat16_rn(v0);
                        __nv_bfloat16 h1 = __float2bfloat16_rn(v1);
                        uint32_t hp = (uint32_t)*(uint16_t*)&h0
                                    | ((uint32_t)*(uint16_t*)&h1 << 16);
                        *(uint32_t*)&g_a1[(size_t)row * ldc + col] = hp;
                    } else {
                        *(float2*)&g_a2[(size_t)row * ldc + col] = make_float2(v0, v1);
                    }
                }
            }
        }
    }
}

// ---------------- K tail --------------------------------------------------------
__global__ __launch_bounds__(256)
void k_tail(const float* __restrict__ W3, const float* __restrict__ b3,
            const float* __restrict__ W4, const float* __restrict__ b4,
            float* __restrict__ out)
{
    __shared__ float a2s[32 * 256];
    __shared__ float a3[32 * 64];
    __shared__ float lg[64];

    const int tid = threadIdx.x;
    const int rb  = blockIdx.x * 32;
    const int warp = tid >> 5, lane = tid & 31;

    {
        const float4* src = (const float4*)(g_a2 + (size_t)rb * 256);
        float4* dst = (float4*)a2s;
        for (int i = tid; i < 32 * 256 / 4; i += 256) dst[i] = src[i];
    }
    __syncthreads();

    for (int task = warp; task < 64 * 4; task += 8) {
        int o  = task >> 2;
        int r0 = (task & 3) * 8;
        const float4* wrow = (const float4*)(W3 + o * 256);
        float acc[8];
#pragma unroll
        for (int i = 0; i < 8; i++) acc[i] = 0.f;
#pragma unroll
        for (int kb = 0; kb < 2; kb++) {
            float4 w = wrow[kb * 32 + lane];
#pragma unroll
            for (int ri = 0; ri < 8; ri++) {
                float4 xv = *(const float4*)&a2s[(r0 + ri) * 256 + kb * 128 + lane * 4];
                acc[ri] = fmaf(w.x, xv.x, fmaf(w.y, xv.y, fmaf(w.z, xv.z, fmaf(w.w, xv.w, acc[ri]))));
            }
        }
#pragma unroll
        for (int off = 16; off; off >>= 1)
#pragma unroll
            for (int ri = 0; ri < 8; ri++)
                acc[ri] += __shfl_xor_sync(0xffffffffu, acc[ri], off);
        if (lane < 8) a3[(r0 + lane) * 64 + o] = fmaxf(acc[lane] + b3[o], 0.f);
    }
    __syncthreads();

    if (tid < 64) {
        int r = tid >> 1, o = tid & 1;
        float s = b4[o];
        const float* xr = &a3[r * 64];
        const float* wr = &W4[o * 64];
#pragma unroll
        for (int k = 0; k < 64; k++) s = fmaf(xr[k], wr[k], s);
        lg[r * 2 + o] = s;
    }
    __syncthreads();

    if (tid < 32) {
        float z0 = lg[tid * 2], z1 = lg[tid * 2 + 1];
        float m = fmaxf(z0, z1);
        float e0 = expf(z0 - m), e1 = expf(z1 - m);
        float inv = 1.f / (e0 + e1);
        out[(rb + tid) * 2]     = e0 * inv;
        out[(rb + tid) * 2 + 1] = e1 * inv;
    }
}

// ---------------- launcher ----------------------------------------------------
extern "C" void kernel_launch(void* const* d_in, const int* in_sizes, int n_in,
                              void* d_out, int out_size)
{
    const float* x1   = (const float*)d_in[0];
    const float* x2   = (const float*)d_in[1];
    const float* W_ih = (const float*)d_in[2];
    const float* W_hh = (const float*)d_in[3];
    const float* b_ih = (const float*)d_in[4];
    const float* b_hh = (const float*)d_in[5];
    const float* W1   = (const float*)d_in[6];
    const float* b1   = (const float*)d_in[7];
    const float* W2   = (const float*)d_in[8];
    const float* b2   = (const float*)d_in[9];
    const float* W3   = (const float*)d_in[10];
    const float* b3   = (const float*)d_in[11];
    const float* W4   = (const float*)d_in[12];
    const float* b4   = (const float*)d_in[13];
    float* out = (float*)d_out;

    const int gemm_smem = NSTAGE * STAGE_B;   // 81920 B

    cudaFuncSetAttribute(k_step, cudaFuncAttributeMaxDynamicSharedMemorySize, gemm_smem);
    cudaFuncSetAttribute(gemm_pipe<1>,
                         cudaFuncAttributeMaxDynamicSharedMemorySize, gemm_smem);
    cudaFuncSetAttribute(gemm_pipe<2>,
                         cudaFuncAttributeMaxDynamicSharedMemorySize, gemm_smem);

    // prep
    k_prep_x<<<(M_ * XK_ + 255) / 256, 256>>>(x1, x2);
    {
        int total = NW_WCAT + NW_W1 + NW_W2 + G4_;
        k_prep_w<<<(total + 255) / 256, 256>>>(W_ih, W1, W2, W_hh, b_ih, b_hh);
    }

    // fused recurrence: 5 steps of [h|x] @ wcat^T + LSTM pointwise
    for (int t = 0; t < T_; t++) {
        dim3 grid(G4_ / 128, B_ / 128);
        k_step<<<grid, 256, gemm_smem>>>(t);
    }

    // L1: g_a1 = relu(hs-slab @ w1^T + b1)   [16384 x 531->544], K=640
    {
        dim3 grid(5, B_ / 128);
        gemm_pipe<1><<<grid, 256, gemm_smem>>>(0, 640, 640 / KTILE, 531, 544, b1);
    }

    // L2: g_a2 = relu(a1 @ w2^T + b2)   [16384 x 256], K=544
    {
        dim3 grid(2, B_ / 128);
        gemm_pipe<2><<<grid, 256, gemm_smem>>>(544, 544, 544 / KTILE, 256, 256, b2);
    }

    // tail
    k_tail<<<B_ / 32, 256>>>(W3, b3, W4, b4, out);
}

// round 14
// speedup vs baseline: 2.7030x; 1.0246x over previous
#include <cuda_runtime.h>
#include <cuda_bf16.h>
#include <math.h>
#include <stdint.h>

#define B_     16384
#define T_     5
#define F1_    300
#define F2_    251
#define IN_    551
#define H_     128
#define G4_    512
#define M_     (B_ * T_)          // 81920
#define XK_    576                // concat K padded to 32-multiple
#define WK_    704                // H_ + XK_  (combined recurrence K)
#define WKT    (WK_ / 32)         // 22 k-tiles

// Gate columns PERMUTED quad-interleaved: col 4j+q = original q*128+j.

// ---------------- scratch (device globals; device-code access ONLY) ----------
__device__ float g_c[B_ * H_];                   // [16384][128] fp32 cell state
__device__ float g_a2[B_ * 256];                 // [16384][256] fp32
__device__ float g_bias[G4_];                    // permuted b_ih+b_hh

__device__ __nv_bfloat16 g_xc[M_ * XK_];         // concat(x1,x2) bf16 [81920][576]
__device__ __nv_bfloat16 g_wcat[G4_ * WK_];      // [Whh | Wih] permuted rows [512][704]
__device__ __nv_bfloat16 g_w1[640 * 640];        // W1 padded
__device__ __nv_bfloat16 g_w2[256 * 544];        // W2 padded
__device__ __nv_bfloat16 g_hs[T_ * B_ * H_];     // h slabs [5][16384][128]
__device__ __nv_bfloat16 g_a1[B_ * 544];         // MLP L1 out [16384][544]

// ---------------- fast gate functions ----------------------------------------
__device__ __forceinline__ float ftanh(float x) {
    float y; asm("tanh.approx.f32 %0, %1;" : "=f"(y) : "f"(x)); return y;
}
__device__ __forceinline__ float fsigm(float x) {
    return fmaf(0.5f, ftanh(0.5f * x), 0.5f);
}

// ---------------- prep: concat x ----------------------------------------------
__global__ void k_prep_x(const float* __restrict__ x1, const float* __restrict__ x2)
{
    int idx = blockIdx.x * blockDim.x + threadIdx.x;
    if (idx >= M_ * XK_) return;
    int m = idx / XK_, k = idx % XK_;
    float v = 0.f;
    if (k < F1_)      v = x1[m * F1_ + k];
    else if (k < IN_) v = x2[m * F2_ + (k - F1_)];
    g_xc[idx] = __float2bfloat16_rn(v);
}

// ---------------- prep: weights (gate permuted, Whh|Wih merged) ----------------
#define NW_WCAT (G4_ * WK_)       // 360448
#define NW_W1   (640 * 640)       // 409600
#define NW_W2   (256 * 544)       // 139264
__global__ void k_prep_w(const float* __restrict__ Wih, const float* __restrict__ W1,
                         const float* __restrict__ W2,  const float* __restrict__ Whh,
                         const float* __restrict__ bih, const float* __restrict__ bhh)
{
    int idx = blockIdx.x * blockDim.x + threadIdx.x;
    if (idx < NW_WCAT) {
        int n = idx / WK_, k = idx % WK_;
        int on = (n & 3) * 128 + (n >> 2);      // permuted -> original gate row
        float v;
        if (k < H_)                 v = Whh[on * H_ + k];
        else if (k - H_ < IN_)      v = Wih[on * IN_ + (k - H_)];
        else                        v = 0.f;
        g_wcat[idx] = __float2bfloat16_rn(v);
        return;
    }
    idx -= NW_WCAT;
    if (idx < NW_W1) {
        int n = idx / 640, k = idx % 640;
        g_w1[idx] = __float2bfloat16_rn((n < 531) ? W1[n * 640 + k] : 0.f);
        return;
    }
    idx -= NW_W1;
    if (idx < NW_W2) {
        int n = idx / 544, k = idx % 544;
        g_w2[idx] = __float2bfloat16_rn((k < 531) ? W2[n * 531 + k] : 0.f);
        return;
    }
    idx -= NW_W2;
    if (idx < G4_) {
        int on = (idx & 3) * 128 + (idx >> 2);
        g_bias[idx] = bih[on] + bhh[on];
    }
}

// ---------------- shared low-level helpers -------------------------------------
__device__ __forceinline__ void cp16(uint32_t d, const void* s) {
    asm volatile("cp.async.cg.shared.global [%0], [%1], 16;" :: "r"(d), "l"(s));
}
#define CP_COMMIT() asm volatile("cp.async.commit_group;")

__device__ __forceinline__ void mma_bf16(float* c, const uint32_t* a, const uint32_t* b) {
    asm volatile(
        "mma.sync.aligned.m16n8k16.row.col.f32.bf16.bf16.f32 "
        "{%0,%1,%2,%3}, {%4,%5,%6,%7}, {%8,%9}, {%0,%1,%2,%3};"
        : "+f"(c[0]), "+f"(c[1]), "+f"(c[2]), "+f"(c[3])
        : "r"(a[0]), "r"(a[1]), "r"(a[2]), "r"(a[3]), "r"(b[0]), "r"(b[1]));
}

__device__ __forceinline__ void ldsm4(uint32_t addr, uint32_t& r0, uint32_t& r1,
                                      uint32_t& r2, uint32_t& r3) {
    asm volatile("ldmatrix.sync.aligned.m8n8.x4.shared.b16 {%0,%1,%2,%3}, [%4];"
                 : "=r"(r0), "=r"(r1), "=r"(r2), "=r"(r3) : "r"(addr));
}

// wait so that at most `rem` cp.async groups remain outstanding
__device__ __forceinline__ void cp_wait_rem(int rem) {
    if (rem >= 2)      asm volatile("cp.async.wait_group 2;");
    else if (rem == 1) asm volatile("cp.async.wait_group 1;");
    else               asm volatile("cp.async.wait_group 0;");
}

#define KTILE   32
#define SMK     40
#define TILEB   (128 * SMK * 2)         // 10240 B
#define STAGE_B (2 * TILEB)             // 20480 B
#define NSTAGE  4
#define CSTRIDE 36
#define HSTRIDE 40

// ================= fused recurrence step =======================================
// gates_t = [h_{t-1} | x_t] @ wcat^T + bias  ->  LSTM pointwise  -> g_c, g_hs[t]
// K = 704 (t>0) or 576 (t=0). ONE __syncthreads per k-tile.
__global__ __launch_bounds__(256, 2)
void k_step(int tstep)
{
    extern __shared__ __align__(16) __nv_bfloat16 smb[];
    const uint32_t smem_u = (uint32_t)__cvta_generic_to_shared(smb);

    const int tid  = threadIdx.x;
    const int n0   = blockIdx.x * 128;
    const int m0   = blockIdx.y * 128;
    const int lane = tid & 31;
    const int warp = tid >> 5;
    const int wm   = warp & 3;
    const int wn   = warp >> 2;
    const int g    = lane >> 2;
    const int tig  = lane & 3;

    const __nv_bfloat16* hprev = g_hs + (size_t)(tstep - 1) * (B_ * H_);
    const int kt0 = (tstep == 0) ? 4 : 0;      // skip h tiles at t=0
    const int KTe = WKT - kt0;

    float acc[2][8][4];
#pragma unroll
    for (int mt = 0; mt < 2; mt++)
#pragma unroll
        for (int nt = 0; nt < 8; nt++)
#pragma unroll
            for (int i = 0; i < 4; i++) acc[mt][nt][i] = 0.f;

    const int srow = tid >> 1;
    const int shalf = tid & 1;
    const uint32_t dst_off = (uint32_t)(srow * (SMK * 2) + shalf * 32);

    const int fl_row = lane & 15;
    const int fl_k   = (lane >> 4) * 8;
    const uint32_t a_frag0 = smem_u + 2u * (uint32_t)((wm * 32 + fl_row) * SMK + fl_k);
    const uint32_t b_frag0 = smem_u + (uint32_t)TILEB
                           + 2u * (uint32_t)((wn * 64 + fl_row) * SMK + fl_k);

    auto issue_stage = [&](int kt, int st) {
        uint32_t d = smem_u + (uint32_t)(st * STAGE_B) + dst_off;
        const __nv_bfloat16* pa;
        if (kt < 4) {   // h part (never taken at t=0)
            pa = hprev + (size_t)(m0 + srow) * H_ + kt * KTILE + shalf * 16;
        } else {        // x part: row (b*T + t)
            pa = g_xc + ((size_t)(m0 + srow) * T_ + tstep) * XK_
               + (kt - 4) * KTILE + shalf * 16;
        }
        const __nv_bfloat16* pb = g_wcat + (size_t)(n0 + srow) * WK_
                                + (size_t)kt * KTILE + shalf * 16;
        cp16(d,             pa); cp16(d + 16,         pa + 8);
        cp16(d + TILEB,     pb); cp16(d + TILEB + 16, pb + 8);
    };

#pragma unroll
    for (int p = 0; p < NSTAGE - 1; p++) {
        issue_stage(kt0 + p, p);
        CP_COMMIT();
    }

    for (int ki = 0; ki < KTe; ki++) {
        cp_wait_rem(KTe - 1 - ki);      // ensure stage ki landed
        __syncthreads();

        // overlap: issue next stage first (writes buffer (ki-1)&3 — safe post-sync)
        if (ki + NSTAGE - 1 < KTe) {
            issue_stage(kt0 + ki + NSTAGE - 1, (ki + NSTAGE - 1) & (NSTAGE - 1));
            CP_COMMIT();
        }

        const uint32_t sb = (uint32_t)((ki & (NSTAGE - 1)) * STAGE_B);
#pragma unroll
        for (int s = 0; s < KTILE / 16; s++) {
            uint32_t aH[2][4];
#pragma unroll
            for (int mt = 0; mt < 2; mt++) {
                uint32_t ad = a_frag0 + sb + 2u * (uint32_t)(mt * 16 * SMK + s * 16);
                ldsm4(ad, aH[mt][0], aH[mt][1], aH[mt][2], aH[mt][3]);
            }
#pragma unroll
            for (int p = 0; p < 4; p++) {
                uint32_t bd = b_frag0 + sb + 2u * (uint32_t)(p * 16 * SMK + s * 16);
                uint32_t h0, h1, h2, h3;
                ldsm4(bd, h0, h1, h2, h3);
                uint32_t b0H[2] = {h0, h2}, b1H[2] = {h1, h3};
#pragma unroll
                for (int mt = 0; mt < 2; mt++) {
                    mma_bf16(acc[mt][2 * p],     aH[mt], b0H);
                    mma_bf16(acc[mt][2 * p + 1], aH[mt], b1H);
                }
            }
        }
        // no trailing barrier: buffer reuse is guarded by next iteration's sync
    }
    __syncthreads();   // protect smem reuse by the epilogue below

    // ---- fused LSTM pointwise epilogue (quad-permuted gate layout) ----
    float* csm = (float*)smb;                                   // [128][36]
    __nv_bfloat16* hsm = (__nv_bfloat16*)((char*)smb + 128 * CSTRIDE * 4);
    const int jbase = n0 >> 2;
    const bool evenL = (lane & 1) == 0;

    // stage c tile (zeros at t=0)
    {
        int row = tid >> 1, half = tid & 1;
        float4* d = (float4*)&csm[row * CSTRIDE + half * 16];
        if (tstep == 0) {
            float4 z = make_float4(0.f, 0.f, 0.f, 0.f);
            d[0] = z; d[1] = z; d[2] = z; d[3] = z;
        } else {
            const float4* s = (const float4*)&g_c[(size_t)(m0 + row) * H_ + jbase + half * 16];
            d[0] = s[0]; d[1] = s[1]; d[2] = s[2]; d[3] = s[3];
        }
    }
    __syncthreads();

    float bv0[8], bv1[8];
#pragma unroll
    for (int nt = 0; nt < 8; nt++) {
        int col = n0 + wn * 64 + nt * 8 + tig * 2;
        bv0[nt] = g_bias[col];
        bv1[nt] = g_bias[col + 1];
    }

#pragma unroll
    for (int mt = 0; mt < 2; mt++)
#pragma unroll
        for (int nt = 0; nt < 8; nt++) {
            int rl0 = wm * 32 + mt * 16 + g;
            float v0 = acc[mt][nt][0] + bv0[nt];
            float v1 = acc[mt][nt][1] + bv1[nt];
            float v2 = acc[mt][nt][2] + bv0[nt];
            float v3 = acc[mt][nt][3] + bv1[nt];
            float s0 = __shfl_xor_sync(0xffffffffu, v0, 1);
            float s1 = __shfl_xor_sync(0xffffffffu, v1, 1);
            float s2 = __shfl_xor_sync(0xffffffffu, v2, 1);
            float s3 = __shfl_xor_sync(0xffffffffu, v3, 1);
            float gi, gf, gg, go; int rl;
            if (evenL) { gi = v0; gf = v1; gg = s0; go = s1; rl = rl0; }
            else       { gi = s2; gf = s3; gg = v2; go = v3; rl = rl0 + 8; }
            int jl = wn * 16 + nt * 2 + (tig >> 1);
            float c0 = csm[rl * CSTRIDE + jl];
            float cn = fsigm(gf) * c0 + fsigm(gi) * ftanh(gg);
            csm[rl * CSTRIDE + jl] = cn;
            float h = fsigm(go) * ftanh(cn);
            hsm[rl * HSTRIDE + jl] = __float2bfloat16_rn(h);
        }
    __syncthreads();

    // write back c and h (coalesced)
    {
        int row = tid >> 1, half = tid & 1;
        float4* s = (float4*)&csm[row * CSTRIDE + half * 16];
        float4* d = (float4*)&g_c[(size_t)(m0 + row) * H_ + jbase + half * 16];
        d[0] = s[0]; d[1] = s[1]; d[2] = s[2]; d[3] = s[3];
        if (half == 0) {
            uint4* hs4 = (uint4*)&hsm[row * HSTRIDE];
            uint4* hd  = (uint4*)&g_hs[(size_t)tstep * (B_ * H_)
                                       + (size_t)(m0 + row) * H_ + jbase];
            hd[0] = hs4[0]; hd[1] = hs4[1]; hd[2] = hs4[2]; hd[3] = hs4[3];
        }
    }
}

// ================= legacy-mma pipelined GEMM (L1/L2) ===========================
// SEL: 1 = L1 (hs-slab @ w1 -> g_a1 bf16, bias+relu)
//      2 = L2 (a1 @ w2 -> g_a2 fp32, bias+relu)
template<int SEL>
__global__ __launch_bounds__(256, 2)
void gemm_pipe(int lda, int ldb, int KT, int Nreal, int ldc,
               const float* __restrict__ bias1)
{
    const __nv_bfloat16* A = (SEL == 2) ? g_a1 : g_hs;
    const __nv_bfloat16* Bm = (SEL == 1) ? g_w1 : g_w2;

    extern __shared__ __align__(16) __nv_bfloat16 smb[];
    const uint32_t smem_u = (uint32_t)__cvta_generic_to_shared(smb);

    const int tid  = threadIdx.x;
    const int n0   = blockIdx.x * 128;
    const int m0   = blockIdx.y * 128;
    const int lane = tid & 31;
    const int warp = tid >> 5;
    const int wm   = warp & 3;
    const int wn   = warp >> 2;
    const int g    = lane >> 2;
    const int tig  = lane & 3;

    float acc[2][8][4];
#pragma unroll
    for (int mt = 0; mt < 2; mt++)
#pragma unroll
        for (int nt = 0; nt < 8; nt++)
#pragma unroll
            for (int i = 0; i < 4; i++) acc[mt][nt][i] = 0.f;

    const int srow = tid >> 1;
    const int shalf = tid & 1;
    const uint32_t dst_off = (uint32_t)(srow * (SMK * 2) + shalf * 32);

    const int fl_row = lane & 15;
    const int fl_k   = (lane >> 4) * 8;
    const uint32_t a_frag0 = smem_u + 2u * (uint32_t)((wm * 32 + fl_row) * SMK + fl_k);
    const uint32_t b_frag0 = smem_u + (uint32_t)TILEB
                           + 2u * (uint32_t)((wn * 64 + fl_row) * SMK + fl_k);

    auto a_off = [&](int kt) -> size_t {
        if (SEL == 1) {
            int t  = kt >> 2;
            int j0 = (kt & 3) * KTILE;
            return ((size_t)t * B_ + (m0 + srow)) * H_ + j0 + shalf * 16;
        }
        return (size_t)(m0 + srow) * lda + (size_t)kt * KTILE + shalf * 16;
    };

    auto issue_stage = [&](int kt, int st) {
        uint32_t d = smem_u + (uint32_t)(st * STAGE_B) + dst_off;
        const __nv_bfloat16* pa = A + a_off(kt);
        const __nv_bfloat16* pb = Bm + (size_t)(n0 + srow) * ldb
                                + (size_t)kt * KTILE + shalf * 16;
        cp16(d,             pa); cp16(d + 16,         pa + 8);
        cp16(d + TILEB,     pb); cp16(d + TILEB + 16, pb + 8);
    };

#pragma unroll
    for (int p = 0; p < NSTAGE - 1; p++) {
        issue_stage(p, p);
        CP_COMMIT();
    }

    for (int kt = 0; kt < KT; kt++) {
        cp_wait_rem(KT - 1 - kt);
        __syncthreads();

        if (kt + NSTAGE - 1 < KT) {
            issue_stage(kt + NSTAGE - 1, (kt + NSTAGE - 1) & (NSTAGE - 1));
            CP_COMMIT();
        }

        const uint32_t sb = (uint32_t)((kt & (NSTAGE - 1)) * STAGE_B);
#pragma unroll
        for (int s = 0; s < KTILE / 16; s++) {
            uint32_t aH[2][4];
#pragma unroll
            for (int mt = 0; mt < 2; mt++) {
                uint32_t ad = a_frag0 + sb + 2u * (uint32_t)(mt * 16 * SMK + s * 16);
                ldsm4(ad, aH[mt][0], aH[mt][1], aH[mt][2], aH[mt][3]);
            }
#pragma unroll
            for (int p = 0; p < 4; p++) {
                uint32_t bd = b_frag0 + sb + 2u * (uint32_t)(p * 16 * SMK + s * 16);
                uint32_t h0, h1, h2, h3;
                ldsm4(bd, h0, h1, h2, h3);
                uint32_t b0H[2] = {h0, h2}, b1H[2] = {h1, h3};
#pragma unroll
                for (int mt = 0; mt < 2; mt++) {
                    mma_bf16(acc[mt][2 * p],     aH[mt], b0H);
                    mma_bf16(acc[mt][2 * p + 1], aH[mt], b1H);
                }
            }
        }
    }

    float bv0[8], bv1[8];
#pragma unroll
    for (int nt = 0; nt < 8; nt++) {
        int col = n0 + wn * 64 + nt * 8 + tig * 2;
        bv0[nt] = (col < Nreal)     ? bias1[col]     : 0.f;
        bv1[nt] = (col + 1 < Nreal) ? bias1[col + 1] : 0.f;
    }
#pragma unroll
    for (int mt = 0; mt < 2; mt++) {
#pragma unroll
        for (int i = 0; i < 2; i++) {
            int row = m0 + wm * 32 + mt * 16 + g + i * 8;
#pragma unroll
            for (int nt = 0; nt < 8; nt++) {
                int col = n0 + wn * 64 + nt * 8 + tig * 2;
                if (col < ldc) {
                    float v0 = fmaxf(acc[mt][nt][i * 2]     + bv0[nt], 0.f);
                    float v1 = fmaxf(acc[mt][nt][i * 2 + 1] + bv1[nt], 0.f);
                    if (col >= Nreal)     v0 = 0.f;
                    if (col + 1 >= Nreal) v1 = 0.f;
                    if (SEL == 1) {
                        __nv_bfloat16 h0 = __float2bfloat16_rn(v0);
                        __nv_bfloat16 h1 = __float2bfloat16_rn(v1);
                        uint32_t hp = (uint32_t)*(uint16_t*)&h0
                                    | ((uint32_t)*(uint16_t*)&h1 << 16);
                        *(uint32_t*)&g_a1[(size_t)row * ldc + col] = hp;
                    } else {
                        *(float2*)&g_a2[(size_t)row * ldc + col] = make_float2(v0, v1);
                    }
                }
            }
        }
    }
}

// ---------------- K tail --------------------------------------------------------
__global__ __launch_bounds__(256)
void k_tail(const float* __restrict__ W3, const float* __restrict__ b3,
            const float* __restrict__ W4, const float* __restrict__ b4,
            float* __restrict__ out)
{
    __shared__ float a2s[32 * 256];
    __shared__ float a3[32 * 64];
    __shared__ float lg[64];

    const int tid = threadIdx.x;
    const int rb  = blockIdx.x * 32;
    const int warp = tid >> 5, lane = tid & 31;

    {
        const float4* src = (const float4*)(g_a2 + (size_t)rb * 256);
        float4* dst = (float4*)a2s;
        for (int i = tid; i < 32 * 256 / 4; i += 256) dst[i] = src[i];
    }
    __syncthreads();

    for (int task = warp; task < 64 * 4; task += 8) {
        int o  = task >> 2;
        int r0 = (task & 3) * 8;
        const float4* wrow = (const float4*)(W3 + o * 256);
        float acc[8];
#pragma unroll
        for (int i = 0; i < 8; i++) acc[i] = 0.f;
#pragma unroll
        for (int kb = 0; kb < 2; kb++) {
            float4 w = wrow[kb * 32 + lane];
#pragma unroll
            for (int ri = 0; ri < 8; ri++) {
                float4 xv = *(const float4*)&a2s[(r0 + ri) * 256 + kb * 128 + lane * 4];
                acc[ri] = fmaf(w.x, xv.x, fmaf(w.y, xv.y, fmaf(w.z, xv.z, fmaf(w.w, xv.w, acc[ri]))));
            }
        }
#pragma unroll
        for (int off = 16; off; off >>= 1)
#pragma unroll
            for (int ri = 0; ri < 8; ri++)
                acc[ri] += __shfl_xor_sync(0xffffffffu, acc[ri], off);
        if (lane < 8) a3[(r0 + lane) * 64 + o] = fmaxf(acc[lane] + b3[o], 0.f);
    }
    __syncthreads();

    if (tid < 64) {
        int r = tid >> 1, o = tid & 1;
        float s = b4[o];
        const float* xr = &a3[r * 64];
        const float* wr = &W4[o * 64];
#pragma unroll
        for (int k = 0; k < 64; k++) s = fmaf(xr[k], wr[k], s);
        lg[r * 2 + o] = s;
    }
    __syncthreads();

    if (tid < 32) {
        float z0 = lg[tid * 2], z1 = lg[tid * 2 + 1];
        float m = fmaxf(z0, z1);
        float e0 = expf(z0 - m), e1 = expf(z1 - m);
        float inv = 1.f / (e0 + e1);
        out[(rb + tid) * 2]     = e0 * inv;
        out[(rb + tid) * 2 + 1] = e1 * inv;
    }
}

// ---------------- launcher ----------------------------------------------------
extern "C" void kernel_launch(void* const* d_in, const int* in_sizes, int n_in,
                              void* d_out, int out_size)
{
    const float* x1   = (const float*)d_in[0];
    const float* x2   = (const float*)d_in[1];
    const float* W_ih = (const float*)d_in[2];
    const float* W_hh = (const float*)d_in[3];
    const float* b_ih = (const float*)d_in[4];
    const float* b_hh = (const float*)d_in[5];
    const float* W1   = (const float*)d_in[6];
    const float* b1   = (const float*)d_in[7];
    const float* W2   = (const float*)d_in[8];
    const float* b2   = (const float*)d_in[9];
    const float* W3   = (const float*)d_in[10];
    const float* b3   = (const float*)d_in[11];
    const float* W4   = (const float*)d_in[12];
    const float* b4   = (const float*)d_in[13];
    float* out = (float*)d_out;

    const int gemm_smem = NSTAGE * STAGE_B;   // 81920 B

    cudaFuncSetAttribute(k_step, cudaFuncAttributeMaxDynamicSharedMemorySize, gemm_smem);
    cudaFuncSetAttribute(gemm_pipe<1>,
                         cudaFuncAttributeMaxDynamicSharedMemorySize, gemm_smem);
    cudaFuncSetAttribute(gemm_pipe<2>,
                         cudaFuncAttributeMaxDynamicSharedMemorySize, gemm_smem);

    // prep
    k_prep_x<<<(M_ * XK_ + 255) / 256, 256>>>(x1, x2);
    {
        int total = NW_WCAT + NW_W1 + NW_W2 + G4_;
        k_prep_w<<<(total + 255) / 256, 256>>>(W_ih, W1, W2, W_hh, b_ih, b_hh);
    }

    // fused recurrence: 5 steps of [h|x] @ wcat^T + LSTM pointwise
    for (int t = 0; t < T_; t++) {
        dim3 grid(G4_ / 128, B_ / 128);
        k_step<<<grid, 256, gemm_smem>>>(t);
    }

    // L1: g_a1 = relu(hs-slab @ w1^T + b1)   [16384 x 531->544], K=640
    {
        dim3 grid(5, B_ / 128);
        gemm_pipe<1><<<grid, 256, gemm_smem>>>(0, 640, 640 / KTILE, 531, 544, b1);
    }

    // L2: g_a2 = relu(a1 @ w2^T + b2)   [16384 x 256], K=544
    {
        dim3 grid(2, B_ / 128);
        gemm_pipe<2><<<grid, 256, gemm_smem>>>(544, 544, 544 / KTILE, 256, 256, b2);
    }

    // tail
    k_tail<<<B_ / 32, 256>>>(W3, b3, W4, b4, out);
}

// round 15
// speedup vs baseline: 2.8006x; 1.0361x over previous
#include <cuda_runtime.h>
#include <cuda_bf16.h>
#include <math.h>
#include <stdint.h>

#define B_     16384
#define T_     5
#define F1_    300
#define F2_    251
#define IN_    551
#define H_     128
#define G4_    512
#define M_     (B_ * T_)          // 81920
#define XK_    576                // concat K padded to 32-multiple
#define WK_    704                // H_ + XK_  (combined recurrence K)
#define WKT    (WK_ / 32)         // 22 k-tiles

// Gate columns PERMUTED quad-interleaved: col 4j+q = original q*128+j.

// ---------------- scratch (device globals; device-code access ONLY) ----------
__device__ float g_c[B_ * H_];                   // [16384][128] fp32 cell state
__device__ float g_a2[B_ * 256];                 // [16384][256] fp32
__device__ float g_bias[G4_];                    // permuted b_ih+b_hh

__device__ __nv_bfloat16 g_xc[M_ * XK_];         // concat(x1,x2) bf16 [81920][576]
__device__ __nv_bfloat16 g_wcat[G4_ * WK_];      // [Whh | Wih] permuted rows [512][704]
__device__ __nv_bfloat16 g_w1[640 * 640];        // W1 padded
__device__ __nv_bfloat16 g_w2[256 * 544];        // W2 padded
__device__ __nv_bfloat16 g_hs[T_ * B_ * H_];     // h slabs [5][16384][128]
__device__ __nv_bfloat16 g_a1[B_ * 544];         // MLP L1 out [16384][544]

// ---------------- fast gate functions ----------------------------------------
__device__ __forceinline__ float ftanh(float x) {
    float y; asm("tanh.approx.f32 %0, %1;" : "=f"(y) : "f"(x)); return y;
}
__device__ __forceinline__ float fsigm(float x) {
    return fmaf(0.5f, ftanh(0.5f * x), 0.5f);
}

// ---------------- prep: concat x ----------------------------------------------
__global__ void k_prep_x(const float* __restrict__ x1, const float* __restrict__ x2)
{
    int idx = blockIdx.x * blockDim.x + threadIdx.x;
    if (idx >= M_ * XK_) return;
    int m = idx / XK_, k = idx % XK_;
    float v = 0.f;
    if (k < F1_)      v = x1[m * F1_ + k];
    else if (k < IN_) v = x2[m * F2_ + (k - F1_)];
    g_xc[idx] = __float2bfloat16_rn(v);
}

// ---------------- prep: weights (gate permuted, Whh|Wih merged) ----------------
#define NW_WCAT (G4_ * WK_)
#define NW_W1   (640 * 640)
#define NW_W2   (256 * 544)
__global__ void k_prep_w(const float* __restrict__ Wih, const float* __restrict__ W1,
                         const float* __restrict__ W2,  const float* __restrict__ Whh,
                         const float* __restrict__ bih, const float* __restrict__ bhh)
{
    int idx = blockIdx.x * blockDim.x + threadIdx.x;
    if (idx < NW_WCAT) {
        int n = idx / WK_, k = idx % WK_;
        int on = (n & 3) * 128 + (n >> 2);
        float v;
        if (k < H_)            v = Whh[on * H_ + k];
        else if (k - H_ < IN_) v = Wih[on * IN_ + (k - H_)];
        else                   v = 0.f;
        g_wcat[idx] = __float2bfloat16_rn(v);
        return;
    }
    idx -= NW_WCAT;
    if (idx < NW_W1) {
        int n = idx / 640, k = idx % 640;
        g_w1[idx] = __float2bfloat16_rn((n < 531) ? W1[n * 640 + k] : 0.f);
        return;
    }
    idx -= NW_W1;
    if (idx < NW_W2) {
        int n = idx / 544, k = idx % 544;
        g_w2[idx] = __float2bfloat16_rn((k < 531) ? W2[n * 531 + k] : 0.f);
        return;
    }
    idx -= NW_W2;
    if (idx < G4_) {
        int on = (idx & 3) * 128 + (idx >> 2);
        g_bias[idx] = bih[on] + bhh[on];
    }
}

// ---------------- shared low-level helpers -------------------------------------
__device__ __forceinline__ void cp16(uint32_t d, const void* s) {
    asm volatile("cp.async.cg.shared.global [%0], [%1], 16;" :: "r"(d), "l"(s));
}
#define CP_COMMIT() asm volatile("cp.async.commit_group;")

__device__ __forceinline__ void mma_bf16(float* c, const uint32_t* a, const uint32_t* b) {
    asm volatile(
        "mma.sync.aligned.m16n8k16.row.col.f32.bf16.bf16.f32 "
        "{%0,%1,%2,%3}, {%4,%5,%6,%7}, {%8,%9}, {%0,%1,%2,%3};"
        : "+f"(c[0]), "+f"(c[1]), "+f"(c[2]), "+f"(c[3])
        : "r"(a[0]), "r"(a[1]), "r"(a[2]), "r"(a[3]), "r"(b[0]), "r"(b[1]));
}

__device__ __forceinline__ void ldsm4(uint32_t addr, uint32_t& r0, uint32_t& r1,
                                      uint32_t& r2, uint32_t& r3) {
    asm volatile("ldmatrix.sync.aligned.m8n8.x4.shared.b16 {%0,%1,%2,%3}, [%4];"
                 : "=r"(r0), "=r"(r1), "=r"(r2), "=r"(r3) : "r"(addr));
}

__device__ __forceinline__ void cp_wait_rem(int rem) {
    if (rem >= 2)      asm volatile("cp.async.wait_group 2;");
    else if (rem == 1) asm volatile("cp.async.wait_group 1;");
    else               asm volatile("cp.async.wait_group 0;");
}

#define KTILE   32
#define SMK     40
#define TILEB   (128 * SMK * 2)         // 10240 B
#define STAGE_B (2 * TILEB)             // 20480 B
#define NSTAGE  4
#define CSTRIDE 36
#define HSTRIDE 40

// ================= fused recurrence step (B-panel resident) ====================
// 1 CTA/SM, 512 threads. Tile 256(m) x 128(n). Weight panel [128][704] resident
// in smem (stride 712 elems -> conflict-free ldmatrix). A staged 2-deep.
// Grid (4 n-blocks, 37); each CTA loops m-tiles (m_idx += 37, 64 total).
#define KS_ASTG   20480                 // 256 rows * 40 elems * 2B per A stage
#define KS_BOFF   (2 * KS_ASTG)         // 40960
#define KS_BROW   712                   // B panel row stride (elems)
#define KS_SMEM   (KS_BOFF + 128 * KS_BROW * 2)   // 40960 + 182272 = 223232

__global__ __launch_bounds__(512, 1)
void k_step(int tstep)
{
    extern __shared__ __align__(16) char smc[];
    const uint32_t smem_u = (uint32_t)__cvta_generic_to_shared(smc);

    const int tid  = threadIdx.x;
    const int n0   = blockIdx.x * 128;
    const int lane = tid & 31;
    const int warp = tid >> 5;          // 0..15
    const int wm   = warp & 7;          // m offset wm*32 (0..224)
    const int wn   = warp >> 3;         // n offset wn*64 (0..64)
    const int g    = lane >> 2;
    const int tig  = lane & 3;

    const __nv_bfloat16* hprev = g_hs + (size_t)(tstep - 1) * (B_ * H_);
    const int kt0 = (tstep == 0) ? 4 : 0;
    const int KTe = WKT - kt0;

    // A stage addressing: 256 rows, 64B/row, thread -> row tid>>1, half tid&1
    const int srow = tid >> 1;
    const int shalf = tid & 1;
    const uint32_t a_dst = (uint32_t)(srow * (SMK * 2) + shalf * 32);

    // B stage addressing: 128 rows x 4 chunks
    const int br = tid >> 2;            // 0..127
    const int bq = tid & 3;

    // fragment bases
    const int fl_row = lane & 15;
    const int fl_k   = (lane >> 4) * 8;
    const uint32_t a_frag0 = smem_u + 2u * (uint32_t)((wm * 32 + fl_row) * SMK + fl_k);
    const uint32_t b_frag0 = smem_u + (uint32_t)KS_BOFF
                           + 2u * (uint32_t)((wn * 64 + fl_row) * KS_BROW + fl_k);

    // bias (fixed per CTA)
    float bv0[8], bv1[8];
#pragma unroll
    for (int nt = 0; nt < 8; nt++) {
        int col = n0 + wn * 64 + nt * 8 + tig * 2;
        bv0[nt] = g_bias[col];
        bv1[nt] = g_bias[col + 1];
    }
    const int jbase = n0 >> 2;
    const bool evenL = (lane & 1) == 0;

    bool firstm = true;
    for (int m_idx = blockIdx.y; m_idx < 64; m_idx += 37) {
        const int m0 = m_idx * 256;

        float acc[2][8][4];
#pragma unroll
        for (int mt = 0; mt < 2; mt++)
#pragma unroll
            for (int nt = 0; nt < 8; nt++)
#pragma unroll
                for (int i = 0; i < 4; i++) acc[mt][nt][i] = 0.f;

        auto stageA = [&](int kt, int st) {
            uint32_t d = smem_u + (uint32_t)(st * KS_ASTG) + a_dst;
            const __nv_bfloat16* pa;
            if (kt < 4) {
                pa = hprev + (size_t)(m0 + srow) * H_ + kt * KTILE + shalf * 16;
            } else {
                pa = g_xc + ((size_t)(m0 + srow) * T_ + tstep) * XK_
                   + (kt - 4) * KTILE + shalf * 16;
            }
            cp16(d, pa); cp16(d + 16, pa + 8);
        };
        auto stageB = [&](int kt) {
            uint32_t d = smem_u + (uint32_t)KS_BOFF
                       + (uint32_t)(br * (KS_BROW * 2) + kt * 64 + bq * 16);
            const __nv_bfloat16* pb = g_wcat + (size_t)(n0 + br) * WK_
                                    + kt * KTILE + bq * 8;
            cp16(d, pb);
        };

        stageA(kt0, 0);
        if (firstm) stageB(kt0);
        CP_COMMIT();

        for (int ki = 0; ki < KTe; ki++) {
            asm volatile("cp.async.wait_group 0;");
            __syncthreads();
            if (ki + 1 < KTe) {
                stageA(kt0 + ki + 1, (ki + 1) & 1);
                if (firstm) stageB(kt0 + ki + 1);
                CP_COMMIT();
            }
            const int ktg = kt0 + ki;
            const uint32_t sb = (uint32_t)((ki & 1) * KS_ASTG);
#pragma unroll
            for (int s = 0; s < 2; s++) {
                uint32_t aH[2][4];
#pragma unroll
                for (int mt = 0; mt < 2; mt++) {
                    uint32_t ad = a_frag0 + sb + (uint32_t)(mt * 16 * SMK * 2 + s * 32);
                    ldsm4(ad, aH[mt][0], aH[mt][1], aH[mt][2], aH[mt][3]);
                }
#pragma unroll
                for (int p = 0; p < 4; p++) {
                    uint32_t bd = b_frag0 + (uint32_t)(ktg * 64 + p * 16 * KS_BROW * 2 + s * 32);
                    uint32_t h0, h1, h2, h3;
                    ldsm4(bd, h0, h1, h2, h3);
                    uint32_t b0H[2] = {h0, h2}, b1H[2] = {h1, h3};
#pragma unroll
                    for (int mt = 0; mt < 2; mt++) {
                        mma_bf16(acc[mt][2 * p],     aH[mt], b0H);
                        mma_bf16(acc[mt][2 * p + 1], aH[mt], b1H);
                    }
                }
            }
        }
        __syncthreads();   // A buffers become epilogue scratch below

        // ---- fused LSTM pointwise epilogue (c in smem, h via registers) ----
        float* csm = (float*)smc;                    // [256][36] fp32 (in A region)

        // stage c tile
        {
            int row = tid >> 1, half = tid & 1;
            float4* d = (float4*)&csm[row * CSTRIDE + half * 16];
            if (tstep == 0) {
                float4 z = make_float4(0.f, 0.f, 0.f, 0.f);
                d[0] = z; d[1] = z; d[2] = z; d[3] = z;
            } else {
                const float4* s = (const float4*)&g_c[(size_t)(m0 + row) * H_
                                                      + jbase + half * 16];
                d[0] = s[0]; d[1] = s[1]; d[2] = s[2]; d[3] = s[3];
            }
        }
        __syncthreads();

        unsigned short hr[16];
#pragma unroll
        for (int mt = 0; mt < 2; mt++)
#pragma unroll
            for (int nt = 0; nt < 8; nt++) {
                int rl0 = wm * 32 + mt * 16 + g;
                float v0 = acc[mt][nt][0] + bv0[nt];
                float v1 = acc[mt][nt][1] + bv1[nt];
                float v2 = acc[mt][nt][2] + bv0[nt];
                float v3 = acc[mt][nt][3] + bv1[nt];
                float s0 = __shfl_xor_sync(0xffffffffu, v0, 1);
                float s1 = __shfl_xor_sync(0xffffffffu, v1, 1);
                float s2 = __shfl_xor_sync(0xffffffffu, v2, 1);
                float s3 = __shfl_xor_sync(0xffffffffu, v3, 1);
                float gi, gf, gg, go; int rl;
                if (evenL) { gi = v0; gf = v1; gg = s0; go = s1; rl = rl0; }
                else       { gi = s2; gf = s3; gg = v2; go = v3; rl = rl0 + 8; }
                int jl = wn * 16 + nt * 2 + (tig >> 1);
                float c0 = csm[rl * CSTRIDE + jl];
                float cn = fsigm(gf) * c0 + fsigm(gi) * ftanh(gg);
                csm[rl * CSTRIDE + jl] = cn;
                float h = fsigm(go) * ftanh(cn);
                __nv_bfloat16 hb = __float2bfloat16_rn(h);
                hr[mt * 8 + nt] = *(unsigned short*)&hb;
            }
        __syncthreads();

        // writeback c
        {
            int row = tid >> 1, half = tid & 1;
            float4* s = (float4*)&csm[row * CSTRIDE + half * 16];
            float4* d = (float4*)&g_c[(size_t)(m0 + row) * H_ + jbase + half * 16];
            d[0] = s[0]; d[1] = s[1]; d[2] = s[2]; d[3] = s[3];
        }
        __syncthreads();

        // stage h into (reused) csm region as bf16 [256][40]
        {
            __nv_bfloat16* hsm = (__nv_bfloat16*)smc;
#pragma unroll
            for (int mt = 0; mt < 2; mt++)
#pragma unroll
                for (int nt = 0; nt < 8; nt++) {
                    int rl = wm * 32 + mt * 16 + g + (evenL ? 0 : 8);
                    int jl = wn * 16 + nt * 2 + (tig >> 1);
                    *(unsigned short*)&hsm[rl * HSTRIDE + jl] = hr[mt * 8 + nt];
                }
        }
        __syncthreads();

        // writeback h
        {
            __nv_bfloat16* hsm = (__nv_bfloat16*)smc;
            int row = tid >> 1, half = tid & 1;
            uint4* s = (uint4*)&hsm[row * HSTRIDE + half * 16];
            uint4* d = (uint4*)&g_hs[(size_t)tstep * (B_ * H_)
                                     + (size_t)(m0 + row) * H_ + jbase + half * 16];
            d[0] = s[0]; d[1] = s[1];
        }
        __syncthreads();   // before next m-tile's stageA reuses this region

        firstm = false;
    }
}

// ================= legacy-mma pipelined GEMM (L1/L2; validated) ================
template<int SEL>
__global__ __launch_bounds__(256, 2)
void gemm_pipe(int lda, int ldb, int KT, int Nreal, int ldc,
               const float* __restrict__ bias1)
{
    const __nv_bfloat16* A = (SEL == 2) ? g_a1 : g_hs;
    const __nv_bfloat16* Bm = (SEL == 1) ? g_w1 : g_w2;

    extern __shared__ __align__(16) __nv_bfloat16 smb[];
    const uint32_t smem_u = (uint32_t)__cvta_generic_to_shared(smb);

    const int tid  = threadIdx.x;
    const int n0   = blockIdx.x * 128;
    const int m0   = blockIdx.y * 128;
    const int lane = tid & 31;
    const int warp = tid >> 5;
    const int wm   = warp & 3;
    const int wn   = warp >> 2;
    const int g    = lane >> 2;
    const int tig  = lane & 3;

    float acc[2][8][4];
#pragma unroll
    for (int mt = 0; mt < 2; mt++)
#pragma unroll
        for (int nt = 0; nt < 8; nt++)
#pragma unroll
            for (int i = 0; i < 4; i++) acc[mt][nt][i] = 0.f;

    const int srow = tid >> 1;
    const int shalf = tid & 1;
    const uint32_t dst_off = (uint32_t)(srow * (SMK * 2) + shalf * 32);

    const int fl_row = lane & 15;
    const int fl_k   = (lane >> 4) * 8;
    const uint32_t a_frag0 = smem_u + 2u * (uint32_t)((wm * 32 + fl_row) * SMK + fl_k);
    const uint32_t b_frag0 = smem_u + (uint32_t)TILEB
                           + 2u * (uint32_t)((wn * 64 + fl_row) * SMK + fl_k);

    auto a_off = [&](int kt) -> size_t {
        if (SEL == 1) {
            int t  = kt >> 2;
            int j0 = (kt & 3) * KTILE;
            return ((size_t)t * B_ + (m0 + srow)) * H_ + j0 + shalf * 16;
        }
        return (size_t)(m0 + srow) * lda + (size_t)kt * KTILE + shalf * 16;
    };

    auto issue_stage = [&](int kt, int st) {
        uint32_t d = smem_u + (uint32_t)(st * STAGE_B) + dst_off;
        const __nv_bfloat16* pa = A + a_off(kt);
        const __nv_bfloat16* pb = Bm + (size_t)(n0 + srow) * ldb
                                + (size_t)kt * KTILE + shalf * 16;
        cp16(d,             pa); cp16(d + 16,         pa + 8);
        cp16(d + TILEB,     pb); cp16(d + TILEB + 16, pb + 8);
    };

#pragma unroll
    for (int p = 0; p < NSTAGE - 1; p++) {
        issue_stage(p, p);
        CP_COMMIT();
    }

    for (int kt = 0; kt < KT; kt++) {
        cp_wait_rem(KT - 1 - kt);
        __syncthreads();

        if (kt + NSTAGE - 1 < KT) {
            issue_stage(kt + NSTAGE - 1, (kt + NSTAGE - 1) & (NSTAGE - 1));
            CP_COMMIT();
        }

        const uint32_t sb = (uint32_t)((kt & (NSTAGE - 1)) * STAGE_B);
#pragma unroll
        for (int s = 0; s < KTILE / 16; s++) {
            uint32_t aH[2][4];
#pragma unroll
            for (int mt = 0; mt < 2; mt++) {
                uint32_t ad = a_frag0 + sb + 2u * (uint32_t)(mt * 16 * SMK + s * 16);
                ldsm4(ad, aH[mt][0], aH[mt][1], aH[mt][2], aH[mt][3]);
            }
#pragma unroll
            for (int p = 0; p < 4; p++) {
                uint32_t bd = b_frag0 + sb + 2u * (uint32_t)(p * 16 * SMK + s * 16);
                uint32_t h0, h1, h2, h3;
                ldsm4(bd, h0, h1, h2, h3);
                uint32_t b0H[2] = {h0, h2}, b1H[2] = {h1, h3};
#pragma unroll
                for (int mt = 0; mt < 2; mt++) {
                    mma_bf16(acc[mt][2 * p],     aH[mt], b0H);
                    mma_bf16(acc[mt][2 * p + 1], aH[mt], b1H);
                }
            }
        }
    }

    float bv0[8], bv1[8];
#pragma unroll
    for (int nt = 0; nt < 8; nt++) {
        int col = n0 + wn * 64 + nt * 8 + tig * 2;
        bv0[nt] = (col < Nreal)     ? bias1[col]     : 0.f;
        bv1[nt] = (col + 1 < Nreal) ? bias1[col + 1] : 0.f;
    }
#pragma unroll
    for (int mt = 0; mt < 2; mt++) {
#pragma unroll
        for (int i = 0; i < 2; i++) {
            int row = m0 + wm * 32 + mt * 16 + g + i * 8;
#pragma unroll
            for (int nt = 0; nt < 8; nt++) {
                int col = n0 + wn * 64 + nt * 8 + tig * 2;
                if (col < ldc) {
                    float v0 = fmaxf(acc[mt][nt][i * 2]     + bv0[nt], 0.f);
                    float v1 = fmaxf(acc[mt][nt][i * 2 + 1] + bv1[nt], 0.f);
                    if (col >= Nreal)     v0 = 0.f;
                    if (col + 1 >= Nreal) v1 = 0.f;
                    if (SEL == 1) {
                        __nv_bfloat16 h0 = __float2bfloat16_rn(v0);
                        __nv_bfloat16 h1 = __float2bfloat16_rn(v1);
                        uint32_t hp = (uint32_t)*(uint16_t*)&h0
                                    | ((uint32_t)*(uint16_t*)&h1 << 16);
                        *(uint32_t*)&g_a1[(size_t)row * ldc + col] = hp;
                    } else {
                        *(float2*)&g_a2[(size_t)row * ldc + col] = make_float2(v0, v1);
                    }
                }
            }
        }
    }
}

// ---------------- K tail --------------------------------------------------------
__global__ __launch_bounds__(256)
void k_tail(const float* __restrict__ W3, const float* __restrict__ b3,
            const float* __restrict__ W4, const float* __restrict__ b4,
            float* __restrict__ out)
{
    __shared__ float a2s[32 * 256];
    __shared__ float a3[32 * 64];
    __shared__ float lg[64];

    const int tid = threadIdx.x;
    const int rb  = blockIdx.x * 32;
    const int warp = tid >> 5, lane = tid & 31;

    {
        const float4* src = (const float4*)(g_a2 + (size_t)rb * 256);
        float4* dst = (float4*)a2s;
        for (int i = tid; i < 32 * 256 / 4; i += 256) dst[i] = src[i];
    }
    __syncthreads();

    for (int task = warp; task < 64 * 4; task += 8) {
        int o  = task >> 2;
        int r0 = (task & 3) * 8;
        const float4* wrow = (const float4*)(W3 + o * 256);
        float acc[8];
#pragma unroll
        for (int i = 0; i < 8; i++) acc[i] = 0.f;
#pragma unroll
        for (int kb = 0; kb < 2; kb++) {
            float4 w = wrow[kb * 32 + lane];
#pragma unroll
            for (int ri = 0; ri < 8; ri++) {
                float4 xv = *(const float4*)&a2s[(r0 + ri) * 256 + kb * 128 + lane * 4];
                acc[ri] = fmaf(w.x, xv.x, fmaf(w.y, xv.y, fmaf(w.z, xv.z, fmaf(w.w, xv.w, acc[ri]))));
            }
        }
#pragma unroll
        for (int off = 16; off; off >>= 1)
#pragma unroll
            for (int ri = 0; ri < 8; ri++)
                acc[ri] += __shfl_xor_sync(0xffffffffu, acc[ri], off);
        if (lane < 8) a3[(r0 + lane) * 64 + o] = fmaxf(acc[lane] + b3[o], 0.f);
    }
    __syncthreads();

    if (tid < 64) {
        int r = tid >> 1, o = tid & 1;
        float s = b4[o];
        const float* xr = &a3[r * 64];
        const float* wr = &W4[o * 64];
#pragma unroll
        for (int k = 0; k < 64; k++) s = fmaf(xr[k], wr[k], s);
        lg[r * 2 + o] = s;
    }
    __syncthreads();

    if (tid < 32) {
        float z0 = lg[tid * 2], z1 = lg[tid * 2 + 1];
        float m = fmaxf(z0, z1);
        float e0 = expf(z0 - m), e1 = expf(z1 - m);
        float inv = 1.f / (e0 + e1);
        out[(rb + tid) * 2]     = e0 * inv;
        out[(rb + tid) * 2 + 1] = e1 * inv;
    }
}

// ---------------- launcher ----------------------------------------------------
extern "C" void kernel_launch(void* const* d_in, const int* in_sizes, int n_in,
                              void* d_out, int out_size)
{
    const float* x1   = (const float*)d_in[0];
    const float* x2   = (const float*)d_in[1];
    const float* W_ih = (const float*)d_in[2];
    const float* W_hh = (const float*)d_in[3];
    const float* b_ih = (const float*)d_in[4];
    const float* b_hh = (const float*)d_in[5];
    const float* W1   = (const float*)d_in[6];
    const float* b1   = (const float*)d_in[7];
    const float* W2   = (const float*)d_in[8];
    const float* b2   = (const float*)d_in[9];
    const float* W3   = (const float*)d_in[10];
    const float* b3   = (const float*)d_in[11];
    const float* W4   = (const float*)d_in[12];
    const float* b4   = (const float*)d_in[13];
    float* out = (float*)d_out;

    const int gemm_smem = NSTAGE * STAGE_B;   // 81920 B

    cudaFuncSetAttribute(k_step, cudaFuncAttributeMaxDynamicSharedMemorySize, KS_SMEM);
    cudaFuncSetAttribute(gemm_pipe<1>,
                         cudaFuncAttributeMaxDynamicSharedMemorySize, gemm_smem);
    cudaFuncSetAttribute(gemm_pipe<2>,
                         cudaFuncAttributeMaxDynamicSharedMemorySize, gemm_smem);

    // prep
    k_prep_x<<<(M_ * XK_ + 255) / 256, 256>>>(x1, x2);
    {
        int total = NW_WCAT + NW_W1 + NW_W2 + G4_;
        k_prep_w<<<(total + 255) / 256, 256>>>(W_ih, W1, W2, W_hh, b_ih, b_hh);
    }

    // fused recurrence: 5 steps; B panel resident per CTA
    for (int t = 0; t < T_; t++) {
        dim3 grid(G4_ / 128, 37);
        k_step<<<grid, 512, KS_SMEM>>>(t);
    }

    // L1: g_a1 = relu(hs-slab @ w1^T + b1)   [16384 x 531->544], K=640
    {
        dim3 grid(5, B_ / 128);
        gemm_pipe<1><<<grid, 256, gemm_smem>>>(0, 640, 640 / KTILE, 531, 544, b1);
    }

    // L2: g_a2 = relu(a1 @ w2^T + b2)   [16384 x 256], K=544
    {
        dim3 grid(2, B_ / 128);
        gemm_pipe<2><<<grid, 256, gemm_smem>>>(544, 544, 544 / KTILE, 256, 256, b2);
    }

    // tail
    k_tail<<<B_ / 32, 256>>>(W3, b3, W4, b4, out);
}

// round 16
// speedup vs baseline: 3.2815x; 1.1717x over previous
#include <cuda_runtime.h>
#include <cuda_bf16.h>
#include <math.h>
#include <stdint.h>

#define B_     16384
#define T_     5
#define F1_    300
#define F2_    251
#define IN_    551
#define H_     128
#define G4_    512
#define M_     (B_ * T_)          // 81920
#define XK_    576                // concat K padded to 32-multiple
#define WK_    704                // H_ + XK_  (combined recurrence K)
#define WKT    (WK_ / 32)         // 22 k-tiles

// Gate columns PERMUTED quad-interleaved: col 4j+q = original q*128+j.

// ---------------- scratch (device globals; device-code access ONLY) ----------
__device__ float g_c[B_ * H_];                   // [16384][128] fp32 cell state
__device__ float g_a2[B_ * 256];                 // [16384][256] fp32
__device__ float g_bias[G4_];                    // permuted b_ih+b_hh

__device__ __nv_bfloat16 g_xc[M_ * XK_];         // concat(x1,x2) bf16 [81920][576]
__device__ __nv_bfloat16 g_wcat[G4_ * WK_];      // [Whh | Wih] permuted rows [512][704]
__device__ __nv_bfloat16 g_w1[640 * 640];        // W1 padded
__device__ __nv_bfloat16 g_w2[256 * 544];        // W2 padded
__device__ __nv_bfloat16 g_hs[T_ * B_ * H_];     // h slabs [5][16384][128]
__device__ __nv_bfloat16 g_a1[B_ * 544];         // MLP L1 out [16384][544]

// ---------------- fast gate functions ----------------------------------------
__device__ __forceinline__ float ftanh(float x) {
    float y; asm("tanh.approx.f32 %0, %1;" : "=f"(y) : "f"(x)); return y;
}
__device__ __forceinline__ float fsigm(float x) {
    return fmaf(0.5f, ftanh(0.5f * x), 0.5f);
}

__device__ __forceinline__ uint32_t pack2bf(float a, float b) {
    __nv_bfloat16 ha = __float2bfloat16_rn(a);
    __nv_bfloat16 hb = __float2bfloat16_rn(b);
    return (uint32_t)*(uint16_t*)&ha | ((uint32_t)*(uint16_t*)&hb << 16);
}

// ---------------- merged prep: x concat (vectorized) + weights -----------------
#define NPX_A (M_ * 75)           // x1 as float4 quads (300 = 75*4)
#define NPX_B (M_ * 63)           // x2 quads (covers cols 300..551, tail guarded)
#define NPX_C (M_ * 6)            // zero pad quads (cols 552..575)
#define NW_WCAT (G4_ * WK_)       // 360448
#define NW_W1   (640 * 640)       // 409600
#define NW_W2   (256 * 544)       // 139264
#define NPREP_TOTAL (NPX_A + NPX_B + NPX_C + NW_WCAT + NW_W1 + NW_W2 + G4_)

__global__ void k_prep(const float* __restrict__ x1, const float* __restrict__ x2,
                       const float* __restrict__ Wih, const float* __restrict__ W1,
                       const float* __restrict__ W2,  const float* __restrict__ Whh,
                       const float* __restrict__ bih, const float* __restrict__ bhh)
{
    int idx = blockIdx.x * blockDim.x + threadIdx.x;
    if (idx < NPX_A) {
        // x1: pure linear float4 read, packed bf16x4 write
        float4 v = ((const float4*)x1)[idx];
        int m = idx / 75, q = idx - m * 75;
        uint2 w; w.x = pack2bf(v.x, v.y); w.y = pack2bf(v.z, v.w);
        *(uint2*)&g_xc[(size_t)m * XK_ + q * 4] = w;
        return;
    }
    idx -= NPX_A;
    if (idx < NPX_B) {
        int m = idx / 63, q = idx - m * 63;
        int kk = q * 4;                       // 0..248 within x2
        const float* p = x2 + (size_t)m * F2_ + kk;
        float a0 = p[0];
        float a1 = p[1];
        float a2v = p[2];
        float a3 = (kk + 3 < F2_) ? p[3] : 0.f;
        uint2 w; w.x = pack2bf(a0, a1); w.y = pack2bf(a2v, a3);
        *(uint2*)&g_xc[(size_t)m * XK_ + F1_ + kk] = w;
        return;
    }
    idx -= NPX_B;
    if (idx < NPX_C) {
        int m = idx / 6, q = idx - m * 6;
        *(uint2*)&g_xc[(size_t)m * XK_ + 552 + q * 4] = make_uint2(0u, 0u);
        return;
    }
    idx -= NPX_C;
    if (idx < NW_WCAT) {
        int n = idx / WK_, k = idx % WK_;
        int on = (n & 3) * 128 + (n >> 2);    // permuted -> original gate row
        float v;
        if (k < H_)            v = Whh[on * H_ + k];
        else if (k - H_ < IN_) v = Wih[on * IN_ + (k - H_)];
        else                   v = 0.f;
        g_wcat[idx] = __float2bfloat16_rn(v);
        return;
    }
    idx -= NW_WCAT;
    if (idx < NW_W1) {
        int n = idx / 640, k = idx % 640;
        g_w1[idx] = __float2bfloat16_rn((n < 531) ? W1[n * 640 + k] : 0.f);
        return;
    }
    idx -= NW_W1;
    if (idx < NW_W2) {
        int n = idx / 544, k = idx % 544;
        g_w2[idx] = __float2bfloat16_rn((k < 531) ? W2[n * 531 + k] : 0.f);
        return;
    }
    idx -= NW_W2;
    if (idx < G4_) {
        int on = (idx & 3) * 128 + (idx >> 2);
        g_bias[idx] = bih[on] + bhh[on];
    }
}

// ---------------- shared low-level helpers -------------------------------------
__device__ __forceinline__ void cp16(uint32_t d, const void* s) {
    asm volatile("cp.async.cg.shared.global [%0], [%1], 16;" :: "r"(d), "l"(s));
}
#define CP_COMMIT() asm volatile("cp.async.commit_group;")

__device__ __forceinline__ void mma_bf16(float* c, const uint32_t* a, const uint32_t* b) {
    asm volatile(
        "mma.sync.aligned.m16n8k16.row.col.f32.bf16.bf16.f32 "
        "{%0,%1,%2,%3}, {%4,%5,%6,%7}, {%8,%9}, {%0,%1,%2,%3};"
        : "+f"(c[0]), "+f"(c[1]), "+f"(c[2]), "+f"(c[3])
        : "r"(a[0]), "r"(a[1]), "r"(a[2]), "r"(a[3]), "r"(b[0]), "r"(b[1]));
}

__device__ __forceinline__ void ldsm4(uint32_t addr, uint32_t& r0, uint32_t& r1,
                                      uint32_t& r2, uint32_t& r3) {
    asm volatile("ldmatrix.sync.aligned.m8n8.x4.shared.b16 {%0,%1,%2,%3}, [%4];"
                 : "=r"(r0), "=r"(r1), "=r"(r2), "=r"(r3) : "r"(addr));
}

__device__ __forceinline__ void cp_wait_rem(int rem) {
    if (rem >= 2)      asm volatile("cp.async.wait_group 2;");
    else if (rem == 1) asm volatile("cp.async.wait_group 1;");
    else               asm volatile("cp.async.wait_group 0;");
}

#define KTILE   32
#define SMK     40
#define TILEB   (128 * SMK * 2)         // 10240 B
#define STAGE_B (2 * TILEB)             // 20480 B
#define NSTAGE  4
#define CSTRIDE 36
#define HSTRIDE 40

// ================= fused recurrence step (B-panel resident) ====================
#define KS_ASTG   20480
#define KS_BOFF   (2 * KS_ASTG)
#define KS_BROW   712
#define KS_SMEM   (KS_BOFF + 128 * KS_BROW * 2)   // 223232

__global__ __launch_bounds__(512, 1)
void k_step(int tstep)
{
    extern __shared__ __align__(16) char smc[];
    const uint32_t smem_u = (uint32_t)__cvta_generic_to_shared(smc);

    const int tid  = threadIdx.x;
    const int n0   = blockIdx.x * 128;
    const int lane = tid & 31;
    const int warp = tid >> 5;
    const int wm   = warp & 7;
    const int wn   = warp >> 3;
    const int g    = lane >> 2;
    const int tig  = lane & 3;

    const __nv_bfloat16* hprev = g_hs + (size_t)(tstep - 1) * (B_ * H_);
    const int kt0 = (tstep == 0) ? 4 : 0;
    const int KTe = WKT - kt0;

    const int srow = tid >> 1;
    const int shalf = tid & 1;
    const uint32_t a_dst = (uint32_t)(srow * (SMK * 2) + shalf * 32);

    const int br = tid >> 2;
    const int bq = tid & 3;

    const int fl_row = lane & 15;
    const int fl_k   = (lane >> 4) * 8;
    const uint32_t a_frag0 = smem_u + 2u * (uint32_t)((wm * 32 + fl_row) * SMK + fl_k);
    const uint32_t b_frag0 = smem_u + (uint32_t)KS_BOFF
                           + 2u * (uint32_t)((wn * 64 + fl_row) * KS_BROW + fl_k);

    float bv0[8], bv1[8];
#pragma unroll
    for (int nt = 0; nt < 8; nt++) {
        int col = n0 + wn * 64 + nt * 8 + tig * 2;
        bv0[nt] = g_bias[col];
        bv1[nt] = g_bias[col + 1];
    }
    const int jbase = n0 >> 2;
    const bool evenL = (lane & 1) == 0;

    bool firstm = true;
    for (int m_idx = blockIdx.y; m_idx < 64; m_idx += 37) {
        const int m0 = m_idx * 256;

        float acc[2][8][4];
#pragma unroll
        for (int mt = 0; mt < 2; mt++)
#pragma unroll
            for (int nt = 0; nt < 8; nt++)
#pragma unroll
                for (int i = 0; i < 4; i++) acc[mt][nt][i] = 0.f;

        auto stageA = [&](int kt, int st) {
            uint32_t d = smem_u + (uint32_t)(st * KS_ASTG) + a_dst;
            const __nv_bfloat16* pa;
            if (kt < 4) {
                pa = hprev + (size_t)(m0 + srow) * H_ + kt * KTILE + shalf * 16;
            } else {
                pa = g_xc + ((size_t)(m0 + srow) * T_ + tstep) * XK_
                   + (kt - 4) * KTILE + shalf * 16;
            }
            cp16(d, pa); cp16(d + 16, pa + 8);
        };
        auto stageB = [&](int kt) {
            uint32_t d = smem_u + (uint32_t)KS_BOFF
                       + (uint32_t)(br * (KS_BROW * 2) + kt * 64 + bq * 16);
            const __nv_bfloat16* pb = g_wcat + (size_t)(n0 + br) * WK_
                                    + kt * KTILE + bq * 8;
            cp16(d, pb);
        };

        stageA(kt0, 0);
        if (firstm) stageB(kt0);
        CP_COMMIT();

        for (int ki = 0; ki < KTe; ki++) {
            asm volatile("cp.async.wait_group 0;");
            __syncthreads();
            if (ki + 1 < KTe) {
                stageA(kt0 + ki + 1, (ki + 1) & 1);
                if (firstm) stageB(kt0 + ki + 1);
                CP_COMMIT();
            }
            const int ktg = kt0 + ki;
            const uint32_t sb = (uint32_t)((ki & 1) * KS_ASTG);
#pragma unroll
            for (int s = 0; s < 2; s++) {
                uint32_t aH[2][4];
#pragma unroll
                for (int mt = 0; mt < 2; mt++) {
                    uint32_t ad = a_frag0 + sb + (uint32_t)(mt * 16 * SMK * 2 + s * 32);
                    ldsm4(ad, aH[mt][0], aH[mt][1], aH[mt][2], aH[mt][3]);
                }
#pragma unroll
                for (int p = 0; p < 4; p++) {
                    uint32_t bd = b_frag0 + (uint32_t)(ktg * 64 + p * 16 * KS_BROW * 2 + s * 32);
                    uint32_t h0, h1, h2, h3;
                    ldsm4(bd, h0, h1, h2, h3);
                    uint32_t b0H[2] = {h0, h2}, b1H[2] = {h1, h3};
#pragma unroll
                    for (int mt = 0; mt < 2; mt++) {
                        mma_bf16(acc[mt][2 * p],     aH[mt], b0H);
                        mma_bf16(acc[mt][2 * p + 1], aH[mt], b1H);
                    }
                }
            }
        }
        __syncthreads();

        // ---- fused LSTM pointwise epilogue ----
        float* csm = (float*)smc;                    // [256][36] fp32

        {
            int row = tid >> 1, half = tid & 1;
            float4* d = (float4*)&csm[row * CSTRIDE + half * 16];
            if (tstep == 0) {
                float4 z = make_float4(0.f, 0.f, 0.f, 0.f);
                d[0] = z; d[1] = z; d[2] = z; d[3] = z;
            } else {
                const float4* s = (const float4*)&g_c[(size_t)(m0 + row) * H_
                                                      + jbase + half * 16];
                d[0] = s[0]; d[1] = s[1]; d[2] = s[2]; d[3] = s[3];
            }
        }
        __syncthreads();

        unsigned short hr[16];
#pragma unroll
        for (int mt = 0; mt < 2; mt++)
#pragma unroll
            for (int nt = 0; nt < 8; nt++) {
                int rl0 = wm * 32 + mt * 16 + g;
                float v0 = acc[mt][nt][0] + bv0[nt];
                float v1 = acc[mt][nt][1] + bv1[nt];
                float v2 = acc[mt][nt][2] + bv0[nt];
                float v3 = acc[mt][nt][3] + bv1[nt];
                float s0 = __shfl_xor_sync(0xffffffffu, v0, 1);
                float s1 = __shfl_xor_sync(0xffffffffu, v1, 1);
                float s2 = __shfl_xor_sync(0xffffffffu, v2, 1);
                float s3 = __shfl_xor_sync(0xffffffffu, v3, 1);
                float gi, gf, gg, go; int rl;
                if (evenL) { gi = v0; gf = v1; gg = s0; go = s1; rl = rl0; }
                else       { gi = s2; gf = s3; gg = v2; go = v3; rl = rl0 + 8; }
                int jl = wn * 16 + nt * 2 + (tig >> 1);
                float c0 = csm[rl * CSTRIDE + jl];
                float cn = fsigm(gf) * c0 + fsigm(gi) * ftanh(gg);
                csm[rl * CSTRIDE + jl] = cn;
                float h = fsigm(go) * ftanh(cn);
                __nv_bfloat16 hb = __float2bfloat16_rn(h);
                hr[mt * 8 + nt] = *(unsigned short*)&hb;
            }
        __syncthreads();

        {
            int row = tid >> 1, half = tid & 1;
            float4* s = (float4*)&csm[row * CSTRIDE + half * 16];
            float4* d = (float4*)&g_c[(size_t)(m0 + row) * H_ + jbase + half * 16];
            d[0] = s[0]; d[1] = s[1]; d[2] = s[2]; d[3] = s[3];
        }
        __syncthreads();

        {
            __nv_bfloat16* hsm = (__nv_bfloat16*)smc;
#pragma unroll
            for (int mt = 0; mt < 2; mt++)
#pragma unroll
                for (int nt = 0; nt < 8; nt++) {
                    int rl = wm * 32 + mt * 16 + g + (evenL ? 0 : 8);
                    int jl = wn * 16 + nt * 2 + (tig >> 1);
                    *(unsigned short*)&hsm[rl * HSTRIDE + jl] = hr[mt * 8 + nt];
                }
        }
        __syncthreads();

        {
            __nv_bfloat16* hsm = (__nv_bfloat16*)smc;
            int row = tid >> 1, half = tid & 1;
            uint4* s = (uint4*)&hsm[row * HSTRIDE + half * 16];
            uint4* d = (uint4*)&g_hs[(size_t)tstep * (B_ * H_)
                                     + (size_t)(m0 + row) * H_ + jbase + half * 16];
            d[0] = s[0]; d[1] = s[1];
        }
        __syncthreads();

        firstm = false;
    }
}

// ================= legacy-mma pipelined GEMM (L1/L2; validated) ================
template<int SEL>
__global__ __launch_bounds__(256, 2)
void gemm_pipe(int lda, int ldb, int KT, int Nreal, int ldc,
               const float* __restrict__ bias1)
{
    const __nv_bfloat16* A = (SEL == 2) ? g_a1 : g_hs;
    const __nv_bfloat16* Bm = (SEL == 1) ? g_w1 : g_w2;

    extern __shared__ __align__(16) __nv_bfloat16 smb[];
    const uint32_t smem_u = (uint32_t)__cvta_generic_to_shared(smb);

    const int tid  = threadIdx.x;
    const int n0   = blockIdx.x * 128;
    const int m0   = blockIdx.y * 128;
    const int lane = tid & 31;
    const int warp = tid >> 5;
    const int wm   = warp & 3;
    const int wn   = warp >> 2;
    const int g    = lane >> 2;
    const int tig  = lane & 3;

    float acc[2][8][4];
#pragma unroll
    for (int mt = 0; mt < 2; mt++)
#pragma unroll
        for (int nt = 0; nt < 8; nt++)
#pragma unroll
            for (int i = 0; i < 4; i++) acc[mt][nt][i] = 0.f;

    const int srow = tid >> 1;
    const int shalf = tid & 1;
    const uint32_t dst_off = (uint32_t)(srow * (SMK * 2) + shalf * 32);

    const int fl_row = lane & 15;
    const int fl_k   = (lane >> 4) * 8;
    const uint32_t a_frag0 = smem_u + 2u * (uint32_t)((wm * 32 + fl_row) * SMK + fl_k);
    const uint32_t b_frag0 = smem_u + (uint32_t)TILEB
                           + 2u * (uint32_t)((wn * 64 + fl_row) * SMK + fl_k);

    auto a_off = [&](int kt) -> size_t {
        if (SEL == 1) {
            int t  = kt >> 2;
            int j0 = (kt & 3) * KTILE;
            return ((size_t)t * B_ + (m0 + srow)) * H_ + j0 + shalf * 16;
        }
        return (size_t)(m0 + srow) * lda + (size_t)kt * KTILE + shalf * 16;
    };

    auto issue_stage = [&](int kt, int st) {
        uint32_t d = smem_u + (uint32_t)(st * STAGE_B) + dst_off;
        const __nv_bfloat16* pa = A + a_off(kt);
        const __nv_bfloat16* pb = Bm + (size_t)(n0 + srow) * ldb
                                + (size_t)kt * KTILE + shalf * 16;
        cp16(d,             pa); cp16(d + 16,         pa + 8);
        cp16(d + TILEB,     pb); cp16(d + TILEB + 16, pb + 8);
    };

#pragma unroll
    for (int p = 0; p < NSTAGE - 1; p++) {
        issue_stage(p, p);
        CP_COMMIT();
    }

    for (int kt = 0; kt < KT; kt++) {
        cp_wait_rem(KT - 1 - kt);
        __syncthreads();

        if (kt + NSTAGE - 1 < KT) {
            issue_stage(kt + NSTAGE - 1, (kt + NSTAGE - 1) & (NSTAGE - 1));
            CP_COMMIT();
        }

        const uint32_t sb = (uint32_t)((kt & (NSTAGE - 1)) * STAGE_B);
#pragma unroll
        for (int s = 0; s < KTILE / 16; s++) {
            uint32_t aH[2][4];
#pragma unroll
            for (int mt = 0; mt < 2; mt++) {
                uint32_t ad = a_frag0 + sb + 2u * (uint32_t)(mt * 16 * SMK + s * 16);
                ldsm4(ad, aH[mt][0], aH[mt][1], aH[mt][2], aH[mt][3]);
            }
#pragma unroll
            for (int p = 0; p < 4; p++) {
                uint32_t bd = b_frag0 + sb + 2u * (uint32_t)(p * 16 * SMK + s * 16);
                uint32_t h0, h1, h2, h3;
                ldsm4(bd, h0, h1, h2, h3);
                uint32_t b0H[2] = {h0, h2}, b1H[2] = {h1, h3};
#pragma unroll
                for (int mt = 0; mt < 2; mt++) {
                    mma_bf16(acc[mt][2 * p],     aH[mt], b0H);
                    mma_bf16(acc[mt][2 * p + 1], aH[mt], b1H);
                }
            }
        }
    }

    float bv0[8], bv1[8];
#pragma unroll
    for (int nt = 0; nt < 8; nt++) {
        int col = n0 + wn * 64 + nt * 8 + tig * 2;
        bv0[nt] = (col < Nreal)     ? bias1[col]     : 0.f;
        bv1[nt] = (col + 1 < Nreal) ? bias1[col + 1] : 0.f;
    }
#pragma unroll
    for (int mt = 0; mt < 2; mt++) {
#pragma unroll
        for (int i = 0; i < 2; i++) {
            int row = m0 + wm * 32 + mt * 16 + g + i * 8;
#pragma unroll
            for (int nt = 0; nt < 8; nt++) {
                int col = n0 + wn * 64 + nt * 8 + tig * 2;
                if (col < ldc) {
                    float v0 = fmaxf(acc[mt][nt][i * 2]     + bv0[nt], 0.f);
                    float v1 = fmaxf(acc[mt][nt][i * 2 + 1] + bv1[nt], 0.f);
                    if (col >= Nreal)     v0 = 0.f;
                    if (col + 1 >= Nreal) v1 = 0.f;
                    if (SEL == 1) {
                        uint32_t hp = pack2bf(v0, v1);
                        *(uint32_t*)&g_a1[(size_t)row * ldc + col] = hp;
                    } else {
                        *(float2*)&g_a2[(size_t)row * ldc + col] = make_float2(v0, v1);
                    }
                }
            }
        }
    }
}

// ---------------- K tail --------------------------------------------------------
__global__ __launch_bounds__(256)
void k_tail(const float* __restrict__ W3, const float* __restrict__ b3,
            const float* __restrict__ W4, const float* __restrict__ b4,
            float* __restrict__ out)
{
    __shared__ float a2s[32 * 256];
    __shared__ float a3[32 * 64];
    __shared__ float lg[64];

    const int tid = threadIdx.x;
    const int rb  = blockIdx.x * 32;
    const int warp = tid >> 5, lane = tid & 31;

    {
        const float4* src = (const float4*)(g_a2 + (size_t)rb * 256);
        float4* dst = (float4*)a2s;
        for (int i = tid; i < 32 * 256 / 4; i += 256) dst[i] = src[i];
    }
    __syncthreads();

    for (int task = warp; task < 64 * 4; task += 8) {
        int o  = task >> 2;
        int r0 = (task & 3) * 8;
        const float4* wrow = (const float4*)(W3 + o * 256);
        float acc[8];
#pragma unroll
        for (int i = 0; i < 8; i++) acc[i] = 0.f;
#pragma unroll
        for (int kb = 0; kb < 2; kb++) {
            float4 w = wrow[kb * 32 + lane];
#pragma unroll
            for (int ri = 0; ri < 8; ri++) {
                float4 xv = *(const float4*)&a2s[(r0 + ri) * 256 + kb * 128 + lane * 4];
                acc[ri] = fmaf(w.x, xv.x, fmaf(w.y, xv.y, fmaf(w.z, xv.z, fmaf(w.w, xv.w, acc[ri]))));
            }
        }
#pragma unroll
        for (int off = 16; off; off >>= 1)
#pragma unroll
            for (int ri = 0; ri < 8; ri++)
                acc[ri] += __shfl_xor_sync(0xffffffffu, acc[ri], off);
        if (lane < 8) a3[(r0 + lane) * 64 + o] = fmaxf(acc[lane] + b3[o], 0.f);
    }
    __syncthreads();

    if (tid < 64) {
        int r = tid >> 1, o = tid & 1;
        float s = b4[o];
        const float* xr = &a3[r * 64];
        const float* wr = &W4[o * 64];
#pragma unroll
        for (int k = 0; k < 64; k++) s = fmaf(xr[k], wr[k], s);
        lg[r * 2 + o] = s;
    }
    __syncthreads();

    if (tid < 32) {
        float z0 = lg[tid * 2], z1 = lg[tid * 2 + 1];
        float m = fmaxf(z0, z1);
        float e0 = expf(z0 - m), e1 = expf(z1 - m);
        float inv = 1.f / (e0 + e1);
        out[(rb + tid) * 2]     = e0 * inv;
        out[(rb + tid) * 2 + 1] = e1 * inv;
    }
}

// ---------------- launcher ----------------------------------------------------
extern "C" void kernel_launch(void* const* d_in, const int* in_sizes, int n_in,
                              void* d_out, int out_size)
{
    const float* x1   = (const float*)d_in[0];
    const float* x2   = (const float*)d_in[1];
    const float* W_ih = (const float*)d_in[2];
    const float* W_hh = (const float*)d_in[3];
    const float* b_ih = (const float*)d_in[4];
    const float* b_hh = (const float*)d_in[5];
    const float* W1   = (const float*)d_in[6];
    const float* b1   = (const float*)d_in[7];
    const float* W2   = (const float*)d_in[8];
    const float* b2   = (const float*)d_in[9];
    const float* W3   = (const float*)d_in[10];
    const float* b3   = (const float*)d_in[11];
    const float* W4   = (const float*)d_in[12];
    const float* b4   = (const float*)d_in[13];
    float* out = (float*)d_out;

    const int gemm_smem = NSTAGE * STAGE_B;   // 81920 B

    cudaFuncSetAttribute(k_step, cudaFuncAttributeMaxDynamicSharedMemorySize, KS_SMEM);
    cudaFuncSetAttribute(gemm_pipe<1>,
                         cudaFuncAttributeMaxDynamicSharedMemorySize, gemm_smem);
    cudaFuncSetAttribute(gemm_pipe<2>,
                         cudaFuncAttributeMaxDynamicSharedMemorySize, gemm_smem);

    // merged prep (vectorized x concat + weights + bias)
    k_prep<<<(NPREP_TOTAL + 255) / 256, 256>>>(x1, x2, W_ih, W1, W2, W_hh, b_ih, b_hh);

    // fused recurrence: 5 steps; B panel resident per CTA
    for (int t = 0; t < T_; t++) {
        dim3 grid(G4_ / 128, 37);
        k_step<<<grid, 512, KS_SMEM>>>(t);
    }

    // L1: g_a1 = relu(hs-slab @ w1^T + b1)   [16384 x 531->544], K=640
    {
        dim3 grid(5, B_ / 128);
        gemm_pipe<1><<<grid, 256, gemm_smem>>>(0, 640, 640 / KTILE, 531, 544, b1);
    }

    // L2: g_a2 = relu(a1 @ w2^T + b2)   [16384 x 256], K=544
    {
        dim3 grid(2, B_ / 128);
        gemm_pipe<2><<<grid, 256, gemm_smem>>>(544, 544, 544 / KTILE, 256, 256, b2);
    }

    // tail
    k_tail<<<B_ / 32, 256>>>(W3, b3, W4, b4, out);
}

// round 17
// speedup vs baseline: 3.5671x; 1.0870x over previous
#include <cuda_runtime.h>
#include <cuda_bf16.h>
#include <math.h>
#include <stdint.h>

#define B_     16384
#define T_     5
#define F1_    300
#define F2_    251
#define IN_    551
#define H_     128
#define G4_    512
#define M_     (B_ * T_)          // 81920
#define XK_    576
#define WK_    704
#define WKT    (WK_ / 32)

// Gate columns PERMUTED quad-interleaved: col 4j+q = original q*128+j.

// ---------------- scratch (device globals; device-code access ONLY) ----------
__device__ float g_c[B_ * H_];                   // [16384][128] fp32 cell state
__device__ float g_bias[G4_];                    // permuted b_ih+b_hh

__device__ __nv_bfloat16 g_xc[M_ * XK_];         // concat(x1,x2) bf16 [81920][576]
__device__ __nv_bfloat16 g_wcat[G4_ * WK_];      // [Whh | Wih] permuted [512][704]
__device__ __nv_bfloat16 g_w1[640 * 640];        // W1 padded
__device__ __nv_bfloat16 g_w2[256 * 544];        // W2 padded
__device__ __nv_bfloat16 g_hs[T_ * B_ * H_];     // h slabs [5][16384][128]
__device__ __nv_bfloat16 g_a1[B_ * 544];         // MLP L1 out [16384][544]

// ---------------- fast gate functions ----------------------------------------
__device__ __forceinline__ float ftanh(float x) {
    float y; asm("tanh.approx.f32 %0, %1;" : "=f"(y) : "f"(x)); return y;
}
__device__ __forceinline__ float fsigm(float x) {
    return fmaf(0.5f, ftanh(0.5f * x), 0.5f);
}

__device__ __forceinline__ uint32_t pack2bf(float a, float b) {
    __nv_bfloat16 ha = __float2bfloat16_rn(a);
    __nv_bfloat16 hb = __float2bfloat16_rn(b);
    return (uint32_t)*(uint16_t*)&ha | ((uint32_t)*(uint16_t*)&hb << 16);
}

// ---------------- merged prep -------------------------------------------------
#define NPX_A (M_ * 75)
#define NPX_B (M_ * 63)
#define NPX_C (M_ * 6)
#define NW_WCAT (G4_ * WK_)
#define NW_W1   (640 * 640)
#define NW_W2   (256 * 544)
#define NPREP_TOTAL (NPX_A + NPX_B + NPX_C + NW_WCAT + NW_W1 + NW_W2 + G4_)

__global__ void k_prep(const float* __restrict__ x1, const float* __restrict__ x2,
                       const float* __restrict__ Wih, const float* __restrict__ W1,
                       const float* __restrict__ W2,  const float* __restrict__ Whh,
                       const float* __restrict__ bih, const float* __restrict__ bhh)
{
    int idx = blockIdx.x * blockDim.x + threadIdx.x;
    if (idx < NPX_A) {
        float4 v = ((const float4*)x1)[idx];
        int m = idx / 75, q = idx - m * 75;
        uint2 w; w.x = pack2bf(v.x, v.y); w.y = pack2bf(v.z, v.w);
        *(uint2*)&g_xc[(size_t)m * XK_ + q * 4] = w;
        return;
    }
    idx -= NPX_A;
    if (idx < NPX_B) {
        int m = idx / 63, q = idx - m * 63;
        int kk = q * 4;
        const float* p = x2 + (size_t)m * F2_ + kk;
        float a0 = p[0];
        float a1 = p[1];
        float a2v = p[2];
        float a3 = (kk + 3 < F2_) ? p[3] : 0.f;
        uint2 w; w.x = pack2bf(a0, a1); w.y = pack2bf(a2v, a3);
        *(uint2*)&g_xc[(size_t)m * XK_ + F1_ + kk] = w;
        return;
    }
    idx -= NPX_B;
    if (idx < NPX_C) {
        int m = idx / 6, q = idx - m * 6;
        *(uint2*)&g_xc[(size_t)m * XK_ + 552 + q * 4] = make_uint2(0u, 0u);
        return;
    }
    idx -= NPX_C;
    if (idx < NW_WCAT) {
        int n = idx / WK_, k = idx % WK_;
        int on = (n & 3) * 128 + (n >> 2);
        float v;
        if (k < H_)            v = Whh[on * H_ + k];
        else if (k - H_ < IN_) v = Wih[on * IN_ + (k - H_)];
        else                   v = 0.f;
        g_wcat[idx] = __float2bfloat16_rn(v);
        return;
    }
    idx -= NW_WCAT;
    if (idx < NW_W1) {
        int n = idx / 640, k = idx % 640;
        g_w1[idx] = __float2bfloat16_rn((n < 531) ? W1[n * 640 + k] : 0.f);
        return;
    }
    idx -= NW_W1;
    if (idx < NW_W2) {
        int n = idx / 544, k = idx % 544;
        g_w2[idx] = __float2bfloat16_rn((k < 531) ? W2[n * 531 + k] : 0.f);
        return;
    }
    idx -= NW_W2;
    if (idx < G4_) {
        int on = (idx & 3) * 128 + (idx >> 2);
        g_bias[idx] = bih[on] + bhh[on];
    }
}

// ---------------- shared low-level helpers -------------------------------------
__device__ __forceinline__ void cp16(uint32_t d, const void* s) {
    asm volatile("cp.async.cg.shared.global [%0], [%1], 16;" :: "r"(d), "l"(s));
}
#define CP_COMMIT() asm volatile("cp.async.commit_group;")

__device__ __forceinline__ void mma_bf16(float* c, const uint32_t* a, const uint32_t* b) {
    asm volatile(
        "mma.sync.aligned.m16n8k16.row.col.f32.bf16.bf16.f32 "
        "{%0,%1,%2,%3}, {%4,%5,%6,%7}, {%8,%9}, {%0,%1,%2,%3};"
        : "+f"(c[0]), "+f"(c[1]), "+f"(c[2]), "+f"(c[3])
        : "r"(a[0]), "r"(a[1]), "r"(a[2]), "r"(a[3]), "r"(b[0]), "r"(b[1]));
}

__device__ __forceinline__ void ldsm4(uint32_t addr, uint32_t& r0, uint32_t& r1,
                                      uint32_t& r2, uint32_t& r3) {
    asm volatile("ldmatrix.sync.aligned.m8n8.x4.shared.b16 {%0,%1,%2,%3}, [%4];"
                 : "=r"(r0), "=r"(r1), "=r"(r2), "=r"(r3) : "r"(addr));
}

__device__ __forceinline__ void cp_wait_rem(int rem) {
    if (rem >= 2)      asm volatile("cp.async.wait_group 2;");
    else if (rem == 1) asm volatile("cp.async.wait_group 1;");
    else               asm volatile("cp.async.wait_group 0;");
}

#define KTILE   32
#define SMK     40
#define TILEB   (128 * SMK * 2)
#define STAGE_B (2 * TILEB)
#define NSTAGE  4
#define CSTRIDE 36
#define HSTRIDE 40

// ================= fused recurrence step (B-panel resident) ====================
#define KS_ASTG   20480
#define KS_BOFF   (2 * KS_ASTG)
#define KS_BROW   712
#define KS_SMEM   (KS_BOFF + 128 * KS_BROW * 2)

__global__ __launch_bounds__(512, 1)
void k_step(int tstep)
{
    extern __shared__ __align__(16) char smc[];
    const uint32_t smem_u = (uint32_t)__cvta_generic_to_shared(smc);

    const int tid  = threadIdx.x;
    const int n0   = blockIdx.x * 128;
    const int lane = tid & 31;
    const int warp = tid >> 5;
    const int wm   = warp & 7;
    const int wn   = warp >> 3;
    const int g    = lane >> 2;
    const int tig  = lane & 3;

    const __nv_bfloat16* hprev = g_hs + (size_t)(tstep - 1) * (B_ * H_);
    const int kt0 = (tstep == 0) ? 4 : 0;
    const int KTe = WKT - kt0;

    const int srow = tid >> 1;
    const int shalf = tid & 1;
    const uint32_t a_dst = (uint32_t)(srow * (SMK * 2) + shalf * 32);

    const int br = tid >> 2;
    const int bq = tid & 3;

    const int fl_row = lane & 15;
    const int fl_k   = (lane >> 4) * 8;
    const uint32_t a_frag0 = smem_u + 2u * (uint32_t)((wm * 32 + fl_row) * SMK + fl_k);
    const uint32_t b_frag0 = smem_u + (uint32_t)KS_BOFF
                           + 2u * (uint32_t)((wn * 64 + fl_row) * KS_BROW + fl_k);

    float bv0[8], bv1[8];
#pragma unroll
    for (int nt = 0; nt < 8; nt++) {
        int col = n0 + wn * 64 + nt * 8 + tig * 2;
        bv0[nt] = g_bias[col];
        bv1[nt] = g_bias[col + 1];
    }
    const int jbase = n0 >> 2;
    const bool evenL = (lane & 1) == 0;

    bool firstm = true;
    for (int m_idx = blockIdx.y; m_idx < 64; m_idx += 37) {
        const int m0 = m_idx * 256;

        float acc[2][8][4];
#pragma unroll
        for (int mt = 0; mt < 2; mt++)
#pragma unroll
            for (int nt = 0; nt < 8; nt++)
#pragma unroll
                for (int i = 0; i < 4; i++) acc[mt][nt][i] = 0.f;

        auto stageA = [&](int kt, int st) {
            uint32_t d = smem_u + (uint32_t)(st * KS_ASTG) + a_dst;
            const __nv_bfloat16* pa;
            if (kt < 4) {
                pa = hprev + (size_t)(m0 + srow) * H_ + kt * KTILE + shalf * 16;
            } else {
                pa = g_xc + ((size_t)(m0 + srow) * T_ + tstep) * XK_
                   + (kt - 4) * KTILE + shalf * 16;
            }
            cp16(d, pa); cp16(d + 16, pa + 8);
        };
        auto stageB = [&](int kt) {
            uint32_t d = smem_u + (uint32_t)KS_BOFF
                       + (uint32_t)(br * (KS_BROW * 2) + kt * 64 + bq * 16);
            const __nv_bfloat16* pb = g_wcat + (size_t)(n0 + br) * WK_
                                    + kt * KTILE + bq * 8;
            cp16(d, pb);
        };

        stageA(kt0, 0);
        if (firstm) stageB(kt0);
        CP_COMMIT();

        for (int ki = 0; ki < KTe; ki++) {
            asm volatile("cp.async.wait_group 0;");
            __syncthreads();
            if (ki + 1 < KTe) {
                stageA(kt0 + ki + 1, (ki + 1) & 1);
                if (firstm) stageB(kt0 + ki + 1);
                CP_COMMIT();
            }
            const int ktg = kt0 + ki;
            const uint32_t sb = (uint32_t)((ki & 1) * KS_ASTG);
#pragma unroll
            for (int s = 0; s < 2; s++) {
                uint32_t aH[2][4];
#pragma unroll
                for (int mt = 0; mt < 2; mt++) {
                    uint32_t ad = a_frag0 + sb + (uint32_t)(mt * 16 * SMK * 2 + s * 32);
                    ldsm4(ad, aH[mt][0], aH[mt][1], aH[mt][2], aH[mt][3]);
                }
#pragma unroll
                for (int p = 0; p < 4; p++) {
                    uint32_t bd = b_frag0 + (uint32_t)(ktg * 64 + p * 16 * KS_BROW * 2 + s * 32);
                    uint32_t h0, h1, h2, h3;
                    ldsm4(bd, h0, h1, h2, h3);
                    uint32_t b0H[2] = {h0, h2}, b1H[2] = {h1, h3};
#pragma unroll
                    for (int mt = 0; mt < 2; mt++) {
                        mma_bf16(acc[mt][2 * p],     aH[mt], b0H);
                        mma_bf16(acc[mt][2 * p + 1], aH[mt], b1H);
                    }
                }
            }
        }
        __syncthreads();

        // ---- fused LSTM pointwise epilogue ----
        float* csm = (float*)smc;

        {
            int row = tid >> 1, half = tid & 1;
            float4* d = (float4*)&csm[row * CSTRIDE + half * 16];
            if (tstep == 0) {
                float4 z = make_float4(0.f, 0.f, 0.f, 0.f);
                d[0] = z; d[1] = z; d[2] = z; d[3] = z;
            } else {
                const float4* s = (const float4*)&g_c[(size_t)(m0 + row) * H_
                                                      + jbase + half * 16];
                d[0] = s[0]; d[1] = s[1]; d[2] = s[2]; d[3] = s[3];
            }
        }
        __syncthreads();

        unsigned short hr[16];
#pragma unroll
        for (int mt = 0; mt < 2; mt++)
#pragma unroll
            for (int nt = 0; nt < 8; nt++) {
                int rl0 = wm * 32 + mt * 16 + g;
                float v0 = acc[mt][nt][0] + bv0[nt];
                float v1 = acc[mt][nt][1] + bv1[nt];
                float v2 = acc[mt][nt][2] + bv0[nt];
                float v3 = acc[mt][nt][3] + bv1[nt];
                float s0 = __shfl_xor_sync(0xffffffffu, v0, 1);
                float s1 = __shfl_xor_sync(0xffffffffu, v1, 1);
                float s2 = __shfl_xor_sync(0xffffffffu, v2, 1);
                float s3 = __shfl_xor_sync(0xffffffffu, v3, 1);
                float gi, gf, gg, go; int rl;
                if (evenL) { gi = v0; gf = v1; gg = s0; go = s1; rl = rl0; }
                else       { gi = s2; gf = s3; gg = v2; go = v3; rl = rl0 + 8; }
                int jl = wn * 16 + nt * 2 + (tig >> 1);
                float c0 = csm[rl * CSTRIDE + jl];
                float cn = fsigm(gf) * c0 + fsigm(gi) * ftanh(gg);
                csm[rl * CSTRIDE + jl] = cn;
                float h = fsigm(go) * ftanh(cn);
                __nv_bfloat16 hb = __float2bfloat16_rn(h);
                hr[mt * 8 + nt] = *(unsigned short*)&hb;
            }
        __syncthreads();

        {
            int row = tid >> 1, half = tid & 1;
            float4* s = (float4*)&csm[row * CSTRIDE + half * 16];
            float4* d = (float4*)&g_c[(size_t)(m0 + row) * H_ + jbase + half * 16];
            d[0] = s[0]; d[1] = s[1]; d[2] = s[2]; d[3] = s[3];
        }
        __syncthreads();

        {
            __nv_bfloat16* hsm = (__nv_bfloat16*)smc;
#pragma unroll
            for (int mt = 0; mt < 2; mt++)
#pragma unroll
                for (int nt = 0; nt < 8; nt++) {
                    int rl = wm * 32 + mt * 16 + g + (evenL ? 0 : 8);
                    int jl = wn * 16 + nt * 2 + (tig >> 1);
                    *(unsigned short*)&hsm[rl * HSTRIDE + jl] = hr[mt * 8 + nt];
                }
        }
        __syncthreads();

        {
            __nv_bfloat16* hsm = (__nv_bfloat16*)smc;
            int row = tid >> 1, half = tid & 1;
            uint4* s = (uint4*)&hsm[row * HSTRIDE + half * 16];
            uint4* d = (uint4*)&g_hs[(size_t)tstep * (B_ * H_)
                                     + (size_t)(m0 + row) * H_ + jbase + half * 16];
            d[0] = s[0]; d[1] = s[1];
        }
        __syncthreads();

        firstm = false;
    }
}

// ================= L1: gemm_pipe (validated) ===================================
__global__ __launch_bounds__(256, 2)
void gemm_l1(int KT, int Nreal, int ldc, const float* __restrict__ bias1)
{
    const __nv_bfloat16* Bm = g_w1;

    extern __shared__ __align__(16) __nv_bfloat16 smb[];
    const uint32_t smem_u = (uint32_t)__cvta_generic_to_shared(smb);

    const int tid  = threadIdx.x;
    const int n0   = blockIdx.x * 128;
    const int m0   = blockIdx.y * 128;
    const int lane = tid & 31;
    const int warp = tid >> 5;
    const int wm   = warp & 3;
    const int wn   = warp >> 2;
    const int g    = lane >> 2;
    const int tig  = lane & 3;

    float acc[2][8][4];
#pragma unroll
    for (int mt = 0; mt < 2; mt++)
#pragma unroll
        for (int nt = 0; nt < 8; nt++)
#pragma unroll
            for (int i = 0; i < 4; i++) acc[mt][nt][i] = 0.f;

    const int srow = tid >> 1;
    const int shalf = tid & 1;
    const uint32_t dst_off = (uint32_t)(srow * (SMK * 2) + shalf * 32);

    const int fl_row = lane & 15;
    const int fl_k   = (lane >> 4) * 8;
    const uint32_t a_frag0 = smem_u + 2u * (uint32_t)((wm * 32 + fl_row) * SMK + fl_k);
    const uint32_t b_frag0 = smem_u + (uint32_t)TILEB
                           + 2u * (uint32_t)((wn * 64 + fl_row) * SMK + fl_k);

    auto issue_stage = [&](int kt, int st) {
        uint32_t d = smem_u + (uint32_t)(st * STAGE_B) + dst_off;
        int t  = kt >> 2;
        int j0 = (kt & 3) * KTILE;
        const __nv_bfloat16* pa = g_hs + ((size_t)t * B_ + (m0 + srow)) * H_
                                + j0 + shalf * 16;
        const __nv_bfloat16* pb = Bm + (size_t)(n0 + srow) * 640
                                + (size_t)kt * KTILE + shalf * 16;
        cp16(d,             pa); cp16(d + 16,         pa + 8);
        cp16(d + TILEB,     pb); cp16(d + TILEB + 16, pb + 8);
    };

#pragma unroll
    for (int p = 0; p < NSTAGE - 1; p++) {
        issue_stage(p, p);
        CP_COMMIT();
    }

    for (int kt = 0; kt < KT; kt++) {
        cp_wait_rem(KT - 1 - kt);
        __syncthreads();

        if (kt + NSTAGE - 1 < KT) {
            issue_stage(kt + NSTAGE - 1, (kt + NSTAGE - 1) & (NSTAGE - 1));
            CP_COMMIT();
        }

        const uint32_t sb = (uint32_t)((kt & (NSTAGE - 1)) * STAGE_B);
#pragma unroll
        for (int s = 0; s < KTILE / 16; s++) {
            uint32_t aH[2][4];
#pragma unroll
            for (int mt = 0; mt < 2; mt++) {
                uint32_t ad = a_frag0 + sb + 2u * (uint32_t)(mt * 16 * SMK + s * 16);
                ldsm4(ad, aH[mt][0], aH[mt][1], aH[mt][2], aH[mt][3]);
            }
#pragma unroll
            for (int p = 0; p < 4; p++) {
                uint32_t bd = b_frag0 + sb + 2u * (uint32_t)(p * 16 * SMK + s * 16);
                uint32_t h0, h1, h2, h3;
                ldsm4(bd, h0, h1, h2, h3);
                uint32_t b0H[2] = {h0, h2}, b1H[2] = {h1, h3};
#pragma unroll
                for (int mt = 0; mt < 2; mt++) {
                    mma_bf16(acc[mt][2 * p],     aH[mt], b0H);
                    mma_bf16(acc[mt][2 * p + 1], aH[mt], b1H);
                }
            }
        }
    }

    float bv0[8], bv1[8];
#pragma unroll
    for (int nt = 0; nt < 8; nt++) {
        int col = n0 + wn * 64 + nt * 8 + tig * 2;
        bv0[nt] = (col < Nreal)     ? bias1[col]     : 0.f;
        bv1[nt] = (col + 1 < Nreal) ? bias1[col + 1] : 0.f;
    }
#pragma unroll
    for (int mt = 0; mt < 2; mt++) {
#pragma unroll
        for (int i = 0; i < 2; i++) {
            int row = m0 + wm * 32 + mt * 16 + g + i * 8;
#pragma unroll
            for (int nt = 0; nt < 8; nt++) {
                int col = n0 + wn * 64 + nt * 8 + tig * 2;
                if (col < ldc) {
                    float v0 = fmaxf(acc[mt][nt][i * 2]     + bv0[nt], 0.f);
                    float v1 = fmaxf(acc[mt][nt][i * 2 + 1] + bv1[nt], 0.f);
                    if (col >= Nreal)     v0 = 0.f;
                    if (col + 1 >= Nreal) v1 = 0.f;
                    *(uint32_t*)&g_a1[(size_t)row * ldc + col] = pack2bf(v0, v1);
                }
            }
        }
    }
}

// ================= fused L2 + layer3 + layer4 + softmax ========================
// Tile 64(m) x 256(n), K=544. a2 tile -> smem bf16 -> layer3 MMA (W3 resident)
// -> layer4 + softmax -> out. 256 threads: main warps wm=warp&1, wn=warp>>1.
#define L2_ASTG  5120                   // 64 rows * 40 elems * 2B
#define L2_BSTG  20480                  // 256 rows * 40 elems * 2B
#define L2_STG   (L2_ASTG + L2_BSTG)    // 25600
#define L2_W3OFF (2 * L2_STG)           // 51200
#define L2_SMK2  264                    // a2s / W3s row stride (elems)
#define L2_SMEM  (L2_W3OFF + 64 * L2_SMK2 * 2)   // 51200 + 33792 = 84992
#define L2_KT    17

__global__ __launch_bounds__(256, 2)
void k_l2tail(const float* __restrict__ b2, const float* __restrict__ W3,
              const float* __restrict__ b3, const float* __restrict__ W4,
              const float* __restrict__ b4, float* __restrict__ out)
{
    extern __shared__ __align__(16) char smc[];
    const uint32_t smem_u = (uint32_t)__cvta_generic_to_shared(smc);

    const int tid  = threadIdx.x;
    const int m0   = blockIdx.x * 64;
    const int lane = tid & 31;
    const int warp = tid >> 5;
    const int wm   = warp & 1;          // m offset wm*32
    const int wn   = warp >> 1;         // n offset wn*64
    const int g    = lane >> 2;
    const int tig  = lane & 3;

    // ---- load W3 (fp32 -> bf16) into resident smem [64][264] ----
    {
        __nv_bfloat16* w3s = (__nv_bfloat16*)(smc + L2_W3OFF);
        int r = tid >> 2, qd = (tid & 3) * 64;    // row, 64-col quarter
        const float4* src = (const float4*)(W3 + (size_t)r * 256 + qd);
#pragma unroll
        for (int i = 0; i < 16; i++) {
            float4 v = src[i];
            uint2 w; w.x = pack2bf(v.x, v.y); w.y = pack2bf(v.z, v.w);
            *(uint2*)&w3s[r * L2_SMK2 + qd + i * 4] = w;
        }
    }

    float acc[2][8][4];
#pragma unroll
    for (int mt = 0; mt < 2; mt++)
#pragma unroll
        for (int nt = 0; nt < 8; nt++)
#pragma unroll
            for (int i = 0; i < 4; i++) acc[mt][nt][i] = 0.f;

    const int fl_row = lane & 15;
    const int fl_k   = (lane >> 4) * 8;
    const uint32_t a_frag0 = smem_u + 2u * (uint32_t)((wm * 32 + fl_row) * SMK + fl_k);
    const uint32_t b_frag0 = smem_u + (uint32_t)L2_ASTG
                           + 2u * (uint32_t)((wn * 64 + fl_row) * SMK + fl_k);

    auto issue_stage = [&](int kt, int st) {
        uint32_t base = smem_u + (uint32_t)(st * L2_STG);
        if (tid < 128) {   // A: 64 rows x 64B
            int srow = tid >> 1, shalf = tid & 1;
            uint32_t d = base + (uint32_t)(srow * (SMK * 2) + shalf * 32);
            const __nv_bfloat16* pa = g_a1 + (size_t)(m0 + srow) * 544
                                    + kt * KTILE + shalf * 16;
            cp16(d, pa); cp16(d + 16, pa + 8);
        }
        // B: 256 rows x 64B, one row per thread
        uint32_t d = base + (uint32_t)L2_ASTG + (uint32_t)(tid * (SMK * 2));
        const __nv_bfloat16* pb = g_w2 + (size_t)tid * 544 + kt * KTILE;
        cp16(d, pb);      cp16(d + 16, pb + 8);
        cp16(d + 32, pb + 16); cp16(d + 48, pb + 24);
    };

    issue_stage(0, 0);
    CP_COMMIT();

    for (int kt = 0; kt < L2_KT; kt++) {
        asm volatile("cp.async.wait_group 0;");
        __syncthreads();
        if (kt + 1 < L2_KT) {
            issue_stage(kt + 1, (kt + 1) & 1);
            CP_COMMIT();
        }
        const uint32_t sb = (uint32_t)((kt & 1) * L2_STG);
#pragma unroll
        for (int s = 0; s < 2; s++) {
            uint32_t aH[2][4];
#pragma unroll
            for (int mt = 0; mt < 2; mt++) {
                uint32_t ad = a_frag0 + sb + (uint32_t)(mt * 16 * SMK * 2 + s * 32);
                ldsm4(ad, aH[mt][0], aH[mt][1], aH[mt][2], aH[mt][3]);
            }
#pragma unroll
            for (int p = 0; p < 4; p++) {
                uint32_t bd = b_frag0 + sb + (uint32_t)(p * 16 * SMK * 2 + s * 32);
                uint32_t h0, h1, h2, h3;
                ldsm4(bd, h0, h1, h2, h3);
                uint32_t b0H[2] = {h0, h2}, b1H[2] = {h1, h3};
#pragma unroll
                for (int mt = 0; mt < 2; mt++) {
                    mma_bf16(acc[mt][2 * p],     aH[mt], b0H);
                    mma_bf16(acc[mt][2 * p + 1], aH[mt], b1H);
                }
            }
        }
    }
    __syncthreads();

    // ---- a2 = relu(acc + b2) -> smem bf16 [64][264] (reuses stage region) ----
    {
        __nv_bfloat16* a2s = (__nv_bfloat16*)smc;
#pragma unroll
        for (int nt = 0; nt < 8; nt++) {
            int col = wn * 64 + nt * 8 + tig * 2;
            float bb0 = b2[col], bb1 = b2[col + 1];
#pragma unroll
            for (int mt = 0; mt < 2; mt++)
#pragma unroll
                for (int i = 0; i < 2; i++) {
                    int row = wm * 32 + mt * 16 + g + i * 8;
                    float v0 = fmaxf(acc[mt][nt][i * 2]     + bb0, 0.f);
                    float v1 = fmaxf(acc[mt][nt][i * 2 + 1] + bb1, 0.f);
                    *(uint32_t*)&a2s[row * L2_SMK2 + col] = pack2bf(v0, v1);
                }
        }
    }
    __syncthreads();

    // ---- layer3: h3 = relu(a2 @ W3^T + b3)  [64 x 64], K=256 ----
    // warps: wm2 = warp&1 (m half 32), wn2 = warp>>1 (n 16 each)
    const int wm2 = wm, wn2 = wn;
    float acc2[2][2][4];
#pragma unroll
    for (int mt = 0; mt < 2; mt++)
#pragma unroll
        for (int nt = 0; nt < 2; nt++)
#pragma unroll
            for (int i = 0; i < 4; i++) acc2[mt][nt][i] = 0.f;

    {
        const uint32_t a2f = smem_u + 2u * (uint32_t)((wm2 * 32 + fl_row) * L2_SMK2 + fl_k);
        const uint32_t w3f = smem_u + (uint32_t)L2_W3OFF
                           + 2u * (uint32_t)((wn2 * 16 + fl_row) * L2_SMK2 + fl_k);
#pragma unroll
        for (int s = 0; s < 16; s++) {
            uint32_t aH[2][4];
#pragma unroll
            for (int mt = 0; mt < 2; mt++) {
                ldsm4(a2f + (uint32_t)(mt * 16 * L2_SMK2 * 2 + s * 32),
                      aH[mt][0], aH[mt][1], aH[mt][2], aH[mt][3]);
            }
            uint32_t h0, h1, h2, h3;
            ldsm4(w3f + (uint32_t)(s * 32), h0, h1, h2, h3);
            uint32_t b0H[2] = {h0, h2}, b1H[2] = {h1, h3};
#pragma unroll
            for (int mt = 0; mt < 2; mt++) {
                mma_bf16(acc2[mt][0], aH[mt], b0H);
                mma_bf16(acc2[mt][1], aH[mt], b1H);
            }
        }
    }
    __syncthreads();   // W3s region becomes h3s

    // ---- h3 -> smem fp32 [64][72] ----
    {
        float* h3s = (float*)(smc + L2_W3OFF);
#pragma unroll
        for (int nt = 0; nt < 2; nt++) {
            int col = wn2 * 16 + nt * 8 + tig * 2;
            float bb0 = b3[col], bb1 = b3[col + 1];
#pragma unroll
            for (int mt = 0; mt < 2; mt++)
#pragma unroll
                for (int i = 0; i < 2; i++) {
                    int row = wm2 * 32 + mt * 16 + g + i * 8;
                    float v0 = fmaxf(acc2[mt][nt][i * 2]     + bb0, 0.f);
                    float v1 = fmaxf(acc2[mt][nt][i * 2 + 1] + bb1, 0.f);
                    *(float2*)&h3s[row * 72 + col] = make_float2(v0, v1);
                }
        }
    }
    __syncthreads();

    // ---- layer4 + softmax ----
    if (tid < 64) {
        const float* h3s = (const float*)(smc + L2_W3OFF);
        const float* xr = &h3s[tid * 72];
        float z0 = b4[0], z1 = b4[1];
#pragma unroll
        for (int k = 0; k < 64; k++) {
            float x = xr[k];
            z0 = fmaf(x, W4[k], z0);
            z1 = fmaf(x, W4[64 + k], z1);
        }
        float mx = fmaxf(z0, z1);
        float e0 = expf(z0 - mx), e1 = expf(z1 - mx);
        float inv = 1.f / (e0 + e1);
        out[(size_t)(m0 + tid) * 2]     = e0 * inv;
        out[(size_t)(m0 + tid) * 2 + 1] = e1 * inv;
    }
}

// ---------------- launcher ----------------------------------------------------
extern "C" void kernel_launch(void* const* d_in, const int* in_sizes, int n_in,
                              void* d_out, int out_size)
{
    const float* x1   = (const float*)d_in[0];
    const float* x2   = (const float*)d_in[1];
    const float* W_ih = (const float*)d_in[2];
    const float* W_hh = (const float*)d_in[3];
    const float* b_ih = (const float*)d_in[4];
    const float* b_hh = (const float*)d_in[5];
    const float* W1   = (const float*)d_in[6];
    const float* b1   = (const float*)d_in[7];
    const float* W2   = (const float*)d_in[8];
    const float* b2   = (const float*)d_in[9];
    const float* W3   = (const float*)d_in[10];
    const float* b3   = (const float*)d_in[11];
    const float* W4   = (const float*)d_in[12];
    const float* b4   = (const float*)d_in[13];
    float* out = (float*)d_out;

    const int gemm_smem = NSTAGE * STAGE_B;   // 81920 B

    cudaFuncSetAttribute(k_step, cudaFuncAttributeMaxDynamicSharedMemorySize, KS_SMEM);
    cudaFuncSetAttribute(gemm_l1, cudaFuncAttributeMaxDynamicSharedMemorySize, gemm_smem);
    cudaFuncSetAttribute(k_l2tail, cudaFuncAttributeMaxDynamicSharedMemorySize, L2_SMEM);

    // merged prep
    k_prep<<<(NPREP_TOTAL + 255) / 256, 256>>>(x1, x2, W_ih, W1, W2, W_hh, b_ih, b_hh);

    // fused recurrence: 5 steps; B panel resident per CTA
    for (int t = 0; t < T_; t++) {
        dim3 grid(G4_ / 128, 37);
        k_step<<<grid, 512, KS_SMEM>>>(t);
    }

    // L1: g_a1 = relu(hs-slab @ w1^T + b1)   [16384 x 531->544], K=640
    {
        dim3 grid(5, B_ / 128);
        gemm_l1<<<grid, 256, gemm_smem>>>(640 / KTILE, 531, 544, b1);
    }

    // fused L2 + layer3 + layer4 + softmax
    k_l2tail<<<B_ / 64, 256, L2_SMEM>>>(b2, W3, b3, W4, b4, out);
}